// round 11
// baseline (speedup 1.0000x reference)
#include <cuda_runtime.h>
#include <cuda_fp16.h>
#include <math.h>
#include <stdint.h>

// Problem constants
#define Bn   4
#define Sn   1024
#define Hn   20
#define Dn   64
#define DMn  1280
#define DFn  5120
#define NTOK 4096           // Bn*Sn
#define NBH  80             // Bn*Hn
#define EPSLN 1e-5f
#define QKVLD 3840          // row stride of fused qkv output

// ---------------- scratch (static device globals; no allocation) -------------
__device__ __half g_hT  [(size_t)NTOK * DMn];          // fragment-major A (reused 3x)
__device__ __half g_qkv [(size_t)NTOK * QKVLD];        // fused q|k|v (plain fp16)
__device__ float  g_x1  [(size_t)NTOK * DMn];          // residual 1
__device__ __half g_f1T [(size_t)NTOK * DFn];          // fragment-major FC1 out
__device__ __half g_wr  [19660800];                    // fragment-major weights (fp16)
__device__ float  g_bqkv[QKVLD];                       // concat bias

#define WSZ_DM (DMn * DMn)          // 1,638,400
#define WSZ_FC (DMn * DFn)          // 6,553,600

// ---------------- fragment-major index helper ---------------------------------
__device__ __forceinline__ size_t fmIdx(int m, int k, int KB) {
    const int mb = m >> 7, mr = m & 127;
    const int kb = k >> 4, kr = k & 15;
    const int mt = mr >> 4, hh = (mr >> 3) & 1, gg = mr & 7;
    const int t4k = (kr >> 1) & 3, khi = kr >> 3, klo = kr & 1;
    return ((size_t)mb * KB + kb) * 2048 +
           (size_t)((mt * 32 + gg * 4 + t4k) * 8 + khi * 4 + hh * 2 + klo);
}

// ---------------- weight transform: 4 k-blocks per CTA, deep ILP --------------
// Bit-identical output to the old per-block transform; only scheduling differs.
// Grid (N/128, K/64), 256 threads. 8 float4 loads staged in registers (MLP 8),
// permute into 4 SMEM tiles, 4 coalesced uint4 stores per thread.
__global__ void __launch_bounds__(256) btrans4_h(const float* __restrict__ B,
                                                 __half* __restrict__ Bt,
                                                 int K, int N, int NBtot, int nbOff)
{
    __shared__ __half s[8192];
    const int nb = blockIdx.x, kb4 = blockIdx.y;
    const int tid = threadIdx.x;
    const float* bb = B + (size_t)(kb4 * 64) * N + nb * 128;

    float4 v[8];
#pragma unroll
    for (int i = 0; i < 8; i++) {
        const int e4 = tid + i * 256;
        const int k = e4 >> 5, colq = (e4 & 31) * 4;
        v[i] = *reinterpret_cast<const float4*>(bb + (size_t)k * N + colq);
    }
#pragma unroll
    for (int i = 0; i < 8; i++) {
        const int e4 = tid + i * 256;
        const int k = e4 >> 5, colq = (e4 & 31) * 4;
        const int kb = k >> 4, kr = k & 15;
        const int t4 = (kr >> 1) & 3, khi = (kr >> 3) & 1, klo = kr & 1;
        const float vv[4] = {v[i].x, v[i].y, v[i].z, v[i].w};
#pragma unroll
        for (int j = 0; j < 4; j++) {
            const int col = colq + j;
            const int ni = col >> 3, gg = col & 7;
            s[kb * 2048 + (ni * 32 + gg * 4 + t4) * 4 + khi * 2 + klo] =
                __float2half_rn(vv[j]);
        }
    }
    __syncthreads();
#pragma unroll
    for (int kk = 0; kk < 4; kk++) {
        __half* ob = Bt + ((size_t)(kb4 * 4 + kk) * NBtot + nbOff + nb) * 2048;
        *reinterpret_cast<uint4*>(ob + tid * 8) =
            *reinterpret_cast<const uint4*>(s + kk * 2048 + tid * 8);
    }
}

// ---------------- bias concat for fused QKV -----------------------------------
__global__ void __launch_bounds__(256) bias_concat(const float* __restrict__ bq,
                                                   const float* __restrict__ bk,
                                                   const float* __restrict__ bv,
                                                   float* __restrict__ o)
{
    const int i = blockIdx.x * 256 + threadIdx.x;
    if (i < DMn) o[i] = bq[i];
    else if (i < 2 * DMn) o[i] = bk[i - DMn];
    else if (i < 3 * DMn) o[i] = bv[i - 2 * DMn];
}

// ---------------- LayerNorm fused with fragment-major fp16 output -------------
__global__ void __launch_bounds__(256) ln_ft(const float* __restrict__ x,
                                             const float* __restrict__ sc,
                                             const float* __restrict__ off,
                                             __half* __restrict__ yT)
{
    const int row = blockIdx.x;
    const float* xr = x + (size_t)row * DMn;
    const int t = threadIdx.x;
    const int lane = t & 31, wid = t >> 5;

    __shared__ float sh[32];
    __shared__ float s_mean, s_rstd;

    float2 p0 = *reinterpret_cast<const float2*>(xr + 2 * t);
    float2 p1 = *reinterpret_cast<const float2*>(xr + 512 + 2 * t);
    float2 p2 = make_float2(0.f, 0.f);
    if (t < 128) p2 = *reinterpret_cast<const float2*>(xr + 1024 + 2 * t);

    float s = p0.x + p0.y + p1.x + p1.y + p2.x + p2.y;
#pragma unroll
    for (int o = 16; o; o >>= 1) s += __shfl_xor_sync(0xffffffffu, s, o);
    if (lane == 0) sh[wid] = s;
    __syncthreads();
    if (wid == 0) {
        float v = (lane < 8) ? sh[lane] : 0.f;
#pragma unroll
        for (int o = 4; o; o >>= 1) v += __shfl_xor_sync(0xffffffffu, v, o);
        if (lane == 0) s_mean = v * (1.0f / DMn);
    }
    __syncthreads();
    const float mean = s_mean;
    __syncthreads();

    float vs = 0.f;
    {
        float d;
        d = p0.x - mean; vs += d * d;
        d = p0.y - mean; vs += d * d;
        d = p1.x - mean; vs += d * d;
        d = p1.y - mean; vs += d * d;
        if (t < 128) {
            d = p2.x - mean; vs += d * d;
            d = p2.y - mean; vs += d * d;
        }
    }
#pragma unroll
    for (int o = 16; o; o >>= 1) vs += __shfl_xor_sync(0xffffffffu, vs, o);
    if (lane == 0) sh[wid] = vs;
    __syncthreads();
    if (wid == 0) {
        float v = (lane < 8) ? sh[lane] : 0.f;
#pragma unroll
        for (int o = 4; o; o >>= 1) v += __shfl_xor_sync(0xffffffffu, v, o);
        if (lane == 0) s_rstd = rsqrtf(v * (1.0f / DMn) + EPSLN);
    }
    __syncthreads();
    const float rstd = s_rstd;

    const int KB = DMn >> 4;
    {
        const int c = 2 * t;
        const float2 g2 = *reinterpret_cast<const float2*>(sc + c);
        const float2 b2 = *reinterpret_cast<const float2*>(off + c);
        *reinterpret_cast<__half2*>(yT + fmIdx(row, c, KB)) =
            __floats2half2_rn((p0.x - mean) * rstd * g2.x + b2.x,
                              (p0.y - mean) * rstd * g2.y + b2.y);
    }
    {
        const int c = 512 + 2 * t;
        const float2 g2 = *reinterpret_cast<const float2*>(sc + c);
        const float2 b2 = *reinterpret_cast<const float2*>(off + c);
        *reinterpret_cast<__half2*>(yT + fmIdx(row, c, KB)) =
            __floats2half2_rn((p1.x - mean) * rstd * g2.x + b2.x,
                              (p1.y - mean) * rstd * g2.y + b2.y);
    }
    if (t < 128) {
        const int c = 1024 + 2 * t;
        const float2 g2 = *reinterpret_cast<const float2*>(sc + c);
        const float2 b2 = *reinterpret_cast<const float2*>(off + c);
        *reinterpret_cast<__half2*>(yT + fmIdx(row, c, KB)) =
            __floats2half2_rn((p2.x - mean) * rstd * g2.x + b2.x,
                              (p2.y - mean) * rstd * g2.y + b2.y);
    }
}

// ---------------- GEMM helpers -------------------------------------------------
__device__ __forceinline__ float gelu_exact(float v) {
    return 0.5f * v * (1.0f + erff(v * 0.70710678118654752f));
}

__device__ __forceinline__ void cp16(void* smem_dst, const void* gsrc) {
    uint32_t s = (uint32_t)__cvta_generic_to_shared(smem_dst);
    asm volatile("cp.async.cg.shared.global [%0], [%1], 16;" :: "r"(s), "l"(gsrc));
}

// Drain discipline: wait_group 1 only while another group is still in flight;
// on the FINAL iteration only the current group remains -> wait_group 0.
#define PIPE_WAIT(kb, KB) \
    do { if ((kb) + 1 < (KB)) asm volatile("cp.async.wait_group 1;" ::: "memory"); \
         else                 asm volatile("cp.async.wait_group 0;" ::: "memory"); } while (0)

#define MMA_H(c, a0,a1,a2,a3, b0,b1) \
    asm volatile("mma.sync.aligned.m16n8k16.row.col.f32.f16.f16.f32 " \
                 "{%0,%1,%2,%3}, {%4,%5,%6,%7}, {%8,%9}, {%0,%1,%2,%3};" \
                 : "+f"((c)[0]), "+f"((c)[1]), "+f"((c)[2]), "+f"((c)[3]) \
                 : "r"(a0), "r"(a1), "r"(a2), "r"(a3), "r"(b0), "r"(b1))

// ---------------- FP16 GEMM, 128x128 tile (EPI: 0 fp16 out, 2 gelu->frag) -----
template <int EPI>
__global__ void __launch_bounds__(256, 2) gemm_h(const __half* __restrict__ At,
                                                 const __half* __restrict__ Bt,
                                                 const float* __restrict__ bias,
                                                 const float* __restrict__ res,
                                                 void* __restrict__ Cv,
                                                 int M, int N, int K)
{
    __shared__ __align__(16) __half As[3][4096];
    __shared__ __align__(16) __half Bs[3][4096];

    const int tid = threadIdx.x;
    const int nb = blockIdx.x, mb = blockIdx.y;
    const int KB = K >> 5;
    const int KB16 = K >> 4;
    const int NB = N >> 7;
    const int lane = tid & 31, warp = tid >> 5;
    const int wmBase = (warp >> 2) * 4;
    const int wnBase = (warp & 3) * 4;
    const int g = lane >> 2, t4 = lane & 3;

    const __half* aBase = At + (size_t)mb * KB16 * 2048;
    const __half* bBase = Bt + (size_t)nb * 2048;

    float acc[16][4];
#pragma unroll
    for (int i = 0; i < 16; i++)
#pragma unroll
        for (int j = 0; j < 4; j++) acc[i][j] = 0.f;

    auto issue = [&](int s, int kb) {
        const __half* ab  = aBase + (size_t)kb * 4096;
        const __half* bb0 = bBase + (size_t)(kb * 2) * NB * 2048;
        const __half* bb1 = bBase + (size_t)(kb * 2 + 1) * NB * 2048;
        cp16(&As[s][tid * 8],        ab + tid * 8);
        cp16(&As[s][2048 + tid * 8], ab + 2048 + tid * 8);
        cp16(&Bs[s][tid * 8],        bb0 + tid * 8);
        cp16(&Bs[s][2048 + tid * 8], bb1 + tid * 8);
        asm volatile("cp.async.commit_group;" ::: "memory");
    };

    issue(0, 0);
    issue(1, 1);

    for (int kb = 0; kb < KB; kb++) {
        const int s = kb % 3;
        PIPE_WAIT(kb, KB);
        __syncthreads();
        if (kb + 2 < KB) issue((kb + 2) % 3, kb + 2);

#pragma unroll
        for (int kk = 0; kk < 2; kk++) {
            uint32_t a[4][4], b[4][2];
#pragma unroll
            for (int mi = 0; mi < 4; mi++) {
                const uint4 fa = *reinterpret_cast<const uint4*>(
                    &As[s][kk * 2048 + ((wmBase + mi) * 32 + lane) * 8]);
                a[mi][0] = fa.x; a[mi][1] = fa.y; a[mi][2] = fa.z; a[mi][3] = fa.w;
            }
#pragma unroll
            for (int ni = 0; ni < 4; ni++) {
                const uint2 fb = *reinterpret_cast<const uint2*>(
                    &Bs[s][kk * 2048 + ((wnBase + ni) * 32 + lane) * 4]);
                b[ni][0] = fb.x; b[ni][1] = fb.y;
            }
#pragma unroll
            for (int mi = 0; mi < 4; mi++)
#pragma unroll
                for (int ni = 0; ni < 4; ni++)
                    MMA_H(acc[mi * 4 + ni], a[mi][0], a[mi][1], a[mi][2], a[mi][3],
                          b[ni][0], b[ni][1]);
        }
    }

    const int rowBase = mb * 128;
    const int colBase = nb * 128;
    const int wm = (warp >> 2) * 64;
    const int wn = (warp & 3) * 32;
    const int KBo = N >> 4;
#pragma unroll
    for (int mi = 0; mi < 4; mi++) {
#pragma unroll
        for (int ni = 0; ni < 4; ni++) {
            float* c = acc[mi * 4 + ni];
            const int col = colBase + wn + ni * 8 + t4 * 2;
            const float2 bb = *reinterpret_cast<const float2*>(bias + col);
#pragma unroll
            for (int h = 0; h < 2; h++) {
                const int row = rowBase + wm + mi * 16 + g + h * 8;
                float o0 = c[h * 2 + 0] + bb.x;
                float o1 = c[h * 2 + 1] + bb.y;
                if (EPI == 0) {
                    __half* Ch = (__half*)Cv;
                    *reinterpret_cast<__half2*>(Ch + (size_t)row * N + col) =
                        __floats2half2_rn(o0, o1);
                } else {
                    __half* Ch = (__half*)Cv;
                    *reinterpret_cast<__half2*>(Ch + fmIdx(row, col, KBo)) =
                        __floats2half2_rn(gelu_exact(o0), gelu_exact(o1));
                }
            }
        }
    }
}

// ---------------- FP16 GEMM, 64x128 tile, EPI = bias+res -> fp32 --------------
__global__ void __launch_bounds__(256, 3) gemm_h64(const __half* __restrict__ At,
                                                   const __half* __restrict__ Bt,
                                                   const float* __restrict__ bias,
                                                   const float* __restrict__ res,
                                                   float* __restrict__ C,
                                                   int M, int N, int K)
{
    __shared__ __align__(16) __half As[3][2048];   // 2 kk x 1024 (4 m-tiles)
    __shared__ __align__(16) __half Bs[3][4096];

    const int tid = threadIdx.x;
    const int nb = blockIdx.x, mb = blockIdx.y;
    const int KB = K >> 5;
    const int KB16 = K >> 4;
    const int NB = N >> 7;
    const int lane = tid & 31, warp = tid >> 5;
    const int wmBase = (warp >> 2) * 2;   // m-tile base (0 or 2)
    const int wnBase = (warp & 3) * 4;
    const int g = lane >> 2, t4 = lane & 3;
    const int mhalf = mb & 1, mblk = mb >> 1;

    const __half* aBase = At + (size_t)mblk * KB16 * 2048 + mhalf * 1024;
    const __half* bBase = Bt + (size_t)nb * 2048;

    float acc[8][4];
#pragma unroll
    for (int i = 0; i < 8; i++)
#pragma unroll
        for (int j = 0; j < 4; j++) acc[i][j] = 0.f;

    auto issue = [&](int s, int kb) {
        const __half* ab0 = aBase + (size_t)(kb * 2) * 2048;
        const __half* ab1 = aBase + (size_t)(kb * 2 + 1) * 2048;
        if (tid < 128) cp16(&As[s][tid * 8], ab0 + tid * 8);
        else           cp16(&As[s][1024 + (tid - 128) * 8], ab1 + (tid - 128) * 8);
        const __half* bb0 = bBase + (size_t)(kb * 2) * NB * 2048;
        const __half* bb1 = bBase + (size_t)(kb * 2 + 1) * NB * 2048;
        cp16(&Bs[s][tid * 8],        bb0 + tid * 8);
        cp16(&Bs[s][2048 + tid * 8], bb1 + tid * 8);
        asm volatile("cp.async.commit_group;" ::: "memory");
    };

    issue(0, 0);
    issue(1, 1);

    for (int kb = 0; kb < KB; kb++) {
        const int s = kb % 3;
        PIPE_WAIT(kb, KB);
        __syncthreads();
        if (kb + 2 < KB) issue((kb + 2) % 3, kb + 2);

#pragma unroll
        for (int kk = 0; kk < 2; kk++) {
            uint32_t a[2][4], b[4][2];
#pragma unroll
            for (int mi = 0; mi < 2; mi++) {
                const uint4 fa = *reinterpret_cast<const uint4*>(
                    &As[s][kk * 1024 + (wmBase + mi) * 256 + lane * 8]);
                a[mi][0] = fa.x; a[mi][1] = fa.y; a[mi][2] = fa.z; a[mi][3] = fa.w;
            }
#pragma unroll
            for (int ni = 0; ni < 4; ni++) {
                const uint2 fb = *reinterpret_cast<const uint2*>(
                    &Bs[s][kk * 2048 + ((wnBase + ni) * 32 + lane) * 4]);
                b[ni][0] = fb.x; b[ni][1] = fb.y;
            }
#pragma unroll
            for (int mi = 0; mi < 2; mi++)
#pragma unroll
                for (int ni = 0; ni < 4; ni++)
                    MMA_H(acc[mi * 4 + ni], a[mi][0], a[mi][1], a[mi][2], a[mi][3],
                          b[ni][0], b[ni][1]);
        }
    }

    const int rowBase = mb * 64;
    const int colBase = nb * 128;
    const int wm = (warp >> 2) * 32;
    const int wn = (warp & 3) * 32;
#pragma unroll
    for (int mi = 0; mi < 2; mi++) {
#pragma unroll
        for (int ni = 0; ni < 4; ni++) {
            float* c = acc[mi * 4 + ni];
            const int col = colBase + wn + ni * 8 + t4 * 2;
            const float2 bb = *reinterpret_cast<const float2*>(bias + col);
#pragma unroll
            for (int h = 0; h < 2; h++) {
                const int row = rowBase + wm + mi * 16 + g + h * 8;
                const float2 r2 = *reinterpret_cast<const float2*>(res + (size_t)row * N + col);
                *reinterpret_cast<float2*>(C + (size_t)row * N + col) =
                    make_float2(c[h * 2 + 0] + bb.x + r2.x, c[h * 2 + 1] + bb.y + r2.y);
            }
        }
    }
}

// ---------------- flash attention: register softmax, 128-row Q tile -----------
// grid (S/128, B*H), 256 threads; warp w owns rows [w*16, w*16+16), all 64 dims.
#define KVST 72
#define FLASH_SMEM (3 * 2 * 64 * KVST * 2)   // 3-stage K+V ring, fp16
__global__ void __launch_bounds__(256, 2) flash_reg(const __half* __restrict__ qkv,
                                                    __half* __restrict__ outT)
{
    extern __shared__ __half kvs[];
    __half* Ks = kvs;                       // [3][64*KVST]
    __half* Vs = kvs + 3 * 64 * KVST;       // [3][64*KVST]

    const int tid = threadIdx.x;
    const int lane = tid & 31, warp = tid >> 5;
    const int g = lane >> 2, t4 = lane & 3;
    const int bh = blockIdx.y;
    const int b = bh / Hn, h = bh % Hn;
    const int t0 = blockIdx.x * 128;
    const int rw = t0 + warp * 16;
    const int lr = tid >> 2, lc = (tid & 3) * 16;

    // Q fragments straight from gmem (row-major fp16 qkv)
    uint32_t aq[4][4];
    {
        const __half* q0 = qkv + (size_t)(b * Sn + rw + g) * QKVLD + h * Dn + 2 * t4;
        const __half* q1 = q0 + (size_t)8 * QKVLD;
#pragma unroll
        for (int ks = 0; ks < 4; ks++) {
            const int k0 = ks * 16;
            aq[ks][0] = *reinterpret_cast<const uint32_t*>(q0 + k0);
            aq[ks][1] = *reinterpret_cast<const uint32_t*>(q1 + k0);
            aq[ks][2] = *reinterpret_cast<const uint32_t*>(q0 + k0 + 8);
            aq[ks][3] = *reinterpret_cast<const uint32_t*>(q1 + k0 + 8);
        }
    }

    float o[8][4];
#pragma unroll
    for (int ni = 0; ni < 8; ni++)
#pragma unroll
        for (int j = 0; j < 4; j++) o[ni][j] = 0.f;
    float m0 = -3e38f, m1 = -3e38f, l0 = 0.f, l1 = 0.f;

    auto loadKV = [&](int buf, int j0) {
        const __half* kr = qkv + (size_t)(b * Sn + j0 + lr) * QKVLD + DMn + h * Dn + lc;
        const __half* vr = kr + DMn;
        __half* kd = Ks + buf * (64 * KVST) + lr * KVST + lc;
        __half* vd = Vs + buf * (64 * KVST) + lr * KVST + lc;
        cp16(kd, kr); cp16(kd + 8, kr + 8);
        cp16(vd, vr); cp16(vd + 8, vr + 8);
        asm volatile("cp.async.commit_group;" ::: "memory");
    };

    loadKV(0, 0);
    loadKV(1, 64);

    for (int j = 0; j < 16; j++) {
        const int s = j % 3;
        PIPE_WAIT(j, 16);
        __syncthreads();
        if (j + 2 < 16) loadKV((j + 2) % 3, (j + 2) * 64);

        const __half* Kb = Ks + s * (64 * KVST);
        const __half* Vb = Vs + s * (64 * KVST);

        // S = Q K^T (scaled)
        float sc[8][4];
#pragma unroll
        for (int ni = 0; ni < 8; ni++)
#pragma unroll
            for (int jj = 0; jj < 4; jj++) sc[ni][jj] = 0.f;
#pragma unroll
        for (int ks = 0; ks < 4; ks++) {
            const int k0 = ks * 16;
#pragma unroll
            for (int ni = 0; ni < 8; ni++) {
                const __half* bp = Kb + (ni * 8 + g) * KVST + k0 + 2 * t4;
                const uint32_t b0 = *reinterpret_cast<const uint32_t*>(bp);
                const uint32_t b1 = *reinterpret_cast<const uint32_t*>(bp + 8);
                MMA_H(sc[ni], aq[ks][0], aq[ks][1], aq[ks][2], aq[ks][3], b0, b1);
            }
        }

        // row stats in registers (rows g and g+8)
        float mx0 = -3e38f, mx1 = -3e38f;
#pragma unroll
        for (int ni = 0; ni < 8; ni++) {
#pragma unroll
            for (int jj = 0; jj < 4; jj++) sc[ni][jj] *= 0.125f;
            mx0 = fmaxf(mx0, fmaxf(sc[ni][0], sc[ni][1]));
            mx1 = fmaxf(mx1, fmaxf(sc[ni][2], sc[ni][3]));
        }
        mx0 = fmaxf(mx0, __shfl_xor_sync(0xffffffffu, mx0, 1));
        mx0 = fmaxf(mx0, __shfl_xor_sync(0xffffffffu, mx0, 2));
        mx1 = fmaxf(mx1, __shfl_xor_sync(0xffffffffu, mx1, 1));
        mx1 = fmaxf(mx1, __shfl_xor_sync(0xffffffffu, mx1, 2));

        const float mn0 = fmaxf(m0, mx0), mn1 = fmaxf(m1, mx1);
        const float al0 = __expf(m0 - mn0), al1 = __expf(m1 - mn1);
        m0 = mn0; m1 = mn1;

        uint32_t p[8][2];
        float sum0 = 0.f, sum1 = 0.f;
#pragma unroll
        for (int ni = 0; ni < 8; ni++) {
            const __half2 h20 = __floats2half2_rn(__expf(sc[ni][0] - m0),
                                                  __expf(sc[ni][1] - m0));
            const __half2 h21 = __floats2half2_rn(__expf(sc[ni][2] - m1),
                                                  __expf(sc[ni][3] - m1));
            p[ni][0] = *reinterpret_cast<const uint32_t*>(&h20);
            p[ni][1] = *reinterpret_cast<const uint32_t*>(&h21);
            sum0 += __low2float(h20) + __high2float(h20);
            sum1 += __low2float(h21) + __high2float(h21);
        }
        sum0 += __shfl_xor_sync(0xffffffffu, sum0, 1);
        sum0 += __shfl_xor_sync(0xffffffffu, sum0, 2);
        sum1 += __shfl_xor_sync(0xffffffffu, sum1, 1);
        sum1 += __shfl_xor_sync(0xffffffffu, sum1, 2);
        l0 = l0 * al0 + sum0;
        l1 = l1 * al1 + sum1;

#pragma unroll
        for (int ni = 0; ni < 8; ni++) {
            o[ni][0] *= al0; o[ni][1] *= al0;
            o[ni][2] *= al1; o[ni][3] *= al1;
        }

        // O += P V  (A from p regs, B = 2-byte V loads)
#pragma unroll
        for (int ks = 0; ks < 4; ks++) {
            const int k0 = ks * 16;
#pragma unroll
            for (int ni = 0; ni < 8; ni++) {
                const __half* vp = Vb + (k0 + 2 * t4) * KVST + ni * 8 + g;
                const uint32_t v00 = *reinterpret_cast<const uint16_t*>(vp);
                const uint32_t v01 = *reinterpret_cast<const uint16_t*>(vp + KVST);
                const uint32_t v10 = *reinterpret_cast<const uint16_t*>(vp + 8 * KVST);
                const uint32_t v11 = *reinterpret_cast<const uint16_t*>(vp + 9 * KVST);
                const uint32_t b0 = v00 | (v01 << 16);
                const uint32_t b1 = v10 | (v11 << 16);
                MMA_H(o[ni], p[2 * ks][0], p[2 * ks][1], p[2 * ks + 1][0], p[2 * ks + 1][1],
                      b0, b1);
            }
        }
    }

    // normalize, write fragment-major fp16
    const float il0 = 1.0f / l0, il1 = 1.0f / l1;
    const int KBo = DMn >> 4;
    const int mr0 = b * Sn + rw + g;
#pragma unroll
    for (int ni = 0; ni < 8; ni++) {
        const int k = h * Dn + ni * 8 + 2 * t4;
        *reinterpret_cast<__half2*>(outT + fmIdx(mr0, k, KBo)) =
            __floats2half2_rn(o[ni][0] * il0, o[ni][1] * il0);
        *reinterpret_cast<__half2*>(outT + fmIdx(mr0 + 8, k, KBo)) =
            __floats2half2_rn(o[ni][2] * il1, o[ni][3] * il1);
    }
}

// ---------------- launch ------------------------------------------------------
extern "C" void kernel_launch(void* const* d_in, const int* in_sizes, int n_in,
                              void* d_out, int out_size)
{
    const float* x        = (const float*)d_in[0];
    const float* ln1_s    = (const float*)d_in[1];
    const float* ln1_o    = (const float*)d_in[2];
    const float* wq       = (const float*)d_in[3];
    const float* bq       = (const float*)d_in[4];
    const float* wk       = (const float*)d_in[5];
    const float* bk       = (const float*)d_in[6];
    const float* wv       = (const float*)d_in[7];
    const float* bv       = (const float*)d_in[8];
    const float* wo       = (const float*)d_in[9];
    const float* bo       = (const float*)d_in[10];
    const float* ln2_s    = (const float*)d_in[11];
    const float* ln2_o    = (const float*)d_in[12];
    const float* fc1_w    = (const float*)d_in[13];
    const float* fc1_b    = (const float*)d_in[14];
    const float* fc2_w    = (const float*)d_in[15];
    const float* fc2_b    = (const float*)d_in[16];
    float* out            = (float*)d_out;

    float *px1, *pbqkv;
    __half *phT, *pqkv, *pf1T, *pwr;
    cudaGetSymbolAddress((void**)&phT,   g_hT);
    cudaGetSymbolAddress((void**)&pqkv,  g_qkv);
    cudaGetSymbolAddress((void**)&px1,   g_x1);
    cudaGetSymbolAddress((void**)&pf1T,  g_f1T);
    cudaGetSymbolAddress((void**)&pwr,   g_wr);
    cudaGetSymbolAddress((void**)&pbqkv, g_bqkv);

    __half* rwqkv = pwr;                                     // fused, NBtot=30
    __half* rwo   = pwr + (size_t)3 * WSZ_DM;
    __half* rfc1  = pwr + (size_t)4 * WSZ_DM;
    __half* rfc2  = pwr + (size_t)4 * WSZ_DM + WSZ_FC;

    static bool attr_done = false;
    if (!attr_done) {
        cudaFuncSetAttribute(flash_reg, cudaFuncAttributeMaxDynamicSharedMemorySize, FLASH_SMEM);
        attr_done = true;
    }

    // 0) weight transforms (fp16 fragment-major; 4 k-blocks per CTA)
    {
        dim3 gdm(DMn / 128, DMn / 64);       // (10, 20)
        btrans4_h<<<gdm, 256>>>(wq, rwqkv, DMn, DMn, 30, 0);
        btrans4_h<<<gdm, 256>>>(wk, rwqkv, DMn, DMn, 30, 10);
        btrans4_h<<<gdm, 256>>>(wv, rwqkv, DMn, DMn, 30, 20);
        btrans4_h<<<gdm, 256>>>(wo, rwo, DMn, DMn, 10, 0);
        dim3 gf1(DFn / 128, DMn / 64);       // (40, 20)
        btrans4_h<<<gf1, 256>>>(fc1_w, rfc1, DMn, DFn, 40, 0);
        dim3 gf2(DMn / 128, DFn / 64);       // (10, 80)
        btrans4_h<<<gf2, 256>>>(fc2_w, rfc2, DFn, DMn, 10, 0);
        bias_concat<<<QKVLD / 256, 256>>>(bq, bk, bv, pbqkv);
    }

    // 1) LN1 -> fragment-major hT
    ln_ft<<<NTOK, 256>>>(x, ln1_s, ln1_o, phT);

    // 2) fused QKV projection -> qkv (plain fp16)
    {
        dim3 grid(QKVLD / 128, NTOK / 128);  // (30, 32)
        gemm_h<0><<<grid, 256>>>(phT, rwqkv, pbqkv, nullptr, pqkv, NTOK, QKVLD, DMn);
    }

    // 3) flash attention (register softmax) -> fragment-major hT (reuse)
    {
        dim3 grid(Sn / 128, NBH);            // (8, 80)
        flash_reg<<<grid, 256, FLASH_SMEM>>>(pqkv, phT);
    }

    // 4) O-proj + residual(x) -> x1 (fp32), 64-row tiles
    {
        dim3 grid(DMn / 128, NTOK / 64);     // (10, 64)
        gemm_h64<<<grid, 256>>>(phT, rwo, bo, x, px1, NTOK, DMn, DMn);
    }

    // 5) LN2 -> fragment-major hT (reuse)
    ln_ft<<<NTOK, 256>>>(px1, ln2_s, ln2_o, phT);

    // 6) FC1 + GELU -> fragment-major f1T
    {
        dim3 grid(DFn / 128, NTOK / 128);    // (40, 32)
        gemm_h<2><<<grid, 256>>>(phT, rfc1, fc1_b, nullptr, pf1T, NTOK, DFn, DMn);
    }

    // 7) FC2 + residual(x1) -> out, 64-row tiles
    {
        dim3 grid(DMn / 128, NTOK / 64);     // (10, 64)
        gemm_h64<<<grid, 256>>>(pf1T, rfc2, fc2_b, px1, out, NTOK, DMn, DFn);
    }
}

// round 12
// speedup vs baseline: 1.0259x; 1.0259x over previous
#include <cuda_runtime.h>
#include <cuda_fp16.h>
#include <math.h>
#include <stdint.h>

// Problem constants
#define Bn   4
#define Sn   1024
#define Hn   20
#define Dn   64
#define DMn  1280
#define DFn  5120
#define NTOK 4096           // Bn*Sn
#define NBH  80             // Bn*Hn
#define EPSLN 1e-5f
#define QKVLD 3840          // row stride of fused qkv output

// ---------------- scratch (static device globals; no allocation) -------------
__device__ __half g_hT  [(size_t)NTOK * DMn];          // fragment-major A (reused 3x)
__device__ __half g_qkv [(size_t)NTOK * QKVLD];        // fused q|k|v (plain fp16)
__device__ float  g_x1  [(size_t)NTOK * DMn];          // residual 1
__device__ __half g_f1T [(size_t)NTOK * DFn];          // fragment-major FC1 out
__device__ __half g_wr  [19660800];                    // fragment-major weights (fp16)
__device__ float  g_bqkv[QKVLD];                       // concat bias

#define WSZ_DM (DMn * DMn)          // 1,638,400
#define WSZ_FC (DMn * DFn)          // 6,553,600

// ---------------- fragment-major index helper ---------------------------------
__device__ __forceinline__ size_t fmIdx(int m, int k, int KB) {
    const int mb = m >> 7, mr = m & 127;
    const int kb = k >> 4, kr = k & 15;
    const int mt = mr >> 4, hh = (mr >> 3) & 1, gg = mr & 7;
    const int t4k = (kr >> 1) & 3, khi = kr >> 3, klo = kr & 1;
    return ((size_t)mb * KB + kb) * 2048 +
           (size_t)((mt * 32 + gg * 4 + t4k) * 8 + khi * 4 + hh * 2 + klo);
}

// ---------------- ALL weight transforms in ONE launch --------------------------
// Round-10 proven btrans_h body (bit-identical output), segment table selects
// which weight a CTA works on. 9600 CTAs total -> full chip occupancy, one
// launch instead of six.
struct WtArgs {
    const float* src[6];
    __half*      dst[6];
    int K[6], N[6], NBtot[6], nbOff[6];
    int blockStart[7];
};

__global__ void __launch_bounds__(256) btrans_all(WtArgs wa)
{
    __shared__ __half s[2048];
    const int gb = blockIdx.x;
    int seg = 0;
#pragma unroll
    for (int i = 1; i < 6; i++) seg += (gb >= wa.blockStart[i]);
    const int lb = gb - wa.blockStart[seg];
    const int K = wa.K[seg], N = wa.N[seg];
    const int NBn = N >> 7;
    const int nb = lb % NBn, kb = lb / NBn;
    const int tid = threadIdx.x;
    const float* bb = wa.src[seg] + (size_t)(kb * 16) * N + nb * 128;

#pragma unroll
    for (int e4 = tid; e4 < 512; e4 += 256) {
        const int k = e4 >> 5, colq = (e4 & 31) * 4;
        const float4 f = *reinterpret_cast<const float4*>(bb + (size_t)k * N + colq);
        const int t4 = (k >> 1) & 3, khi = (k >> 3) & 1, klo = k & 1;
        const float vv[4] = {f.x, f.y, f.z, f.w};
#pragma unroll
        for (int j = 0; j < 4; j++) {
            const int col = colq + j;
            const int ni = col >> 3, gg = col & 7;
            s[(ni * 32 + gg * 4 + t4) * 4 + khi * 2 + klo] = __float2half_rn(vv[j]);
        }
    }
    __syncthreads();
    __half* ob = wa.dst[seg] + ((size_t)kb * wa.NBtot[seg] + wa.nbOff[seg] + nb) * 2048;
    *reinterpret_cast<uint4*>(ob + tid * 8) = *reinterpret_cast<const uint4*>(s + tid * 8);
}

// ---------------- bias concat for fused QKV -----------------------------------
__global__ void __launch_bounds__(256) bias_concat(const float* __restrict__ bq,
                                                   const float* __restrict__ bk,
                                                   const float* __restrict__ bv,
                                                   float* __restrict__ o)
{
    const int i = blockIdx.x * 256 + threadIdx.x;
    if (i < DMn) o[i] = bq[i];
    else if (i < 2 * DMn) o[i] = bk[i - DMn];
    else if (i < 3 * DMn) o[i] = bv[i - 2 * DMn];
}

// ---------------- LayerNorm fused with fragment-major fp16 output -------------
__global__ void __launch_bounds__(256) ln_ft(const float* __restrict__ x,
                                             const float* __restrict__ sc,
                                             const float* __restrict__ off,
                                             __half* __restrict__ yT)
{
    const int row = blockIdx.x;
    const float* xr = x + (size_t)row * DMn;
    const int t = threadIdx.x;
    const int lane = t & 31, wid = t >> 5;

    __shared__ float sh[32];
    __shared__ float s_mean, s_rstd;

    float2 p0 = *reinterpret_cast<const float2*>(xr + 2 * t);
    float2 p1 = *reinterpret_cast<const float2*>(xr + 512 + 2 * t);
    float2 p2 = make_float2(0.f, 0.f);
    if (t < 128) p2 = *reinterpret_cast<const float2*>(xr + 1024 + 2 * t);

    float s = p0.x + p0.y + p1.x + p1.y + p2.x + p2.y;
#pragma unroll
    for (int o = 16; o; o >>= 1) s += __shfl_xor_sync(0xffffffffu, s, o);
    if (lane == 0) sh[wid] = s;
    __syncthreads();
    if (wid == 0) {
        float v = (lane < 8) ? sh[lane] : 0.f;
#pragma unroll
        for (int o = 4; o; o >>= 1) v += __shfl_xor_sync(0xffffffffu, v, o);
        if (lane == 0) s_mean = v * (1.0f / DMn);
    }
    __syncthreads();
    const float mean = s_mean;
    __syncthreads();

    float vs = 0.f;
    {
        float d;
        d = p0.x - mean; vs += d * d;
        d = p0.y - mean; vs += d * d;
        d = p1.x - mean; vs += d * d;
        d = p1.y - mean; vs += d * d;
        if (t < 128) {
            d = p2.x - mean; vs += d * d;
            d = p2.y - mean; vs += d * d;
        }
    }
#pragma unroll
    for (int o = 16; o; o >>= 1) vs += __shfl_xor_sync(0xffffffffu, vs, o);
    if (lane == 0) sh[wid] = vs;
    __syncthreads();
    if (wid == 0) {
        float v = (lane < 8) ? sh[lane] : 0.f;
#pragma unroll
        for (int o = 4; o; o >>= 1) v += __shfl_xor_sync(0xffffffffu, v, o);
        if (lane == 0) s_rstd = rsqrtf(v * (1.0f / DMn) + EPSLN);
    }
    __syncthreads();
    const float rstd = s_rstd;

    const int KB = DMn >> 4;
    {
        const int c = 2 * t;
        const float2 g2 = *reinterpret_cast<const float2*>(sc + c);
        const float2 b2 = *reinterpret_cast<const float2*>(off + c);
        *reinterpret_cast<__half2*>(yT + fmIdx(row, c, KB)) =
            __floats2half2_rn((p0.x - mean) * rstd * g2.x + b2.x,
                              (p0.y - mean) * rstd * g2.y + b2.y);
    }
    {
        const int c = 512 + 2 * t;
        const float2 g2 = *reinterpret_cast<const float2*>(sc + c);
        const float2 b2 = *reinterpret_cast<const float2*>(off + c);
        *reinterpret_cast<__half2*>(yT + fmIdx(row, c, KB)) =
            __floats2half2_rn((p1.x - mean) * rstd * g2.x + b2.x,
                              (p1.y - mean) * rstd * g2.y + b2.y);
    }
    if (t < 128) {
        const int c = 1024 + 2 * t;
        const float2 g2 = *reinterpret_cast<const float2*>(sc + c);
        const float2 b2 = *reinterpret_cast<const float2*>(off + c);
        *reinterpret_cast<__half2*>(yT + fmIdx(row, c, KB)) =
            __floats2half2_rn((p2.x - mean) * rstd * g2.x + b2.x,
                              (p2.y - mean) * rstd * g2.y + b2.y);
    }
}

// ---------------- GEMM helpers -------------------------------------------------
__device__ __forceinline__ float gelu_exact(float v) {
    return 0.5f * v * (1.0f + erff(v * 0.70710678118654752f));
}

__device__ __forceinline__ void cp16(void* smem_dst, const void* gsrc) {
    uint32_t s = (uint32_t)__cvta_generic_to_shared(smem_dst);
    asm volatile("cp.async.cg.shared.global [%0], [%1], 16;" :: "r"(s), "l"(gsrc));
}

// Drain discipline: wait_group 1 only while another group is still in flight;
// on the FINAL iteration only the current group remains -> wait_group 0.
#define PIPE_WAIT(kb, KB) \
    do { if ((kb) + 1 < (KB)) asm volatile("cp.async.wait_group 1;" ::: "memory"); \
         else                 asm volatile("cp.async.wait_group 0;" ::: "memory"); } while (0)

#define MMA_H(c, a0,a1,a2,a3, b0,b1) \
    asm volatile("mma.sync.aligned.m16n8k16.row.col.f32.f16.f16.f32 " \
                 "{%0,%1,%2,%3}, {%4,%5,%6,%7}, {%8,%9}, {%0,%1,%2,%3};" \
                 : "+f"((c)[0]), "+f"((c)[1]), "+f"((c)[2]), "+f"((c)[3]) \
                 : "r"(a0), "r"(a1), "r"(a2), "r"(a3), "r"(b0), "r"(b1))

// ---------------- FP16 GEMM, 128x128 tile (EPI: 0 fp16 out, 2 gelu->frag) -----
template <int EPI>
__global__ void __launch_bounds__(256, 2) gemm_h(const __half* __restrict__ At,
                                                 const __half* __restrict__ Bt,
                                                 const float* __restrict__ bias,
                                                 const float* __restrict__ res,
                                                 void* __restrict__ Cv,
                                                 int M, int N, int K)
{
    __shared__ __align__(16) __half As[3][4096];
    __shared__ __align__(16) __half Bs[3][4096];

    const int tid = threadIdx.x;
    const int nb = blockIdx.x, mb = blockIdx.y;
    const int KB = K >> 5;
    const int KB16 = K >> 4;
    const int NB = N >> 7;
    const int lane = tid & 31, warp = tid >> 5;
    const int wmBase = (warp >> 2) * 4;
    const int wnBase = (warp & 3) * 4;
    const int g = lane >> 2, t4 = lane & 3;

    const __half* aBase = At + (size_t)mb * KB16 * 2048;
    const __half* bBase = Bt + (size_t)nb * 2048;

    float acc[16][4];
#pragma unroll
    for (int i = 0; i < 16; i++)
#pragma unroll
        for (int j = 0; j < 4; j++) acc[i][j] = 0.f;

    auto issue = [&](int s, int kb) {
        const __half* ab  = aBase + (size_t)kb * 4096;
        const __half* bb0 = bBase + (size_t)(kb * 2) * NB * 2048;
        const __half* bb1 = bBase + (size_t)(kb * 2 + 1) * NB * 2048;
        cp16(&As[s][tid * 8],        ab + tid * 8);
        cp16(&As[s][2048 + tid * 8], ab + 2048 + tid * 8);
        cp16(&Bs[s][tid * 8],        bb0 + tid * 8);
        cp16(&Bs[s][2048 + tid * 8], bb1 + tid * 8);
        asm volatile("cp.async.commit_group;" ::: "memory");
    };

    issue(0, 0);
    issue(1, 1);

    for (int kb = 0; kb < KB; kb++) {
        const int s = kb % 3;
        PIPE_WAIT(kb, KB);
        __syncthreads();
        if (kb + 2 < KB) issue((kb + 2) % 3, kb + 2);

#pragma unroll
        for (int kk = 0; kk < 2; kk++) {
            uint32_t a[4][4], b[4][2];
#pragma unroll
            for (int mi = 0; mi < 4; mi++) {
                const uint4 fa = *reinterpret_cast<const uint4*>(
                    &As[s][kk * 2048 + ((wmBase + mi) * 32 + lane) * 8]);
                a[mi][0] = fa.x; a[mi][1] = fa.y; a[mi][2] = fa.z; a[mi][3] = fa.w;
            }
#pragma unroll
            for (int ni = 0; ni < 4; ni++) {
                const uint2 fb = *reinterpret_cast<const uint2*>(
                    &Bs[s][kk * 2048 + ((wnBase + ni) * 32 + lane) * 4]);
                b[ni][0] = fb.x; b[ni][1] = fb.y;
            }
#pragma unroll
            for (int mi = 0; mi < 4; mi++)
#pragma unroll
                for (int ni = 0; ni < 4; ni++)
                    MMA_H(acc[mi * 4 + ni], a[mi][0], a[mi][1], a[mi][2], a[mi][3],
                          b[ni][0], b[ni][1]);
        }
    }

    const int rowBase = mb * 128;
    const int colBase = nb * 128;
    const int wm = (warp >> 2) * 64;
    const int wn = (warp & 3) * 32;
    const int KBo = N >> 4;
#pragma unroll
    for (int mi = 0; mi < 4; mi++) {
#pragma unroll
        for (int ni = 0; ni < 4; ni++) {
            float* c = acc[mi * 4 + ni];
            const int col = colBase + wn + ni * 8 + t4 * 2;
            const float2 bb = *reinterpret_cast<const float2*>(bias + col);
#pragma unroll
            for (int h = 0; h < 2; h++) {
                const int row = rowBase + wm + mi * 16 + g + h * 8;
                float o0 = c[h * 2 + 0] + bb.x;
                float o1 = c[h * 2 + 1] + bb.y;
                if (EPI == 0) {
                    __half* Ch = (__half*)Cv;
                    *reinterpret_cast<__half2*>(Ch + (size_t)row * N + col) =
                        __floats2half2_rn(o0, o1);
                } else {
                    __half* Ch = (__half*)Cv;
                    *reinterpret_cast<__half2*>(Ch + fmIdx(row, col, KBo)) =
                        __floats2half2_rn(gelu_exact(o0), gelu_exact(o1));
                }
            }
        }
    }
}

// ---------------- FP16 GEMM, 64x128 tile, EPI = bias+res -> fp32 --------------
__global__ void __launch_bounds__(256, 3) gemm_h64(const __half* __restrict__ At,
                                                   const __half* __restrict__ Bt,
                                                   const float* __restrict__ bias,
                                                   const float* __restrict__ res,
                                                   float* __restrict__ C,
                                                   int M, int N, int K)
{
    __shared__ __align__(16) __half As[3][2048];   // 2 kk x 1024 (4 m-tiles)
    __shared__ __align__(16) __half Bs[3][4096];

    const int tid = threadIdx.x;
    const int nb = blockIdx.x, mb = blockIdx.y;
    const int KB = K >> 5;
    const int KB16 = K >> 4;
    const int NB = N >> 7;
    const int lane = tid & 31, warp = tid >> 5;
    const int wmBase = (warp >> 2) * 2;   // m-tile base (0 or 2)
    const int wnBase = (warp & 3) * 4;
    const int g = lane >> 2, t4 = lane & 3;
    const int mhalf = mb & 1, mblk = mb >> 1;

    const __half* aBase = At + (size_t)mblk * KB16 * 2048 + mhalf * 1024;
    const __half* bBase = Bt + (size_t)nb * 2048;

    float acc[8][4];
#pragma unroll
    for (int i = 0; i < 8; i++)
#pragma unroll
        for (int j = 0; j < 4; j++) acc[i][j] = 0.f;

    auto issue = [&](int s, int kb) {
        const __half* ab0 = aBase + (size_t)(kb * 2) * 2048;
        const __half* ab1 = aBase + (size_t)(kb * 2 + 1) * 2048;
        if (tid < 128) cp16(&As[s][tid * 8], ab0 + tid * 8);
        else           cp16(&As[s][1024 + (tid - 128) * 8], ab1 + (tid - 128) * 8);
        const __half* bb0 = bBase + (size_t)(kb * 2) * NB * 2048;
        const __half* bb1 = bBase + (size_t)(kb * 2 + 1) * NB * 2048;
        cp16(&Bs[s][tid * 8],        bb0 + tid * 8);
        cp16(&Bs[s][2048 + tid * 8], bb1 + tid * 8);
        asm volatile("cp.async.commit_group;" ::: "memory");
    };

    issue(0, 0);
    issue(1, 1);

    for (int kb = 0; kb < KB; kb++) {
        const int s = kb % 3;
        PIPE_WAIT(kb, KB);
        __syncthreads();
        if (kb + 2 < KB) issue((kb + 2) % 3, kb + 2);

#pragma unroll
        for (int kk = 0; kk < 2; kk++) {
            uint32_t a[2][4], b[4][2];
#pragma unroll
            for (int mi = 0; mi < 2; mi++) {
                const uint4 fa = *reinterpret_cast<const uint4*>(
                    &As[s][kk * 1024 + (wmBase + mi) * 256 + lane * 8]);
                a[mi][0] = fa.x; a[mi][1] = fa.y; a[mi][2] = fa.z; a[mi][3] = fa.w;
            }
#pragma unroll
            for (int ni = 0; ni < 4; ni++) {
                const uint2 fb = *reinterpret_cast<const uint2*>(
                    &Bs[s][kk * 2048 + ((wnBase + ni) * 32 + lane) * 4]);
                b[ni][0] = fb.x; b[ni][1] = fb.y;
            }
#pragma unroll
            for (int mi = 0; mi < 2; mi++)
#pragma unroll
                for (int ni = 0; ni < 4; ni++)
                    MMA_H(acc[mi * 4 + ni], a[mi][0], a[mi][1], a[mi][2], a[mi][3],
                          b[ni][0], b[ni][1]);
        }
    }

    const int rowBase = mb * 64;
    const int colBase = nb * 128;
    const int wm = (warp >> 2) * 32;
    const int wn = (warp & 3) * 32;
#pragma unroll
    for (int mi = 0; mi < 2; mi++) {
#pragma unroll
        for (int ni = 0; ni < 4; ni++) {
            float* c = acc[mi * 4 + ni];
            const int col = colBase + wn + ni * 8 + t4 * 2;
            const float2 bb = *reinterpret_cast<const float2*>(bias + col);
#pragma unroll
            for (int h = 0; h < 2; h++) {
                const int row = rowBase + wm + mi * 16 + g + h * 8;
                const float2 r2 = *reinterpret_cast<const float2*>(res + (size_t)row * N + col);
                *reinterpret_cast<float2*>(C + (size_t)row * N + col) =
                    make_float2(c[h * 2 + 0] + bb.x + r2.x, c[h * 2 + 1] + bb.y + r2.y);
            }
        }
    }
}

// ---------------- flash attention: register softmax, 128-row Q tile -----------
// grid (S/128, B*H), 256 threads; warp w owns rows [w*16, w*16+16), all 64 dims.
#define KVST 72
#define FLASH_SMEM (3 * 2 * 64 * KVST * 2)   // 3-stage K+V ring, fp16
__global__ void __launch_bounds__(256, 2) flash_reg(const __half* __restrict__ qkv,
                                                    __half* __restrict__ outT)
{
    extern __shared__ __half kvs[];
    __half* Ks = kvs;                       // [3][64*KVST]
    __half* Vs = kvs + 3 * 64 * KVST;       // [3][64*KVST]

    const int tid = threadIdx.x;
    const int lane = tid & 31, warp = tid >> 5;
    const int g = lane >> 2, t4 = lane & 3;
    const int bh = blockIdx.y;
    const int b = bh / Hn, h = bh % Hn;
    const int t0 = blockIdx.x * 128;
    const int rw = t0 + warp * 16;
    const int lr = tid >> 2, lc = (tid & 3) * 16;

    // Q fragments straight from gmem (row-major fp16 qkv)
    uint32_t aq[4][4];
    {
        const __half* q0 = qkv + (size_t)(b * Sn + rw + g) * QKVLD + h * Dn + 2 * t4;
        const __half* q1 = q0 + (size_t)8 * QKVLD;
#pragma unroll
        for (int ks = 0; ks < 4; ks++) {
            const int k0 = ks * 16;
            aq[ks][0] = *reinterpret_cast<const uint32_t*>(q0 + k0);
            aq[ks][1] = *reinterpret_cast<const uint32_t*>(q1 + k0);
            aq[ks][2] = *reinterpret_cast<const uint32_t*>(q0 + k0 + 8);
            aq[ks][3] = *reinterpret_cast<const uint32_t*>(q1 + k0 + 8);
        }
    }

    float o[8][4];
#pragma unroll
    for (int ni = 0; ni < 8; ni++)
#pragma unroll
        for (int j = 0; j < 4; j++) o[ni][j] = 0.f;
    float m0 = -3e38f, m1 = -3e38f, l0 = 0.f, l1 = 0.f;

    auto loadKV = [&](int buf, int j0) {
        const __half* kr = qkv + (size_t)(b * Sn + j0 + lr) * QKVLD + DMn + h * Dn + lc;
        const __half* vr = kr + DMn;
        __half* kd = Ks + buf * (64 * KVST) + lr * KVST + lc;
        __half* vd = Vs + buf * (64 * KVST) + lr * KVST + lc;
        cp16(kd, kr); cp16(kd + 8, kr + 8);
        cp16(vd, vr); cp16(vd + 8, vr + 8);
        asm volatile("cp.async.commit_group;" ::: "memory");
    };

    loadKV(0, 0);
    loadKV(1, 64);

    for (int j = 0; j < 16; j++) {
        const int s = j % 3;
        PIPE_WAIT(j, 16);
        __syncthreads();
        if (j + 2 < 16) loadKV((j + 2) % 3, (j + 2) * 64);

        const __half* Kb = Ks + s * (64 * KVST);
        const __half* Vb = Vs + s * (64 * KVST);

        // S = Q K^T (scaled)
        float sc[8][4];
#pragma unroll
        for (int ni = 0; ni < 8; ni++)
#pragma unroll
            for (int jj = 0; jj < 4; jj++) sc[ni][jj] = 0.f;
#pragma unroll
        for (int ks = 0; ks < 4; ks++) {
            const int k0 = ks * 16;
#pragma unroll
            for (int ni = 0; ni < 8; ni++) {
                const __half* bp = Kb + (ni * 8 + g) * KVST + k0 + 2 * t4;
                const uint32_t b0 = *reinterpret_cast<const uint32_t*>(bp);
                const uint32_t b1 = *reinterpret_cast<const uint32_t*>(bp + 8);
                MMA_H(sc[ni], aq[ks][0], aq[ks][1], aq[ks][2], aq[ks][3], b0, b1);
            }
        }

        // row stats in registers (rows g and g+8)
        float mx0 = -3e38f, mx1 = -3e38f;
#pragma unroll
        for (int ni = 0; ni < 8; ni++) {
#pragma unroll
            for (int jj = 0; jj < 4; jj++) sc[ni][jj] *= 0.125f;
            mx0 = fmaxf(mx0, fmaxf(sc[ni][0], sc[ni][1]));
            mx1 = fmaxf(mx1, fmaxf(sc[ni][2], sc[ni][3]));
        }
        mx0 = fmaxf(mx0, __shfl_xor_sync(0xffffffffu, mx0, 1));
        mx0 = fmaxf(mx0, __shfl_xor_sync(0xffffffffu, mx0, 2));
        mx1 = fmaxf(mx1, __shfl_xor_sync(0xffffffffu, mx1, 1));
        mx1 = fmaxf(mx1, __shfl_xor_sync(0xffffffffu, mx1, 2));

        const float mn0 = fmaxf(m0, mx0), mn1 = fmaxf(m1, mx1);
        const float al0 = __expf(m0 - mn0), al1 = __expf(m1 - mn1);
        m0 = mn0; m1 = mn1;

        uint32_t p[8][2];
        float sum0 = 0.f, sum1 = 0.f;
#pragma unroll
        for (int ni = 0; ni < 8; ni++) {
            const __half2 h20 = __floats2half2_rn(__expf(sc[ni][0] - m0),
                                                  __expf(sc[ni][1] - m0));
            const __half2 h21 = __floats2half2_rn(__expf(sc[ni][2] - m1),
                                                  __expf(sc[ni][3] - m1));
            p[ni][0] = *reinterpret_cast<const uint32_t*>(&h20);
            p[ni][1] = *reinterpret_cast<const uint32_t*>(&h21);
            sum0 += __low2float(h20) + __high2float(h20);
            sum1 += __low2float(h21) + __high2float(h21);
        }
        sum0 += __shfl_xor_sync(0xffffffffu, sum0, 1);
        sum0 += __shfl_xor_sync(0xffffffffu, sum0, 2);
        sum1 += __shfl_xor_sync(0xffffffffu, sum1, 1);
        sum1 += __shfl_xor_sync(0xffffffffu, sum1, 2);
        l0 = l0 * al0 + sum0;
        l1 = l1 * al1 + sum1;

#pragma unroll
        for (int ni = 0; ni < 8; ni++) {
            o[ni][0] *= al0; o[ni][1] *= al0;
            o[ni][2] *= al1; o[ni][3] *= al1;
        }

        // O += P V  (A from p regs, B = 2-byte V loads)
#pragma unroll
        for (int ks = 0; ks < 4; ks++) {
            const int k0 = ks * 16;
#pragma unroll
            for (int ni = 0; ni < 8; ni++) {
                const __half* vp = Vb + (k0 + 2 * t4) * KVST + ni * 8 + g;
                const uint32_t v00 = *reinterpret_cast<const uint16_t*>(vp);
                const uint32_t v01 = *reinterpret_cast<const uint16_t*>(vp + KVST);
                const uint32_t v10 = *reinterpret_cast<const uint16_t*>(vp + 8 * KVST);
                const uint32_t v11 = *reinterpret_cast<const uint16_t*>(vp + 9 * KVST);
                const uint32_t b0 = v00 | (v01 << 16);
                const uint32_t b1 = v10 | (v11 << 16);
                MMA_H(o[ni], p[2 * ks][0], p[2 * ks][1], p[2 * ks + 1][0], p[2 * ks + 1][1],
                      b0, b1);
            }
        }
    }

    // normalize, write fragment-major fp16
    const float il0 = 1.0f / l0, il1 = 1.0f / l1;
    const int KBo = DMn >> 4;
    const int mr0 = b * Sn + rw + g;
#pragma unroll
    for (int ni = 0; ni < 8; ni++) {
        const int k = h * Dn + ni * 8 + 2 * t4;
        *reinterpret_cast<__half2*>(outT + fmIdx(mr0, k, KBo)) =
            __floats2half2_rn(o[ni][0] * il0, o[ni][1] * il0);
        *reinterpret_cast<__half2*>(outT + fmIdx(mr0 + 8, k, KBo)) =
            __floats2half2_rn(o[ni][2] * il1, o[ni][3] * il1);
    }
}

// ---------------- launch ------------------------------------------------------
extern "C" void kernel_launch(void* const* d_in, const int* in_sizes, int n_in,
                              void* d_out, int out_size)
{
    const float* x        = (const float*)d_in[0];
    const float* ln1_s    = (const float*)d_in[1];
    const float* ln1_o    = (const float*)d_in[2];
    const float* wq       = (const float*)d_in[3];
    const float* bq       = (const float*)d_in[4];
    const float* wk       = (const float*)d_in[5];
    const float* bk       = (const float*)d_in[6];
    const float* wv       = (const float*)d_in[7];
    const float* bv       = (const float*)d_in[8];
    const float* wo       = (const float*)d_in[9];
    const float* bo       = (const float*)d_in[10];
    const float* ln2_s    = (const float*)d_in[11];
    const float* ln2_o    = (const float*)d_in[12];
    const float* fc1_w    = (const float*)d_in[13];
    const float* fc1_b    = (const float*)d_in[14];
    const float* fc2_w    = (const float*)d_in[15];
    const float* fc2_b    = (const float*)d_in[16];
    float* out            = (float*)d_out;

    float *px1, *pbqkv;
    __half *phT, *pqkv, *pf1T, *pwr;
    cudaGetSymbolAddress((void**)&phT,   g_hT);
    cudaGetSymbolAddress((void**)&pqkv,  g_qkv);
    cudaGetSymbolAddress((void**)&px1,   g_x1);
    cudaGetSymbolAddress((void**)&pf1T,  g_f1T);
    cudaGetSymbolAddress((void**)&pwr,   g_wr);
    cudaGetSymbolAddress((void**)&pbqkv, g_bqkv);

    __half* rwqkv = pwr;                                     // fused, NBtot=30
    __half* rwo   = pwr + (size_t)3 * WSZ_DM;
    __half* rfc1  = pwr + (size_t)4 * WSZ_DM;
    __half* rfc2  = pwr + (size_t)4 * WSZ_DM + WSZ_FC;

    static bool attr_done = false;
    if (!attr_done) {
        cudaFuncSetAttribute(flash_reg, cudaFuncAttributeMaxDynamicSharedMemorySize, FLASH_SMEM);
        attr_done = true;
    }

    // 0) ALL weight transforms in one launch (9600 CTAs)
    {
        WtArgs wa;
        wa.src[0] = wq;   wa.dst[0] = rwqkv; wa.K[0] = DMn; wa.N[0] = DMn; wa.NBtot[0] = 30; wa.nbOff[0] = 0;
        wa.src[1] = wk;   wa.dst[1] = rwqkv; wa.K[1] = DMn; wa.N[1] = DMn; wa.NBtot[1] = 30; wa.nbOff[1] = 10;
        wa.src[2] = wv;   wa.dst[2] = rwqkv; wa.K[2] = DMn; wa.N[2] = DMn; wa.NBtot[2] = 30; wa.nbOff[2] = 20;
        wa.src[3] = wo;   wa.dst[3] = rwo;   wa.K[3] = DMn; wa.N[3] = DMn; wa.NBtot[3] = 10; wa.nbOff[3] = 0;
        wa.src[4] = fc1_w; wa.dst[4] = rfc1; wa.K[4] = DMn; wa.N[4] = DFn; wa.NBtot[4] = 40; wa.nbOff[4] = 0;
        wa.src[5] = fc2_w; wa.dst[5] = rfc2; wa.K[5] = DFn; wa.N[5] = DMn; wa.NBtot[5] = 10; wa.nbOff[5] = 0;
        wa.blockStart[0] = 0;
        wa.blockStart[1] = 800;     // wq: (1280/16)*(1280/128) = 80*10
        wa.blockStart[2] = 1600;
        wa.blockStart[3] = 2400;
        wa.blockStart[4] = 3200;
        wa.blockStart[5] = 6400;    // fc1: 80*40 = 3200
        wa.blockStart[6] = 9600;    // fc2: 320*10 = 3200
        btrans_all<<<9600, 256>>>(wa);
        bias_concat<<<QKVLD / 256, 256>>>(bq, bk, bv, pbqkv);
    }

    // 1) LN1 -> fragment-major hT
    ln_ft<<<NTOK, 256>>>(x, ln1_s, ln1_o, phT);

    // 2) fused QKV projection -> qkv (plain fp16)
    {
        dim3 grid(QKVLD / 128, NTOK / 128);  // (30, 32)
        gemm_h<0><<<grid, 256>>>(phT, rwqkv, pbqkv, nullptr, pqkv, NTOK, QKVLD, DMn);
    }

    // 3) flash attention (register softmax) -> fragment-major hT (reuse)
    {
        dim3 grid(Sn / 128, NBH);            // (8, 80)
        flash_reg<<<grid, 256, FLASH_SMEM>>>(pqkv, phT);
    }

    // 4) O-proj + residual(x) -> x1 (fp32), 64-row tiles
    {
        dim3 grid(DMn / 128, NTOK / 64);     // (10, 64)
        gemm_h64<<<grid, 256>>>(phT, rwo, bo, x, px1, NTOK, DMn, DMn);
    }

    // 5) LN2 -> fragment-major hT (reuse)
    ln_ft<<<NTOK, 256>>>(px1, ln2_s, ln2_o, phT);

    // 6) FC1 + GELU -> fragment-major f1T
    {
        dim3 grid(DFn / 128, NTOK / 128);    // (40, 32)
        gemm_h<2><<<grid, 256>>>(phT, rfc1, fc1_b, nullptr, pf1T, NTOK, DFn, DMn);
    }

    // 7) FC2 + residual(x1) -> out, 64-row tiles
    {
        dim3 grid(DMn / 128, NTOK / 64);     // (10, 64)
        gemm_h64<<<grid, 256>>>(pf1T, rfc2, fc2_b, px1, out, NTOK, DMn, DFn);
    }
}

// round 13
// speedup vs baseline: 1.0474x; 1.0210x over previous
#include <cuda_runtime.h>
#include <cuda_fp16.h>
#include <math.h>
#include <stdint.h>

// Problem constants
#define Bn   4
#define Sn   1024
#define Hn   20
#define Dn   64
#define DMn  1280
#define DFn  5120
#define NTOK 4096           // Bn*Sn
#define NBH  80             // Bn*Hn
#define EPSLN 1e-5f
#define QKVLD 3840          // row stride of fused qkv output

// ---------------- scratch (static device globals; no allocation) -------------
__device__ __half g_hT  [(size_t)NTOK * DMn];          // fragment-major A (reused 3x)
__device__ __half g_qkv [(size_t)NTOK * QKVLD];        // fused q|k|v (plain fp16)
__device__ float  g_x1  [(size_t)NTOK * DMn];          // residual 1
__device__ __half g_f1T [(size_t)NTOK * DFn];          // fragment-major FC1 out
__device__ __half g_wr  [19660800];                    // fragment-major weights (fp16)
__device__ float  g_bqkv[QKVLD];                       // concat bias

#define WSZ_DM (DMn * DMn)          // 1,638,400
#define WSZ_FC (DMn * DFn)          // 6,553,600

// ---------------- fragment-major index helper ---------------------------------
__device__ __forceinline__ size_t fmIdx(int m, int k, int KB) {
    const int mb = m >> 7, mr = m & 127;
    const int kb = k >> 4, kr = k & 15;
    const int mt = mr >> 4, hh = (mr >> 3) & 1, gg = mr & 7;
    const int t4k = (kr >> 1) & 3, khi = kr >> 3, klo = kr & 1;
    return ((size_t)mb * KB + kb) * 2048 +
           (size_t)((mt * 32 + gg * 4 + t4k) * 8 + khi * 4 + hh * 2 + klo);
}

// ---------------- ALL weight transforms in ONE launch --------------------------
struct WtArgs {
    const float* src[6];
    __half*      dst[6];
    int K[6], N[6], NBtot[6], nbOff[6];
    int blockStart[7];
};

__global__ void __launch_bounds__(256) btrans_all(WtArgs wa)
{
    __shared__ __half s[2048];
    const int gb = blockIdx.x;
    int seg = 0;
#pragma unroll
    for (int i = 1; i < 6; i++) seg += (gb >= wa.blockStart[i]);
    const int lb = gb - wa.blockStart[seg];
    const int N = wa.N[seg];
    const int NBn = N >> 7;
    const int nb = lb % NBn, kb = lb / NBn;
    const int tid = threadIdx.x;
    const float* bb = wa.src[seg] + (size_t)(kb * 16) * N + nb * 128;

#pragma unroll
    for (int e4 = tid; e4 < 512; e4 += 256) {
        const int k = e4 >> 5, colq = (e4 & 31) * 4;
        const float4 f = *reinterpret_cast<const float4*>(bb + (size_t)k * N + colq);
        const int t4 = (k >> 1) & 3, khi = (k >> 3) & 1, klo = k & 1;
        const float vv[4] = {f.x, f.y, f.z, f.w};
#pragma unroll
        for (int j = 0; j < 4; j++) {
            const int col = colq + j;
            const int ni = col >> 3, gg = col & 7;
            s[(ni * 32 + gg * 4 + t4) * 4 + khi * 2 + klo] = __float2half_rn(vv[j]);
        }
    }
    __syncthreads();
    __half* ob = wa.dst[seg] + ((size_t)kb * wa.NBtot[seg] + wa.nbOff[seg] + nb) * 2048;
    *reinterpret_cast<uint4*>(ob + tid * 8) = *reinterpret_cast<const uint4*>(s + tid * 8);
}

// ---------------- bias concat for fused QKV -----------------------------------
__global__ void __launch_bounds__(256) bias_concat(const float* __restrict__ bq,
                                                   const float* __restrict__ bk,
                                                   const float* __restrict__ bv,
                                                   float* __restrict__ o)
{
    const int i = blockIdx.x * 256 + threadIdx.x;
    if (i < DMn) o[i] = bq[i];
    else if (i < 2 * DMn) o[i] = bk[i - DMn];
    else if (i < 3 * DMn) o[i] = bv[i - 2 * DMn];
}

// ---------------- LayerNorm fused with fragment-major fp16 output -------------
__global__ void __launch_bounds__(256) ln_ft(const float* __restrict__ x,
                                             const float* __restrict__ sc,
                                             const float* __restrict__ off,
                                             __half* __restrict__ yT)
{
    const int row = blockIdx.x;
    const float* xr = x + (size_t)row * DMn;
    const int t = threadIdx.x;
    const int lane = t & 31, wid = t >> 5;

    __shared__ float sh[32];
    __shared__ float s_mean, s_rstd;

    float2 p0 = *reinterpret_cast<const float2*>(xr + 2 * t);
    float2 p1 = *reinterpret_cast<const float2*>(xr + 512 + 2 * t);
    float2 p2 = make_float2(0.f, 0.f);
    if (t < 128) p2 = *reinterpret_cast<const float2*>(xr + 1024 + 2 * t);

    float s = p0.x + p0.y + p1.x + p1.y + p2.x + p2.y;
#pragma unroll
    for (int o = 16; o; o >>= 1) s += __shfl_xor_sync(0xffffffffu, s, o);
    if (lane == 0) sh[wid] = s;
    __syncthreads();
    if (wid == 0) {
        float v = (lane < 8) ? sh[lane] : 0.f;
#pragma unroll
        for (int o = 4; o; o >>= 1) v += __shfl_xor_sync(0xffffffffu, v, o);
        if (lane == 0) s_mean = v * (1.0f / DMn);
    }
    __syncthreads();
    const float mean = s_mean;
    __syncthreads();

    float vs = 0.f;
    {
        float d;
        d = p0.x - mean; vs += d * d;
        d = p0.y - mean; vs += d * d;
        d = p1.x - mean; vs += d * d;
        d = p1.y - mean; vs += d * d;
        if (t < 128) {
            d = p2.x - mean; vs += d * d;
            d = p2.y - mean; vs += d * d;
        }
    }
#pragma unroll
    for (int o = 16; o; o >>= 1) vs += __shfl_xor_sync(0xffffffffu, vs, o);
    if (lane == 0) sh[wid] = vs;
    __syncthreads();
    if (wid == 0) {
        float v = (lane < 8) ? sh[lane] : 0.f;
#pragma unroll
        for (int o = 4; o; o >>= 1) v += __shfl_xor_sync(0xffffffffu, v, o);
        if (lane == 0) s_rstd = rsqrtf(v * (1.0f / DMn) + EPSLN);
    }
    __syncthreads();
    const float rstd = s_rstd;

    const int KB = DMn >> 4;
    {
        const int c = 2 * t;
        const float2 g2 = *reinterpret_cast<const float2*>(sc + c);
        const float2 b2 = *reinterpret_cast<const float2*>(off + c);
        *reinterpret_cast<__half2*>(yT + fmIdx(row, c, KB)) =
            __floats2half2_rn((p0.x - mean) * rstd * g2.x + b2.x,
                              (p0.y - mean) * rstd * g2.y + b2.y);
    }
    {
        const int c = 512 + 2 * t;
        const float2 g2 = *reinterpret_cast<const float2*>(sc + c);
        const float2 b2 = *reinterpret_cast<const float2*>(off + c);
        *reinterpret_cast<__half2*>(yT + fmIdx(row, c, KB)) =
            __floats2half2_rn((p1.x - mean) * rstd * g2.x + b2.x,
                              (p1.y - mean) * rstd * g2.y + b2.y);
    }
    if (t < 128) {
        const int c = 1024 + 2 * t;
        const float2 g2 = *reinterpret_cast<const float2*>(sc + c);
        const float2 b2 = *reinterpret_cast<const float2*>(off + c);
        *reinterpret_cast<__half2*>(yT + fmIdx(row, c, KB)) =
            __floats2half2_rn((p2.x - mean) * rstd * g2.x + b2.x,
                              (p2.y - mean) * rstd * g2.y + b2.y);
    }
}

// ---------------- GEMM helpers -------------------------------------------------
__device__ __forceinline__ float gelu_exact(float v) {
    return 0.5f * v * (1.0f + erff(v * 0.70710678118654752f));
}

__device__ __forceinline__ void cp16(void* smem_dst, const void* gsrc) {
    uint32_t s = (uint32_t)__cvta_generic_to_shared(smem_dst);
    asm volatile("cp.async.cg.shared.global [%0], [%1], 16;" :: "r"(s), "l"(gsrc));
}

// 3-stage drain (flash): wait_group 1 while another group is in flight, else 0.
#define PIPE_WAIT(kb, KB) \
    do { if ((kb) + 1 < (KB)) asm volatile("cp.async.wait_group 1;" ::: "memory"); \
         else                 asm volatile("cp.async.wait_group 0;" ::: "memory"); } while (0)

// 4-stage drain (GEMMs): groups kb..min(kb+2,KB-1) outstanding at the wait.
// Group kb must complete -> allow (#outstanding - 1) incomplete.
#define PIPE_WAIT4(kb, KB) \
    do { const int _rem = (KB) - 1 - (kb); \
         if (_rem >= 2)      asm volatile("cp.async.wait_group 2;" ::: "memory"); \
         else if (_rem == 1) asm volatile("cp.async.wait_group 1;" ::: "memory"); \
         else                asm volatile("cp.async.wait_group 0;" ::: "memory"); } while (0)

#define MMA_H(c, a0,a1,a2,a3, b0,b1) \
    asm volatile("mma.sync.aligned.m16n8k16.row.col.f32.f16.f16.f32 " \
                 "{%0,%1,%2,%3}, {%4,%5,%6,%7}, {%8,%9}, {%0,%1,%2,%3};" \
                 : "+f"((c)[0]), "+f"((c)[1]), "+f"((c)[2]), "+f"((c)[3]) \
                 : "r"(a0), "r"(a1), "r"(a2), "r"(a3), "r"(b0), "r"(b1))

// ---------------- FP16 GEMM, 128x128 tile, 4-stage (EPI: 0 fp16, 2 gelu) ------
template <int EPI>
__global__ void __launch_bounds__(256, 2) gemm_h(const __half* __restrict__ At,
                                                 const __half* __restrict__ Bt,
                                                 const float* __restrict__ bias,
                                                 const float* __restrict__ res,
                                                 void* __restrict__ Cv,
                                                 int M, int N, int K)
{
    __shared__ __align__(16) __half As[4][4096];
    __shared__ __align__(16) __half Bs[4][4096];

    const int tid = threadIdx.x;
    const int nb = blockIdx.x, mb = blockIdx.y;
    const int KB = K >> 5;
    const int KB16 = K >> 4;
    const int NB = N >> 7;
    const int lane = tid & 31, warp = tid >> 5;
    const int wmBase = (warp >> 2) * 4;
    const int wnBase = (warp & 3) * 4;
    const int g = lane >> 2, t4 = lane & 3;

    const __half* aBase = At + (size_t)mb * KB16 * 2048;
    const __half* bBase = Bt + (size_t)nb * 2048;

    float acc[16][4];
#pragma unroll
    for (int i = 0; i < 16; i++)
#pragma unroll
        for (int j = 0; j < 4; j++) acc[i][j] = 0.f;

    auto issue = [&](int s, int kb) {
        const __half* ab  = aBase + (size_t)kb * 4096;
        const __half* bb0 = bBase + (size_t)(kb * 2) * NB * 2048;
        const __half* bb1 = bBase + (size_t)(kb * 2 + 1) * NB * 2048;
        cp16(&As[s][tid * 8],        ab + tid * 8);
        cp16(&As[s][2048 + tid * 8], ab + 2048 + tid * 8);
        cp16(&Bs[s][tid * 8],        bb0 + tid * 8);
        cp16(&Bs[s][2048 + tid * 8], bb1 + tid * 8);
        asm volatile("cp.async.commit_group;" ::: "memory");
    };

    issue(0, 0);
    issue(1, 1);
    issue(2, 2);

    for (int kb = 0; kb < KB; kb++) {
        const int s = kb & 3;
        PIPE_WAIT4(kb, KB);
        __syncthreads();
        if (kb + 3 < KB) issue((kb + 3) & 3, kb + 3);

#pragma unroll
        for (int kk = 0; kk < 2; kk++) {
            uint32_t a[4][4], b[4][2];
#pragma unroll
            for (int mi = 0; mi < 4; mi++) {
                const uint4 fa = *reinterpret_cast<const uint4*>(
                    &As[s][kk * 2048 + ((wmBase + mi) * 32 + lane) * 8]);
                a[mi][0] = fa.x; a[mi][1] = fa.y; a[mi][2] = fa.z; a[mi][3] = fa.w;
            }
#pragma unroll
            for (int ni = 0; ni < 4; ni++) {
                const uint2 fb = *reinterpret_cast<const uint2*>(
                    &Bs[s][kk * 2048 + ((wnBase + ni) * 32 + lane) * 4]);
                b[ni][0] = fb.x; b[ni][1] = fb.y;
            }
#pragma unroll
            for (int mi = 0; mi < 4; mi++)
#pragma unroll
                for (int ni = 0; ni < 4; ni++)
                    MMA_H(acc[mi * 4 + ni], a[mi][0], a[mi][1], a[mi][2], a[mi][3],
                          b[ni][0], b[ni][1]);
        }
    }

    const int rowBase = mb * 128;
    const int colBase = nb * 128;
    const int wm = (warp >> 2) * 64;
    const int wn = (warp & 3) * 32;
    const int KBo = N >> 4;
#pragma unroll
    for (int mi = 0; mi < 4; mi++) {
#pragma unroll
        for (int ni = 0; ni < 4; ni++) {
            float* c = acc[mi * 4 + ni];
            const int col = colBase + wn + ni * 8 + t4 * 2;
            const float2 bb = *reinterpret_cast<const float2*>(bias + col);
#pragma unroll
            for (int h = 0; h < 2; h++) {
                const int row = rowBase + wm + mi * 16 + g + h * 8;
                float o0 = c[h * 2 + 0] + bb.x;
                float o1 = c[h * 2 + 1] + bb.y;
                if (EPI == 0) {
                    __half* Ch = (__half*)Cv;
                    *reinterpret_cast<__half2*>(Ch + (size_t)row * N + col) =
                        __floats2half2_rn(o0, o1);
                } else {
                    __half* Ch = (__half*)Cv;
                    *reinterpret_cast<__half2*>(Ch + fmIdx(row, col, KBo)) =
                        __floats2half2_rn(gelu_exact(o0), gelu_exact(o1));
                }
            }
        }
    }
}

// ---------------- FP16 GEMM, 64x128 tile, 4-stage, EPI = bias+res -> fp32 -----
__global__ void __launch_bounds__(256, 3) gemm_h64(const __half* __restrict__ At,
                                                   const __half* __restrict__ Bt,
                                                   const float* __restrict__ bias,
                                                   const float* __restrict__ res,
                                                   float* __restrict__ C,
                                                   int M, int N, int K)
{
    __shared__ __align__(16) __half As[4][2048];
    __shared__ __align__(16) __half Bs[4][4096];

    const int tid = threadIdx.x;
    const int nb = blockIdx.x, mb = blockIdx.y;
    const int KB = K >> 5;
    const int KB16 = K >> 4;
    const int NB = N >> 7;
    const int lane = tid & 31, warp = tid >> 5;
    const int wmBase = (warp >> 2) * 2;
    const int wnBase = (warp & 3) * 4;
    const int g = lane >> 2, t4 = lane & 3;
    const int mhalf = mb & 1, mblk = mb >> 1;

    const __half* aBase = At + (size_t)mblk * KB16 * 2048 + mhalf * 1024;
    const __half* bBase = Bt + (size_t)nb * 2048;

    float acc[8][4];
#pragma unroll
    for (int i = 0; i < 8; i++)
#pragma unroll
        for (int j = 0; j < 4; j++) acc[i][j] = 0.f;

    auto issue = [&](int s, int kb) {
        const __half* ab0 = aBase + (size_t)(kb * 2) * 2048;
        const __half* ab1 = aBase + (size_t)(kb * 2 + 1) * 2048;
        if (tid < 128) cp16(&As[s][tid * 8], ab0 + tid * 8);
        else           cp16(&As[s][1024 + (tid - 128) * 8], ab1 + (tid - 128) * 8);
        const __half* bb0 = bBase + (size_t)(kb * 2) * NB * 2048;
        const __half* bb1 = bBase + (size_t)(kb * 2 + 1) * NB * 2048;
        cp16(&Bs[s][tid * 8],        bb0 + tid * 8);
        cp16(&Bs[s][2048 + tid * 8], bb1 + tid * 8);
        asm volatile("cp.async.commit_group;" ::: "memory");
    };

    issue(0, 0);
    issue(1, 1);
    issue(2, 2);

    for (int kb = 0; kb < KB; kb++) {
        const int s = kb & 3;
        PIPE_WAIT4(kb, KB);
        __syncthreads();
        if (kb + 3 < KB) issue((kb + 3) & 3, kb + 3);

#pragma unroll
        for (int kk = 0; kk < 2; kk++) {
            uint32_t a[2][4], b[4][2];
#pragma unroll
            for (int mi = 0; mi < 2; mi++) {
                const uint4 fa = *reinterpret_cast<const uint4*>(
                    &As[s][kk * 1024 + (wmBase + mi) * 256 + lane * 8]);
                a[mi][0] = fa.x; a[mi][1] = fa.y; a[mi][2] = fa.z; a[mi][3] = fa.w;
            }
#pragma unroll
            for (int ni = 0; ni < 4; ni++) {
                const uint2 fb = *reinterpret_cast<const uint2*>(
                    &Bs[s][kk * 2048 + ((wnBase + ni) * 32 + lane) * 4]);
                b[ni][0] = fb.x; b[ni][1] = fb.y;
            }
#pragma unroll
            for (int mi = 0; mi < 2; mi++)
#pragma unroll
                for (int ni = 0; ni < 4; ni++)
                    MMA_H(acc[mi * 4 + ni], a[mi][0], a[mi][1], a[mi][2], a[mi][3],
                          b[ni][0], b[ni][1]);
        }
    }

    const int rowBase = mb * 64;
    const int colBase = nb * 128;
    const int wm = (warp >> 2) * 32;
    const int wn = (warp & 3) * 32;
#pragma unroll
    for (int mi = 0; mi < 2; mi++) {
#pragma unroll
        for (int ni = 0; ni < 4; ni++) {
            float* c = acc[mi * 4 + ni];
            const int col = colBase + wn + ni * 8 + t4 * 2;
            const float2 bb = *reinterpret_cast<const float2*>(bias + col);
#pragma unroll
            for (int h = 0; h < 2; h++) {
                const int row = rowBase + wm + mi * 16 + g + h * 8;
                const float2 r2 = *reinterpret_cast<const float2*>(res + (size_t)row * N + col);
                *reinterpret_cast<float2*>(C + (size_t)row * N + col) =
                    make_float2(c[h * 2 + 0] + bb.x + r2.x, c[h * 2 + 1] + bb.y + r2.y);
            }
        }
    }
}

// ---------------- flash attention: register softmax, PERSISTENT ---------------
// grid = 2*numSM persistent CTAs loop over 640 (q-tile, head) work items.
#define KVST 72
#define FLASH_ITEMS ((Sn / 128) * NBH)       // 8 * 80 = 640
#define FLASH_SMEM (3 * 2 * 64 * KVST * 2)   // 3-stage K+V ring, fp16
__global__ void __launch_bounds__(256, 2) flash_reg(const __half* __restrict__ qkv,
                                                    __half* __restrict__ outT)
{
    extern __shared__ __half kvs[];
    __half* Ks = kvs;                       // [3][64*KVST]
    __half* Vs = kvs + 3 * 64 * KVST;       // [3][64*KVST]

    const int tid = threadIdx.x;
    const int lane = tid & 31, warp = tid >> 5;
    const int g = lane >> 2, t4 = lane & 3;
    const int lr = tid >> 2, lc = (tid & 3) * 16;
    const int KBo = DMn >> 4;

    for (int item = blockIdx.x; item < FLASH_ITEMS; item += gridDim.x) {
        const int bx = item & 7;             // Sn/128 = 8
        const int bh = item >> 3;
        const int b = bh / Hn, h = bh % Hn;
        const int t0 = bx * 128;
        const int rw = t0 + warp * 16;

        // protect KV ring from the previous item's in-flight reads
        __syncthreads();

        // Q fragments straight from gmem (row-major fp16 qkv)
        uint32_t aq[4][4];
        {
            const __half* q0 = qkv + (size_t)(b * Sn + rw + g) * QKVLD + h * Dn + 2 * t4;
            const __half* q1 = q0 + (size_t)8 * QKVLD;
#pragma unroll
            for (int ks = 0; ks < 4; ks++) {
                const int k0 = ks * 16;
                aq[ks][0] = *reinterpret_cast<const uint32_t*>(q0 + k0);
                aq[ks][1] = *reinterpret_cast<const uint32_t*>(q1 + k0);
                aq[ks][2] = *reinterpret_cast<const uint32_t*>(q0 + k0 + 8);
                aq[ks][3] = *reinterpret_cast<const uint32_t*>(q1 + k0 + 8);
            }
        }

        float o[8][4];
#pragma unroll
        for (int ni = 0; ni < 8; ni++)
#pragma unroll
            for (int j = 0; j < 4; j++) o[ni][j] = 0.f;
        float m0 = -3e38f, m1 = -3e38f, l0 = 0.f, l1 = 0.f;

        auto loadKV = [&](int buf, int j0) {
            const __half* kr = qkv + (size_t)(b * Sn + j0 + lr) * QKVLD + DMn + h * Dn + lc;
            const __half* vr = kr + DMn;
            __half* kd = Ks + buf * (64 * KVST) + lr * KVST + lc;
            __half* vd = Vs + buf * (64 * KVST) + lr * KVST + lc;
            cp16(kd, kr); cp16(kd + 8, kr + 8);
            cp16(vd, vr); cp16(vd + 8, vr + 8);
            asm volatile("cp.async.commit_group;" ::: "memory");
        };

        loadKV(0, 0);
        loadKV(1, 64);

        for (int j = 0; j < 16; j++) {
            const int s = j % 3;
            PIPE_WAIT(j, 16);
            __syncthreads();
            if (j + 2 < 16) loadKV((j + 2) % 3, (j + 2) * 64);

            const __half* Kb = Ks + s * (64 * KVST);
            const __half* Vb = Vs + s * (64 * KVST);

            // S = Q K^T (scaled)
            float sc[8][4];
#pragma unroll
            for (int ni = 0; ni < 8; ni++)
#pragma unroll
                for (int jj = 0; jj < 4; jj++) sc[ni][jj] = 0.f;
#pragma unroll
            for (int ks = 0; ks < 4; ks++) {
                const int k0 = ks * 16;
#pragma unroll
                for (int ni = 0; ni < 8; ni++) {
                    const __half* bp = Kb + (ni * 8 + g) * KVST + k0 + 2 * t4;
                    const uint32_t b0 = *reinterpret_cast<const uint32_t*>(bp);
                    const uint32_t b1 = *reinterpret_cast<const uint32_t*>(bp + 8);
                    MMA_H(sc[ni], aq[ks][0], aq[ks][1], aq[ks][2], aq[ks][3], b0, b1);
                }
            }

            // row stats in registers (rows g and g+8)
            float mx0 = -3e38f, mx1 = -3e38f;
#pragma unroll
            for (int ni = 0; ni < 8; ni++) {
#pragma unroll
                for (int jj = 0; jj < 4; jj++) sc[ni][jj] *= 0.125f;
                mx0 = fmaxf(mx0, fmaxf(sc[ni][0], sc[ni][1]));
                mx1 = fmaxf(mx1, fmaxf(sc[ni][2], sc[ni][3]));
            }
            mx0 = fmaxf(mx0, __shfl_xor_sync(0xffffffffu, mx0, 1));
            mx0 = fmaxf(mx0, __shfl_xor_sync(0xffffffffu, mx0, 2));
            mx1 = fmaxf(mx1, __shfl_xor_sync(0xffffffffu, mx1, 1));
            mx1 = fmaxf(mx1, __shfl_xor_sync(0xffffffffu, mx1, 2));

            const float mn0 = fmaxf(m0, mx0), mn1 = fmaxf(m1, mx1);
            const float al0 = __expf(m0 - mn0), al1 = __expf(m1 - mn1);
            m0 = mn0; m1 = mn1;

            uint32_t p[8][2];
            float sum0 = 0.f, sum1 = 0.f;
#pragma unroll
            for (int ni = 0; ni < 8; ni++) {
                const __half2 h20 = __floats2half2_rn(__expf(sc[ni][0] - m0),
                                                      __expf(sc[ni][1] - m0));
                const __half2 h21 = __floats2half2_rn(__expf(sc[ni][2] - m1),
                                                      __expf(sc[ni][3] - m1));
                p[ni][0] = *reinterpret_cast<const uint32_t*>(&h20);
                p[ni][1] = *reinterpret_cast<const uint32_t*>(&h21);
                sum0 += __low2float(h20) + __high2float(h20);
                sum1 += __low2float(h21) + __high2float(h21);
            }
            sum0 += __shfl_xor_sync(0xffffffffu, sum0, 1);
            sum0 += __shfl_xor_sync(0xffffffffu, sum0, 2);
            sum1 += __shfl_xor_sync(0xffffffffu, sum1, 1);
            sum1 += __shfl_xor_sync(0xffffffffu, sum1, 2);
            l0 = l0 * al0 + sum0;
            l1 = l1 * al1 + sum1;

#pragma unroll
            for (int ni = 0; ni < 8; ni++) {
                o[ni][0] *= al0; o[ni][1] *= al0;
                o[ni][2] *= al1; o[ni][3] *= al1;
            }

            // O += P V
#pragma unroll
            for (int ks = 0; ks < 4; ks++) {
                const int k0 = ks * 16;
#pragma unroll
                for (int ni = 0; ni < 8; ni++) {
                    const __half* vp = Vb + (k0 + 2 * t4) * KVST + ni * 8 + g;
                    const uint32_t v00 = *reinterpret_cast<const uint16_t*>(vp);
                    const uint32_t v01 = *reinterpret_cast<const uint16_t*>(vp + KVST);
                    const uint32_t v10 = *reinterpret_cast<const uint16_t*>(vp + 8 * KVST);
                    const uint32_t v11 = *reinterpret_cast<const uint16_t*>(vp + 9 * KVST);
                    const uint32_t b0 = v00 | (v01 << 16);
                    const uint32_t b1 = v10 | (v11 << 16);
                    MMA_H(o[ni], p[2 * ks][0], p[2 * ks][1], p[2 * ks + 1][0], p[2 * ks + 1][1],
                          b0, b1);
                }
            }
        }

        // normalize, write fragment-major fp16
        const float il0 = 1.0f / l0, il1 = 1.0f / l1;
        const int mr0 = b * Sn + rw + g;
#pragma unroll
        for (int ni = 0; ni < 8; ni++) {
            const int k = h * Dn + ni * 8 + 2 * t4;
            *reinterpret_cast<__half2*>(outT + fmIdx(mr0, k, KBo)) =
                __floats2half2_rn(o[ni][0] * il0, o[ni][1] * il0);
            *reinterpret_cast<__half2*>(outT + fmIdx(mr0 + 8, k, KBo)) =
                __floats2half2_rn(o[ni][2] * il1, o[ni][3] * il1);
        }
    }
}

// ---------------- launch ------------------------------------------------------
extern "C" void kernel_launch(void* const* d_in, const int* in_sizes, int n_in,
                              void* d_out, int out_size)
{
    const float* x        = (const float*)d_in[0];
    const float* ln1_s    = (const float*)d_in[1];
    const float* ln1_o    = (const float*)d_in[2];
    const float* wq       = (const float*)d_in[3];
    const float* bq       = (const float*)d_in[4];
    const float* wk       = (const float*)d_in[5];
    const float* bk       = (const float*)d_in[6];
    const float* wv       = (const float*)d_in[7];
    const float* bv       = (const float*)d_in[8];
    const float* wo       = (const float*)d_in[9];
    const float* bo       = (const float*)d_in[10];
    const float* ln2_s    = (const float*)d_in[11];
    const float* ln2_o    = (const float*)d_in[12];
    const float* fc1_w    = (const float*)d_in[13];
    const float* fc1_b    = (const float*)d_in[14];
    const float* fc2_w    = (const float*)d_in[15];
    const float* fc2_b    = (const float*)d_in[16];
    float* out            = (float*)d_out;

    float *px1, *pbqkv;
    __half *phT, *pqkv, *pf1T, *pwr;
    cudaGetSymbolAddress((void**)&phT,   g_hT);
    cudaGetSymbolAddress((void**)&pqkv,  g_qkv);
    cudaGetSymbolAddress((void**)&px1,   g_x1);
    cudaGetSymbolAddress((void**)&pf1T,  g_f1T);
    cudaGetSymbolAddress((void**)&pwr,   g_wr);
    cudaGetSymbolAddress((void**)&pbqkv, g_bqkv);

    __half* rwqkv = pwr;                                     // fused, NBtot=30
    __half* rwo   = pwr + (size_t)3 * WSZ_DM;
    __half* rfc1  = pwr + (size_t)4 * WSZ_DM;
    __half* rfc2  = pwr + (size_t)4 * WSZ_DM + WSZ_FC;

    static int nsm = 0;
    if (!nsm) {
        cudaDeviceGetAttribute(&nsm, cudaDevAttrMultiProcessorCount, 0);
        cudaFuncSetAttribute(flash_reg, cudaFuncAttributeMaxDynamicSharedMemorySize, FLASH_SMEM);
    }
    const int flashGrid = 2 * nsm;

    // 0) ALL weight transforms in one launch (9600 CTAs)
    {
        WtArgs wa;
        wa.src[0] = wq;   wa.dst[0] = rwqkv; wa.K[0] = DMn; wa.N[0] = DMn; wa.NBtot[0] = 30; wa.nbOff[0] = 0;
        wa.src[1] = wk;   wa.dst[1] = rwqkv; wa.K[1] = DMn; wa.N[1] = DMn; wa.NBtot[1] = 30; wa.nbOff[1] = 10;
        wa.src[2] = wv;   wa.dst[2] = rwqkv; wa.K[2] = DMn; wa.N[2] = DMn; wa.NBtot[2] = 30; wa.nbOff[2] = 20;
        wa.src[3] = wo;   wa.dst[3] = rwo;   wa.K[3] = DMn; wa.N[3] = DMn; wa.NBtot[3] = 10; wa.nbOff[3] = 0;
        wa.src[4] = fc1_w; wa.dst[4] = rfc1; wa.K[4] = DMn; wa.N[4] = DFn; wa.NBtot[4] = 40; wa.nbOff[4] = 0;
        wa.src[5] = fc2_w; wa.dst[5] = rfc2; wa.K[5] = DFn; wa.N[5] = DMn; wa.NBtot[5] = 10; wa.nbOff[5] = 0;
        wa.blockStart[0] = 0;
        wa.blockStart[1] = 800;
        wa.blockStart[2] = 1600;
        wa.blockStart[3] = 2400;
        wa.blockStart[4] = 3200;
        wa.blockStart[5] = 6400;
        wa.blockStart[6] = 9600;
        btrans_all<<<9600, 256>>>(wa);
        bias_concat<<<QKVLD / 256, 256>>>(bq, bk, bv, pbqkv);
    }

    // 1) LN1 -> fragment-major hT
    ln_ft<<<NTOK, 256>>>(x, ln1_s, ln1_o, phT);

    // 2) fused QKV projection -> qkv (plain fp16)
    {
        dim3 grid(QKVLD / 128, NTOK / 128);  // (30, 32)
        gemm_h<0><<<grid, 256>>>(phT, rwqkv, pbqkv, nullptr, pqkv, NTOK, QKVLD, DMn);
    }

    // 3) flash attention (persistent) -> fragment-major hT (reuse)
    flash_reg<<<flashGrid, 256, FLASH_SMEM>>>(pqkv, phT);

    // 4) O-proj + residual(x) -> x1 (fp32), 64-row tiles
    {
        dim3 grid(DMn / 128, NTOK / 64);     // (10, 64)
        gemm_h64<<<grid, 256>>>(phT, rwo, bo, x, px1, NTOK, DMn, DMn);
    }

    // 5) LN2 -> fragment-major hT (reuse)
    ln_ft<<<NTOK, 256>>>(px1, ln2_s, ln2_o, phT);

    // 6) FC1 + GELU -> fragment-major f1T
    {
        dim3 grid(DFn / 128, NTOK / 128);    // (40, 32)
        gemm_h<2><<<grid, 256>>>(phT, rfc1, fc1_b, nullptr, pf1T, NTOK, DFn, DMn);
    }

    // 7) FC2 + residual(x1) -> out, 64-row tiles
    {
        dim3 grid(DMn / 128, NTOK / 64);     // (10, 64)
        gemm_h64<<<grid, 256>>>(pf1T, rfc2, fc2_b, px1, out, NTOK, DMn, DFn);
    }
}

// round 14
// speedup vs baseline: 1.0563x; 1.0085x over previous
#include <cuda_runtime.h>
#include <cuda_fp16.h>
#include <math.h>
#include <stdint.h>

// Problem constants
#define Bn   4
#define Sn   1024
#define Hn   20
#define Dn   64
#define DMn  1280
#define DFn  5120
#define NTOK 4096           // Bn*Sn
#define NBH  80             // Bn*Hn
#define EPSLN 1e-5f
#define QKVLD 3840          // row stride of fused qkv output

// ---------------- scratch (static device globals; no allocation) -------------
__device__ __half g_hT  [(size_t)NTOK * DMn];          // fragment-major A (reused 3x)
__device__ __half g_qkv [(size_t)NTOK * QKVLD];        // fused q|k|v (plain fp16)
__device__ float  g_x1  [(size_t)NTOK * DMn];          // residual 1
__device__ __half g_f1T [(size_t)NTOK * DFn];          // fragment-major FC1 out
__device__ __half g_wr  [19660800];                    // fragment-major weights (fp16)
__device__ float  g_bqkv[QKVLD];                       // concat bias

#define WSZ_DM (DMn * DMn)          // 1,638,400
#define WSZ_FC (DMn * DFn)          // 6,553,600

// ---------------- fragment-major index helper ---------------------------------
__device__ __forceinline__ size_t fmIdx(int m, int k, int KB) {
    const int mb = m >> 7, mr = m & 127;
    const int kb = k >> 4, kr = k & 15;
    const int mt = mr >> 4, hh = (mr >> 3) & 1, gg = mr & 7;
    const int t4k = (kr >> 1) & 3, khi = kr >> 3, klo = kr & 1;
    return ((size_t)mb * KB + kb) * 2048 +
           (size_t)((mt * 32 + gg * 4 + t4k) * 8 + khi * 4 + hh * 2 + klo);
}

// ---------------- ALL weight transforms in ONE launch --------------------------
struct WtArgs {
    const float* src[6];
    __half*      dst[6];
    int K[6], N[6], NBtot[6], nbOff[6];
    int blockStart[7];
};

__global__ void __launch_bounds__(256) btrans_all(WtArgs wa)
{
    __shared__ __half s[2048];
    const int gb = blockIdx.x;
    int seg = 0;
#pragma unroll
    for (int i = 1; i < 6; i++) seg += (gb >= wa.blockStart[i]);
    const int lb = gb - wa.blockStart[seg];
    const int N = wa.N[seg];
    const int NBn = N >> 7;
    const int nb = lb % NBn, kb = lb / NBn;
    const int tid = threadIdx.x;
    const float* bb = wa.src[seg] + (size_t)(kb * 16) * N + nb * 128;

#pragma unroll
    for (int e4 = tid; e4 < 512; e4 += 256) {
        const int k = e4 >> 5, colq = (e4 & 31) * 4;
        const float4 f = *reinterpret_cast<const float4*>(bb + (size_t)k * N + colq);
        const int t4 = (k >> 1) & 3, khi = (k >> 3) & 1, klo = k & 1;
        const float vv[4] = {f.x, f.y, f.z, f.w};
#pragma unroll
        for (int j = 0; j < 4; j++) {
            const int col = colq + j;
            const int ni = col >> 3, gg = col & 7;
            s[(ni * 32 + gg * 4 + t4) * 4 + khi * 2 + klo] = __float2half_rn(vv[j]);
        }
    }
    __syncthreads();
    __half* ob = wa.dst[seg] + ((size_t)kb * wa.NBtot[seg] + wa.nbOff[seg] + nb) * 2048;
    *reinterpret_cast<uint4*>(ob + tid * 8) = *reinterpret_cast<const uint4*>(s + tid * 8);
}

// ---------------- bias concat for fused QKV -----------------------------------
__global__ void __launch_bounds__(256) bias_concat(const float* __restrict__ bq,
                                                   const float* __restrict__ bk,
                                                   const float* __restrict__ bv,
                                                   float* __restrict__ o)
{
    const int i = blockIdx.x * 256 + threadIdx.x;
    if (i < DMn) o[i] = bq[i];
    else if (i < 2 * DMn) o[i] = bk[i - DMn];
    else if (i < 3 * DMn) o[i] = bv[i - 2 * DMn];
}

// ---------------- LayerNorm fused with fragment-major fp16 output -------------
__global__ void __launch_bounds__(256) ln_ft(const float* __restrict__ x,
                                             const float* __restrict__ sc,
                                             const float* __restrict__ off,
                                             __half* __restrict__ yT)
{
    const int row = blockIdx.x;
    const float* xr = x + (size_t)row * DMn;
    const int t = threadIdx.x;
    const int lane = t & 31, wid = t >> 5;

    __shared__ float sh[32];
    __shared__ float s_mean, s_rstd;

    float2 p0 = *reinterpret_cast<const float2*>(xr + 2 * t);
    float2 p1 = *reinterpret_cast<const float2*>(xr + 512 + 2 * t);
    float2 p2 = make_float2(0.f, 0.f);
    if (t < 128) p2 = *reinterpret_cast<const float2*>(xr + 1024 + 2 * t);

    float s = p0.x + p0.y + p1.x + p1.y + p2.x + p2.y;
#pragma unroll
    for (int o = 16; o; o >>= 1) s += __shfl_xor_sync(0xffffffffu, s, o);
    if (lane == 0) sh[wid] = s;
    __syncthreads();
    if (wid == 0) {
        float v = (lane < 8) ? sh[lane] : 0.f;
#pragma unroll
        for (int o = 4; o; o >>= 1) v += __shfl_xor_sync(0xffffffffu, v, o);
        if (lane == 0) s_mean = v * (1.0f / DMn);
    }
    __syncthreads();
    const float mean = s_mean;
    __syncthreads();

    float vs = 0.f;
    {
        float d;
        d = p0.x - mean; vs += d * d;
        d = p0.y - mean; vs += d * d;
        d = p1.x - mean; vs += d * d;
        d = p1.y - mean; vs += d * d;
        if (t < 128) {
            d = p2.x - mean; vs += d * d;
            d = p2.y - mean; vs += d * d;
        }
    }
#pragma unroll
    for (int o = 16; o; o >>= 1) vs += __shfl_xor_sync(0xffffffffu, vs, o);
    if (lane == 0) sh[wid] = vs;
    __syncthreads();
    if (wid == 0) {
        float v = (lane < 8) ? sh[lane] : 0.f;
#pragma unroll
        for (int o = 4; o; o >>= 1) v += __shfl_xor_sync(0xffffffffu, v, o);
        if (lane == 0) s_rstd = rsqrtf(v * (1.0f / DMn) + EPSLN);
    }
    __syncthreads();
    const float rstd = s_rstd;

    const int KB = DMn >> 4;
    {
        const int c = 2 * t;
        const float2 g2 = *reinterpret_cast<const float2*>(sc + c);
        const float2 b2 = *reinterpret_cast<const float2*>(off + c);
        *reinterpret_cast<__half2*>(yT + fmIdx(row, c, KB)) =
            __floats2half2_rn((p0.x - mean) * rstd * g2.x + b2.x,
                              (p0.y - mean) * rstd * g2.y + b2.y);
    }
    {
        const int c = 512 + 2 * t;
        const float2 g2 = *reinterpret_cast<const float2*>(sc + c);
        const float2 b2 = *reinterpret_cast<const float2*>(off + c);
        *reinterpret_cast<__half2*>(yT + fmIdx(row, c, KB)) =
            __floats2half2_rn((p1.x - mean) * rstd * g2.x + b2.x,
                              (p1.y - mean) * rstd * g2.y + b2.y);
    }
    if (t < 128) {
        const int c = 1024 + 2 * t;
        const float2 g2 = *reinterpret_cast<const float2*>(sc + c);
        const float2 b2 = *reinterpret_cast<const float2*>(off + c);
        *reinterpret_cast<__half2*>(yT + fmIdx(row, c, KB)) =
            __floats2half2_rn((p2.x - mean) * rstd * g2.x + b2.x,
                              (p2.y - mean) * rstd * g2.y + b2.y);
    }
}

// ---------------- GEMM helpers -------------------------------------------------
__device__ __forceinline__ float gelu_exact(float v) {
    return 0.5f * v * (1.0f + erff(v * 0.70710678118654752f));
}

__device__ __forceinline__ void cp16(void* smem_dst, const void* gsrc) {
    uint32_t s = (uint32_t)__cvta_generic_to_shared(smem_dst);
    asm volatile("cp.async.cg.shared.global [%0], [%1], 16;" :: "r"(s), "l"(gsrc));
}

// 3-stage drain (flash): wait_group 1 while another group is in flight, else 0.
#define PIPE_WAIT(kb, KB) \
    do { if ((kb) + 1 < (KB)) asm volatile("cp.async.wait_group 1;" ::: "memory"); \
         else                 asm volatile("cp.async.wait_group 0;" ::: "memory"); } while (0)

// Pair drain (6-stage GEMMs): before computing pair p = (kb, kb+1), groups
// issued so far reach 2p+3; groups kb..kb+1 must be complete -> allow 2
// incomplete groups, except on the FINAL pair where none remain -> allow 0.
#define PIPE_WAIT_PAIR(p, NP) \
    do { if ((p) + 1 < (NP)) asm volatile("cp.async.wait_group 2;" ::: "memory"); \
         else                asm volatile("cp.async.wait_group 0;" ::: "memory"); } while (0)

#define MMA_H(c, a0,a1,a2,a3, b0,b1) \
    asm volatile("mma.sync.aligned.m16n8k16.row.col.f32.f16.f16.f32 " \
                 "{%0,%1,%2,%3}, {%4,%5,%6,%7}, {%8,%9}, {%0,%1,%2,%3};" \
                 : "+f"((c)[0]), "+f"((c)[1]), "+f"((c)[2]), "+f"((c)[3]) \
                 : "r"(a0), "r"(a1), "r"(a2), "r"(a3), "r"(b0), "r"(b1))

// ---------------- FP16 GEMM, 128x128 tile, 6-stage pair-barrier ---------------
// EPI: 0 = bias -> plain fp16 ; 2 = bias+gelu -> fragment-major fp16.
// Dynamic SMEM: 6 stages x (A 4096 + B 4096) halves = 96 KB.
#define GEMM_SMEM (6 * 8192 * 2)
template <int EPI>
__global__ void __launch_bounds__(256, 2) gemm_h(const __half* __restrict__ At,
                                                 const __half* __restrict__ Bt,
                                                 const float* __restrict__ bias,
                                                 const float* __restrict__ res,
                                                 void* __restrict__ Cv,
                                                 int M, int N, int K)
{
    extern __shared__ __half smg[];
    __half* As = smg;                 // [6][4096]
    __half* Bs = smg + 6 * 4096;      // [6][4096]

    const int tid = threadIdx.x;
    const int nb = blockIdx.x, mb = blockIdx.y;
    const int KB = K >> 5;            // even for all our K
    const int NP = KB >> 1;
    const int KB16 = K >> 4;
    const int NB = N >> 7;
    const int lane = tid & 31, warp = tid >> 5;
    const int wmBase = (warp >> 2) * 4;
    const int wnBase = (warp & 3) * 4;
    const int g = lane >> 2, t4 = lane & 3;

    const __half* aBase = At + (size_t)mb * KB16 * 2048;
    const __half* bBase = Bt + (size_t)nb * 2048;

    float acc[16][4];
#pragma unroll
    for (int i = 0; i < 16; i++)
#pragma unroll
        for (int j = 0; j < 4; j++) acc[i][j] = 0.f;

    auto issue = [&](int kb) {
        const int s = kb % 6;
        const __half* ab  = aBase + (size_t)kb * 4096;
        const __half* bb0 = bBase + (size_t)(kb * 2) * NB * 2048;
        const __half* bb1 = bBase + (size_t)(kb * 2 + 1) * NB * 2048;
        cp16(&As[s * 4096 + tid * 8],        ab + tid * 8);
        cp16(&As[s * 4096 + 2048 + tid * 8], ab + 2048 + tid * 8);
        cp16(&Bs[s * 4096 + tid * 8],        bb0 + tid * 8);
        cp16(&Bs[s * 4096 + 2048 + tid * 8], bb1 + tid * 8);
        asm volatile("cp.async.commit_group;" ::: "memory");
    };
    auto compute = [&](int kb) {
        const int s = kb % 6;
#pragma unroll
        for (int kk = 0; kk < 2; kk++) {
            uint32_t a[4][4], b[4][2];
#pragma unroll
            for (int mi = 0; mi < 4; mi++) {
                const uint4 fa = *reinterpret_cast<const uint4*>(
                    &As[s * 4096 + kk * 2048 + ((wmBase + mi) * 32 + lane) * 8]);
                a[mi][0] = fa.x; a[mi][1] = fa.y; a[mi][2] = fa.z; a[mi][3] = fa.w;
            }
#pragma unroll
            for (int ni = 0; ni < 4; ni++) {
                const uint2 fb = *reinterpret_cast<const uint2*>(
                    &Bs[s * 4096 + kk * 2048 + ((wnBase + ni) * 32 + lane) * 4]);
                b[ni][0] = fb.x; b[ni][1] = fb.y;
            }
#pragma unroll
            for (int mi = 0; mi < 4; mi++)
#pragma unroll
                for (int ni = 0; ni < 4; ni++)
                    MMA_H(acc[mi * 4 + ni], a[mi][0], a[mi][1], a[mi][2], a[mi][3],
                          b[ni][0], b[ni][1]);
        }
    };

    issue(0); issue(1); issue(2); issue(3);

    for (int p = 0; p < NP; p++) {
        const int kb = 2 * p;
        PIPE_WAIT_PAIR(p, NP);
        __syncthreads();
        if (kb + 4 < KB) issue(kb + 4);
        if (kb + 5 < KB) issue(kb + 5);
        compute(kb);
        compute(kb + 1);
    }

    const int rowBase = mb * 128;
    const int colBase = nb * 128;
    const int wm = (warp >> 2) * 64;
    const int wn = (warp & 3) * 32;
    const int KBo = N >> 4;
#pragma unroll
    for (int mi = 0; mi < 4; mi++) {
#pragma unroll
        for (int ni = 0; ni < 4; ni++) {
            float* c = acc[mi * 4 + ni];
            const int col = colBase + wn + ni * 8 + t4 * 2;
            const float2 bb = *reinterpret_cast<const float2*>(bias + col);
#pragma unroll
            for (int h = 0; h < 2; h++) {
                const int row = rowBase + wm + mi * 16 + g + h * 8;
                float o0 = c[h * 2 + 0] + bb.x;
                float o1 = c[h * 2 + 1] + bb.y;
                if (EPI == 0) {
                    __half* Ch = (__half*)Cv;
                    *reinterpret_cast<__half2*>(Ch + (size_t)row * N + col) =
                        __floats2half2_rn(o0, o1);
                } else {
                    __half* Ch = (__half*)Cv;
                    *reinterpret_cast<__half2*>(Ch + fmIdx(row, col, KBo)) =
                        __floats2half2_rn(gelu_exact(o0), gelu_exact(o1));
                }
            }
        }
    }
}

// ---------------- FP16 GEMM, 64x128 tile, 6-stage pair-barrier, bias+res ------
// Dynamic SMEM: 6 stages x (A 2048 + B 4096) halves = 72 KB.
#define GEMM64_SMEM (6 * 6144 * 2)
__global__ void __launch_bounds__(256, 3) gemm_h64(const __half* __restrict__ At,
                                                   const __half* __restrict__ Bt,
                                                   const float* __restrict__ bias,
                                                   const float* __restrict__ res,
                                                   float* __restrict__ C,
                                                   int M, int N, int K)
{
    extern __shared__ __half smg[];
    __half* As = smg;                 // [6][2048]
    __half* Bs = smg + 6 * 2048;      // [6][4096]

    const int tid = threadIdx.x;
    const int nb = blockIdx.x, mb = blockIdx.y;
    const int KB = K >> 5;
    const int NP = KB >> 1;
    const int KB16 = K >> 4;
    const int NB = N >> 7;
    const int lane = tid & 31, warp = tid >> 5;
    const int wmBase = (warp >> 2) * 2;
    const int wnBase = (warp & 3) * 4;
    const int g = lane >> 2, t4 = lane & 3;
    const int mhalf = mb & 1, mblk = mb >> 1;

    const __half* aBase = At + (size_t)mblk * KB16 * 2048 + mhalf * 1024;
    const __half* bBase = Bt + (size_t)nb * 2048;

    float acc[8][4];
#pragma unroll
    for (int i = 0; i < 8; i++)
#pragma unroll
        for (int j = 0; j < 4; j++) acc[i][j] = 0.f;

    auto issue = [&](int kb) {
        const int s = kb % 6;
        const __half* ab0 = aBase + (size_t)(kb * 2) * 2048;
        const __half* ab1 = aBase + (size_t)(kb * 2 + 1) * 2048;
        if (tid < 128) cp16(&As[s * 2048 + tid * 8], ab0 + tid * 8);
        else           cp16(&As[s * 2048 + 1024 + (tid - 128) * 8], ab1 + (tid - 128) * 8);
        const __half* bb0 = bBase + (size_t)(kb * 2) * NB * 2048;
        const __half* bb1 = bBase + (size_t)(kb * 2 + 1) * NB * 2048;
        cp16(&Bs[s * 4096 + tid * 8],        bb0 + tid * 8);
        cp16(&Bs[s * 4096 + 2048 + tid * 8], bb1 + tid * 8);
        asm volatile("cp.async.commit_group;" ::: "memory");
    };
    auto compute = [&](int kb) {
        const int s = kb % 6;
#pragma unroll
        for (int kk = 0; kk < 2; kk++) {
            uint32_t a[2][4], b[4][2];
#pragma unroll
            for (int mi = 0; mi < 2; mi++) {
                const uint4 fa = *reinterpret_cast<const uint4*>(
                    &As[s * 2048 + kk * 1024 + (wmBase + mi) * 256 + lane * 8]);
                a[mi][0] = fa.x; a[mi][1] = fa.y; a[mi][2] = fa.z; a[mi][3] = fa.w;
            }
#pragma unroll
            for (int ni = 0; ni < 4; ni++) {
                const uint2 fb = *reinterpret_cast<const uint2*>(
                    &Bs[s * 4096 + kk * 2048 + ((wnBase + ni) * 32 + lane) * 4]);
                b[ni][0] = fb.x; b[ni][1] = fb.y;
            }
#pragma unroll
            for (int mi = 0; mi < 2; mi++)
#pragma unroll
                for (int ni = 0; ni < 4; ni++)
                    MMA_H(acc[mi * 4 + ni], a[mi][0], a[mi][1], a[mi][2], a[mi][3],
                          b[ni][0], b[ni][1]);
        }
    };

    issue(0); issue(1); issue(2); issue(3);

    for (int p = 0; p < NP; p++) {
        const int kb = 2 * p;
        PIPE_WAIT_PAIR(p, NP);
        __syncthreads();
        if (kb + 4 < KB) issue(kb + 4);
        if (kb + 5 < KB) issue(kb + 5);
        compute(kb);
        compute(kb + 1);
    }

    const int rowBase = mb * 64;
    const int colBase = nb * 128;
    const int wm = (warp >> 2) * 32;
    const int wn = (warp & 3) * 32;
#pragma unroll
    for (int mi = 0; mi < 2; mi++) {
#pragma unroll
        for (int ni = 0; ni < 4; ni++) {
            float* c = acc[mi * 4 + ni];
            const int col = colBase + wn + ni * 8 + t4 * 2;
            const float2 bb = *reinterpret_cast<const float2*>(bias + col);
#pragma unroll
            for (int h = 0; h < 2; h++) {
                const int row = rowBase + wm + mi * 16 + g + h * 8;
                const float2 r2 = *reinterpret_cast<const float2*>(res + (size_t)row * N + col);
                *reinterpret_cast<float2*>(C + (size_t)row * N + col) =
                    make_float2(c[h * 2 + 0] + bb.x + r2.x, c[h * 2 + 1] + bb.y + r2.y);
            }
        }
    }
}

// ---------------- flash attention: register softmax, PERSISTENT ---------------
#define KVST 72
#define FLASH_ITEMS ((Sn / 128) * NBH)       // 8 * 80 = 640
#define FLASH_SMEM (3 * 2 * 64 * KVST * 2)   // 3-stage K+V ring, fp16
__global__ void __launch_bounds__(256, 2) flash_reg(const __half* __restrict__ qkv,
                                                    __half* __restrict__ outT)
{
    extern __shared__ __half kvs[];
    __half* Ks = kvs;                       // [3][64*KVST]
    __half* Vs = kvs + 3 * 64 * KVST;       // [3][64*KVST]

    const int tid = threadIdx.x;
    const int lane = tid & 31, warp = tid >> 5;
    const int g = lane >> 2, t4 = lane & 3;
    const int lr = tid >> 2, lc = (tid & 3) * 16;
    const int KBo = DMn >> 4;

    for (int item = blockIdx.x; item < FLASH_ITEMS; item += gridDim.x) {
        const int bx = item & 7;
        const int bh = item >> 3;
        const int b = bh / Hn, h = bh % Hn;
        const int t0 = bx * 128;
        const int rw = t0 + warp * 16;

        __syncthreads();   // protect KV ring from previous item's readers

        uint32_t aq[4][4];
        {
            const __half* q0 = qkv + (size_t)(b * Sn + rw + g) * QKVLD + h * Dn + 2 * t4;
            const __half* q1 = q0 + (size_t)8 * QKVLD;
#pragma unroll
            for (int ks = 0; ks < 4; ks++) {
                const int k0 = ks * 16;
                aq[ks][0] = *reinterpret_cast<const uint32_t*>(q0 + k0);
                aq[ks][1] = *reinterpret_cast<const uint32_t*>(q1 + k0);
                aq[ks][2] = *reinterpret_cast<const uint32_t*>(q0 + k0 + 8);
                aq[ks][3] = *reinterpret_cast<const uint32_t*>(q1 + k0 + 8);
            }
        }

        float o[8][4];
#pragma unroll
        for (int ni = 0; ni < 8; ni++)
#pragma unroll
            for (int j = 0; j < 4; j++) o[ni][j] = 0.f;
        float m0 = -3e38f, m1 = -3e38f, l0 = 0.f, l1 = 0.f;

        auto loadKV = [&](int buf, int j0) {
            const __half* kr = qkv + (size_t)(b * Sn + j0 + lr) * QKVLD + DMn + h * Dn + lc;
            const __half* vr = kr + DMn;
            __half* kd = Ks + buf * (64 * KVST) + lr * KVST + lc;
            __half* vd = Vs + buf * (64 * KVST) + lr * KVST + lc;
            cp16(kd, kr); cp16(kd + 8, kr + 8);
            cp16(vd, vr); cp16(vd + 8, vr + 8);
            asm volatile("cp.async.commit_group;" ::: "memory");
        };

        loadKV(0, 0);
        loadKV(1, 64);

        for (int j = 0; j < 16; j++) {
            const int s = j % 3;
            PIPE_WAIT(j, 16);
            __syncthreads();
            if (j + 2 < 16) loadKV((j + 2) % 3, (j + 2) * 64);

            const __half* Kb = Ks + s * (64 * KVST);
            const __half* Vb = Vs + s * (64 * KVST);

            float sc[8][4];
#pragma unroll
            for (int ni = 0; ni < 8; ni++)
#pragma unroll
                for (int jj = 0; jj < 4; jj++) sc[ni][jj] = 0.f;
#pragma unroll
            for (int ks = 0; ks < 4; ks++) {
                const int k0 = ks * 16;
#pragma unroll
                for (int ni = 0; ni < 8; ni++) {
                    const __half* bp = Kb + (ni * 8 + g) * KVST + k0 + 2 * t4;
                    const uint32_t b0 = *reinterpret_cast<const uint32_t*>(bp);
                    const uint32_t b1 = *reinterpret_cast<const uint32_t*>(bp + 8);
                    MMA_H(sc[ni], aq[ks][0], aq[ks][1], aq[ks][2], aq[ks][3], b0, b1);
                }
            }

            float mx0 = -3e38f, mx1 = -3e38f;
#pragma unroll
            for (int ni = 0; ni < 8; ni++) {
#pragma unroll
                for (int jj = 0; jj < 4; jj++) sc[ni][jj] *= 0.125f;
                mx0 = fmaxf(mx0, fmaxf(sc[ni][0], sc[ni][1]));
                mx1 = fmaxf(mx1, fmaxf(sc[ni][2], sc[ni][3]));
            }
            mx0 = fmaxf(mx0, __shfl_xor_sync(0xffffffffu, mx0, 1));
            mx0 = fmaxf(mx0, __shfl_xor_sync(0xffffffffu, mx0, 2));
            mx1 = fmaxf(mx1, __shfl_xor_sync(0xffffffffu, mx1, 1));
            mx1 = fmaxf(mx1, __shfl_xor_sync(0xffffffffu, mx1, 2));

            const float mn0 = fmaxf(m0, mx0), mn1 = fmaxf(m1, mx1);
            const float al0 = __expf(m0 - mn0), al1 = __expf(m1 - mn1);
            m0 = mn0; m1 = mn1;

            uint32_t p[8][2];
            float sum0 = 0.f, sum1 = 0.f;
#pragma unroll
            for (int ni = 0; ni < 8; ni++) {
                const __half2 h20 = __floats2half2_rn(__expf(sc[ni][0] - m0),
                                                      __expf(sc[ni][1] - m0));
                const __half2 h21 = __floats2half2_rn(__expf(sc[ni][2] - m1),
                                                      __expf(sc[ni][3] - m1));
                p[ni][0] = *reinterpret_cast<const uint32_t*>(&h20);
                p[ni][1] = *reinterpret_cast<const uint32_t*>(&h21);
                sum0 += __low2float(h20) + __high2float(h20);
                sum1 += __low2float(h21) + __high2float(h21);
            }
            sum0 += __shfl_xor_sync(0xffffffffu, sum0, 1);
            sum0 += __shfl_xor_sync(0xffffffffu, sum0, 2);
            sum1 += __shfl_xor_sync(0xffffffffu, sum1, 1);
            sum1 += __shfl_xor_sync(0xffffffffu, sum1, 2);
            l0 = l0 * al0 + sum0;
            l1 = l1 * al1 + sum1;

#pragma unroll
            for (int ni = 0; ni < 8; ni++) {
                o[ni][0] *= al0; o[ni][1] *= al0;
                o[ni][2] *= al1; o[ni][3] *= al1;
            }

#pragma unroll
            for (int ks = 0; ks < 4; ks++) {
                const int k0 = ks * 16;
#pragma unroll
                for (int ni = 0; ni < 8; ni++) {
                    const __half* vp = Vb + (k0 + 2 * t4) * KVST + ni * 8 + g;
                    const uint32_t v00 = *reinterpret_cast<const uint16_t*>(vp);
                    const uint32_t v01 = *reinterpret_cast<const uint16_t*>(vp + KVST);
                    const uint32_t v10 = *reinterpret_cast<const uint16_t*>(vp + 8 * KVST);
                    const uint32_t v11 = *reinterpret_cast<const uint16_t*>(vp + 9 * KVST);
                    const uint32_t b0 = v00 | (v01 << 16);
                    const uint32_t b1 = v10 | (v11 << 16);
                    MMA_H(o[ni], p[2 * ks][0], p[2 * ks][1], p[2 * ks + 1][0], p[2 * ks + 1][1],
                          b0, b1);
                }
            }
        }

        const float il0 = 1.0f / l0, il1 = 1.0f / l1;
        const int mr0 = b * Sn + rw + g;
#pragma unroll
        for (int ni = 0; ni < 8; ni++) {
            const int k = h * Dn + ni * 8 + 2 * t4;
            *reinterpret_cast<__half2*>(outT + fmIdx(mr0, k, KBo)) =
                __floats2half2_rn(o[ni][0] * il0, o[ni][1] * il0);
            *reinterpret_cast<__half2*>(outT + fmIdx(mr0 + 8, k, KBo)) =
                __floats2half2_rn(o[ni][2] * il1, o[ni][3] * il1);
        }
    }
}

// ---------------- launch ------------------------------------------------------
extern "C" void kernel_launch(void* const* d_in, const int* in_sizes, int n_in,
                              void* d_out, int out_size)
{
    const float* x        = (const float*)d_in[0];
    const float* ln1_s    = (const float*)d_in[1];
    const float* ln1_o    = (const float*)d_in[2];
    const float* wq       = (const float*)d_in[3];
    const float* bq       = (const float*)d_in[4];
    const float* wk       = (const float*)d_in[5];
    const float* bk       = (const float*)d_in[6];
    const float* wv       = (const float*)d_in[7];
    const float* bv       = (const float*)d_in[8];
    const float* wo       = (const float*)d_in[9];
    const float* bo       = (const float*)d_in[10];
    const float* ln2_s    = (const float*)d_in[11];
    const float* ln2_o    = (const float*)d_in[12];
    const float* fc1_w    = (const float*)d_in[13];
    const float* fc1_b    = (const float*)d_in[14];
    const float* fc2_w    = (const float*)d_in[15];
    const float* fc2_b    = (const float*)d_in[16];
    float* out            = (float*)d_out;

    float *px1, *pbqkv;
    __half *phT, *pqkv, *pf1T, *pwr;
    cudaGetSymbolAddress((void**)&phT,   g_hT);
    cudaGetSymbolAddress((void**)&pqkv,  g_qkv);
    cudaGetSymbolAddress((void**)&px1,   g_x1);
    cudaGetSymbolAddress((void**)&pf1T,  g_f1T);
    cudaGetSymbolAddress((void**)&pwr,   g_wr);
    cudaGetSymbolAddress((void**)&pbqkv, g_bqkv);

    __half* rwqkv = pwr;                                     // fused, NBtot=30
    __half* rwo   = pwr + (size_t)3 * WSZ_DM;
    __half* rfc1  = pwr + (size_t)4 * WSZ_DM;
    __half* rfc2  = pwr + (size_t)4 * WSZ_DM + WSZ_FC;

    static int nsm = 0;
    if (!nsm) {
        cudaDeviceGetAttribute(&nsm, cudaDevAttrMultiProcessorCount, 0);
        cudaFuncSetAttribute(flash_reg, cudaFuncAttributeMaxDynamicSharedMemorySize, FLASH_SMEM);
        cudaFuncSetAttribute(gemm_h<0>, cudaFuncAttributeMaxDynamicSharedMemorySize, GEMM_SMEM);
        cudaFuncSetAttribute(gemm_h<2>, cudaFuncAttributeMaxDynamicSharedMemorySize, GEMM_SMEM);
        cudaFuncSetAttribute(gemm_h64,  cudaFuncAttributeMaxDynamicSharedMemorySize, GEMM64_SMEM);
    }
    const int flashGrid = 2 * nsm;

    // 0) ALL weight transforms in one launch (9600 CTAs)
    {
        WtArgs wa;
        wa.src[0] = wq;   wa.dst[0] = rwqkv; wa.K[0] = DMn; wa.N[0] = DMn; wa.NBtot[0] = 30; wa.nbOff[0] = 0;
        wa.src[1] = wk;   wa.dst[1] = rwqkv; wa.K[1] = DMn; wa.N[1] = DMn; wa.NBtot[1] = 30; wa.nbOff[1] = 10;
        wa.src[2] = wv;   wa.dst[2] = rwqkv; wa.K[2] = DMn; wa.N[2] = DMn; wa.NBtot[2] = 30; wa.nbOff[2] = 20;
        wa.src[3] = wo;   wa.dst[3] = rwo;   wa.K[3] = DMn; wa.N[3] = DMn; wa.NBtot[3] = 10; wa.nbOff[3] = 0;
        wa.src[4] = fc1_w; wa.dst[4] = rfc1; wa.K[4] = DMn; wa.N[4] = DFn; wa.NBtot[4] = 40; wa.nbOff[4] = 0;
        wa.src[5] = fc2_w; wa.dst[5] = rfc2; wa.K[5] = DFn; wa.N[5] = DMn; wa.NBtot[5] = 10; wa.nbOff[5] = 0;
        wa.blockStart[0] = 0;
        wa.blockStart[1] = 800;
        wa.blockStart[2] = 1600;
        wa.blockStart[3] = 2400;
        wa.blockStart[4] = 3200;
        wa.blockStart[5] = 6400;
        wa.blockStart[6] = 9600;
        btrans_all<<<9600, 256>>>(wa);
        bias_concat<<<QKVLD / 256, 256>>>(bq, bk, bv, pbqkv);
    }

    // 1) LN1 -> fragment-major hT
    ln_ft<<<NTOK, 256>>>(x, ln1_s, ln1_o, phT);

    // 2) fused QKV projection -> qkv (plain fp16)
    {
        dim3 grid(QKVLD / 128, NTOK / 128);  // (30, 32)
        gemm_h<0><<<grid, 256, GEMM_SMEM>>>(phT, rwqkv, pbqkv, nullptr, pqkv, NTOK, QKVLD, DMn);
    }

    // 3) flash attention (persistent) -> fragment-major hT (reuse)
    flash_reg<<<flashGrid, 256, FLASH_SMEM>>>(pqkv, phT);

    // 4) O-proj + residual(x) -> x1 (fp32), 64-row tiles
    {
        dim3 grid(DMn / 128, NTOK / 64);     // (10, 64)
        gemm_h64<<<grid, 256, GEMM64_SMEM>>>(phT, rwo, bo, x, px1, NTOK, DMn, DMn);
    }

    // 5) LN2 -> fragment-major hT (reuse)
    ln_ft<<<NTOK, 256>>>(px1, ln2_s, ln2_o, phT);

    // 6) FC1 + GELU -> fragment-major f1T
    {
        dim3 grid(DFn / 128, NTOK / 128);    // (40, 32)
        gemm_h<2><<<grid, 256, GEMM_SMEM>>>(phT, rfc1, fc1_b, nullptr, pf1T, NTOK, DFn, DMn);
    }

    // 7) FC2 + residual(x1) -> out, 64-row tiles
    {
        dim3 grid(DMn / 128, NTOK / 64);     // (10, 64)
        gemm_h64<<<grid, 256, GEMM64_SMEM>>>(pf1T, rfc2, fc2_b, px1, out, NTOK, DMn, DFn);
    }
}

// round 16
// speedup vs baseline: 1.0597x; 1.0033x over previous
#include <cuda_runtime.h>
#include <cuda_fp16.h>
#include <math.h>
#include <stdint.h>

// Problem constants
#define Bn   4
#define Sn   1024
#define Hn   20
#define Dn   64
#define DMn  1280
#define DFn  5120
#define NTOK 4096           // Bn*Sn
#define NBH  80             // Bn*Hn
#define EPSLN 1e-5f
#define QKVLD 3840          // row stride of fused qkv output

// ---------------- scratch (static device globals; no allocation) -------------
__device__ __half g_hT  [(size_t)NTOK * DMn];          // fragment-major A (reused 3x)
__device__ __half g_qkv [(size_t)NTOK * QKVLD];        // fused q|k|v (plain fp16)
__device__ float  g_x1  [(size_t)NTOK * DMn];          // residual 1
__device__ __half g_f1T [(size_t)NTOK * DFn];          // fragment-major FC1 out
__device__ __half g_wr  [19660800];                    // fragment-major weights (fp16)
__device__ float  g_bqkv[QKVLD];                       // concat bias
__device__ float  g_part[(size_t)2 * NTOK * DMn];      // split-K partials

#define WSZ_DM (DMn * DMn)          // 1,638,400
#define WSZ_FC (DMn * DFn)          // 6,553,600

// ---------------- fragment-major index helper ---------------------------------
__device__ __forceinline__ size_t fmIdx(int m, int k, int KB) {
    const int mb = m >> 7, mr = m & 127;
    const int kb = k >> 4, kr = k & 15;
    const int mt = mr >> 4, hh = (mr >> 3) & 1, gg = mr & 7;
    const int t4k = (kr >> 1) & 3, khi = kr >> 3, klo = kr & 1;
    return ((size_t)mb * KB + kb) * 2048 +
           (size_t)((mt * 32 + gg * 4 + t4k) * 8 + khi * 4 + hh * 2 + klo);
}

// ---------------- ALL weight transforms in ONE launch --------------------------
struct WtArgs {
    const float* src[6];
    __half*      dst[6];
    int K[6], N[6], NBtot[6], nbOff[6];
    int blockStart[7];
};

__global__ void __launch_bounds__(256) btrans_all(WtArgs wa)
{
    __shared__ __half s[2048];
    const int gb = blockIdx.x;
    int seg = 0;
#pragma unroll
    for (int i = 1; i < 6; i++) seg += (gb >= wa.blockStart[i]);
    const int lb = gb - wa.blockStart[seg];
    const int N = wa.N[seg];
    const int NBn = N >> 7;
    const int nb = lb % NBn, kb = lb / NBn;
    const int tid = threadIdx.x;
    const float* bb = wa.src[seg] + (size_t)(kb * 16) * N + nb * 128;

#pragma unroll
    for (int e4 = tid; e4 < 512; e4 += 256) {
        const int k = e4 >> 5, colq = (e4 & 31) * 4;
        const float4 f = *reinterpret_cast<const float4*>(bb + (size_t)k * N + colq);
        const int t4 = (k >> 1) & 3, khi = (k >> 3) & 1, klo = k & 1;
        const float vv[4] = {f.x, f.y, f.z, f.w};
#pragma unroll
        for (int j = 0; j < 4; j++) {
            const int col = colq + j;
            const int ni = col >> 3, gg = col & 7;
            s[(ni * 32 + gg * 4 + t4) * 4 + khi * 2 + klo] = __float2half_rn(vv[j]);
        }
    }
    __syncthreads();
    __half* ob = wa.dst[seg] + ((size_t)kb * wa.NBtot[seg] + wa.nbOff[seg] + nb) * 2048;
    *reinterpret_cast<uint4*>(ob + tid * 8) = *reinterpret_cast<const uint4*>(s + tid * 8);
}

// ---------------- bias concat for fused QKV -----------------------------------
__global__ void __launch_bounds__(256) bias_concat(const float* __restrict__ bq,
                                                   const float* __restrict__ bk,
                                                   const float* __restrict__ bv,
                                                   float* __restrict__ o)
{
    const int i = blockIdx.x * 256 + threadIdx.x;
    if (i < DMn) o[i] = bq[i];
    else if (i < 2 * DMn) o[i] = bk[i - DMn];
    else if (i < 3 * DMn) o[i] = bv[i - 2 * DMn];
}

// ---------------- split-K combine: out = p0 + p1 + bias + res ------------------
__global__ void __launch_bounds__(256) combine_res(const float* __restrict__ p0,
                                                   const float* __restrict__ p1,
                                                   const float* __restrict__ bias,
                                                   const float* __restrict__ res,
                                                   float* __restrict__ out)
{
    const size_t i4 = (size_t)blockIdx.x * 256 + threadIdx.x;   // float4 index
    const size_t i = i4 * 4;
    const int col = (int)(i % DMn);
    const float4 a = *reinterpret_cast<const float4*>(p0 + i);
    const float4 b = *reinterpret_cast<const float4*>(p1 + i);
    const float4 r = *reinterpret_cast<const float4*>(res + i);
    const float4 bb = *reinterpret_cast<const float4*>(bias + col);
    float4 o;
    o.x = a.x + b.x + bb.x + r.x;
    o.y = a.y + b.y + bb.y + r.y;
    o.z = a.z + b.z + bb.z + r.z;
    o.w = a.w + b.w + bb.w + r.w;
    *reinterpret_cast<float4*>(out + i) = o;
}

// ---------------- LayerNorm fused with fragment-major fp16 output -------------
__global__ void __launch_bounds__(256) ln_ft(const float* __restrict__ x,
                                             const float* __restrict__ sc,
                                             const float* __restrict__ off,
                                             __half* __restrict__ yT)
{
    const int row = blockIdx.x;
    const float* xr = x + (size_t)row * DMn;
    const int t = threadIdx.x;
    const int lane = t & 31, wid = t >> 5;

    __shared__ float sh[32];
    __shared__ float s_mean, s_rstd;

    float2 p0 = *reinterpret_cast<const float2*>(xr + 2 * t);
    float2 p1 = *reinterpret_cast<const float2*>(xr + 512 + 2 * t);
    float2 p2 = make_float2(0.f, 0.f);
    if (t < 128) p2 = *reinterpret_cast<const float2*>(xr + 1024 + 2 * t);

    float s = p0.x + p0.y + p1.x + p1.y + p2.x + p2.y;
#pragma unroll
    for (int o = 16; o; o >>= 1) s += __shfl_xor_sync(0xffffffffu, s, o);
    if (lane == 0) sh[wid] = s;
    __syncthreads();
    if (wid == 0) {
        float v = (lane < 8) ? sh[lane] : 0.f;
#pragma unroll
        for (int o = 4; o; o >>= 1) v += __shfl_xor_sync(0xffffffffu, v, o);
        if (lane == 0) s_mean = v * (1.0f / DMn);
    }
    __syncthreads();
    const float mean = s_mean;
    __syncthreads();

    float vs = 0.f;
    {
        float d;
        d = p0.x - mean; vs += d * d;
        d = p0.y - mean; vs += d * d;
        d = p1.x - mean; vs += d * d;
        d = p1.y - mean; vs += d * d;
        if (t < 128) {
            d = p2.x - mean; vs += d * d;
            d = p2.y - mean; vs += d * d;
        }
    }
#pragma unroll
    for (int o = 16; o; o >>= 1) vs += __shfl_xor_sync(0xffffffffu, vs, o);
    if (lane == 0) sh[wid] = vs;
    __syncthreads();
    if (wid == 0) {
        float v = (lane < 8) ? sh[lane] : 0.f;
#pragma unroll
        for (int o = 4; o; o >>= 1) v += __shfl_xor_sync(0xffffffffu, v, o);
        if (lane == 0) s_rstd = rsqrtf(v * (1.0f / DMn) + EPSLN);
    }
    __syncthreads();
    const float rstd = s_rstd;

    const int KB = DMn >> 4;
    {
        const int c = 2 * t;
        const float2 g2 = *reinterpret_cast<const float2*>(sc + c);
        const float2 b2 = *reinterpret_cast<const float2*>(off + c);
        *reinterpret_cast<__half2*>(yT + fmIdx(row, c, KB)) =
            __floats2half2_rn((p0.x - mean) * rstd * g2.x + b2.x,
                              (p0.y - mean) * rstd * g2.y + b2.y);
    }
    {
        const int c = 512 + 2 * t;
        const float2 g2 = *reinterpret_cast<const float2*>(sc + c);
        const float2 b2 = *reinterpret_cast<const float2*>(off + c);
        *reinterpret_cast<__half2*>(yT + fmIdx(row, c, KB)) =
            __floats2half2_rn((p1.x - mean) * rstd * g2.x + b2.x,
                              (p1.y - mean) * rstd * g2.y + b2.y);
    }
    if (t < 128) {
        const int c = 1024 + 2 * t;
        const float2 g2 = *reinterpret_cast<const float2*>(sc + c);
        const float2 b2 = *reinterpret_cast<const float2*>(off + c);
        *reinterpret_cast<__half2*>(yT + fmIdx(row, c, KB)) =
            __floats2half2_rn((p2.x - mean) * rstd * g2.x + b2.x,
                              (p2.y - mean) * rstd * g2.y + b2.y);
    }
}

// ---------------- GEMM helpers -------------------------------------------------
__device__ __forceinline__ float gelu_exact(float v) {
    return 0.5f * v * (1.0f + erff(v * 0.70710678118654752f));
}

__device__ __forceinline__ void cp16(void* smem_dst, const void* gsrc) {
    uint32_t s = (uint32_t)__cvta_generic_to_shared(smem_dst);
    asm volatile("cp.async.cg.shared.global [%0], [%1], 16;" :: "r"(s), "l"(gsrc));
}

// 3-stage drain (flash): wait_group 1 while another group is in flight, else 0.
#define PIPE_WAIT(kb, KB) \
    do { if ((kb) + 1 < (KB)) asm volatile("cp.async.wait_group 1;" ::: "memory"); \
         else                 asm volatile("cp.async.wait_group 0;" ::: "memory"); } while (0)

// Pair drain (6-stage GEMMs): see round-13 analysis; wait_group 2 normally,
// 0 on the final pair (race-safe drain from round-9 lesson).
#define PIPE_WAIT_PAIR(p, NP) \
    do { if ((p) + 1 < (NP)) asm volatile("cp.async.wait_group 2;" ::: "memory"); \
         else                asm volatile("cp.async.wait_group 0;" ::: "memory"); } while (0)

#define MMA_H(c, a0,a1,a2,a3, b0,b1) \
    asm volatile("mma.sync.aligned.m16n8k16.row.col.f32.f16.f16.f32 " \
                 "{%0,%1,%2,%3}, {%4,%5,%6,%7}, {%8,%9}, {%0,%1,%2,%3};" \
                 : "+f"((c)[0]), "+f"((c)[1]), "+f"((c)[2]), "+f"((c)[3]) \
                 : "r"(a0), "r"(a1), "r"(a2), "r"(a3), "r"(b0), "r"(b1))

// ---------------- FP16 GEMM, 128x128 tile, 6-stage pair-barrier ---------------
// EPI: 0 = bias -> plain fp16 ; 2 = bias+gelu -> fragment-major fp16.
#define GEMM_SMEM (6 * 8192 * 2)
template <int EPI>
__global__ void __launch_bounds__(256, 2) gemm_h(const __half* __restrict__ At,
                                                 const __half* __restrict__ Bt,
                                                 const float* __restrict__ bias,
                                                 const float* __restrict__ res,
                                                 void* __restrict__ Cv,
                                                 int M, int N, int K)
{
    extern __shared__ __half smg[];
    __half* As = smg;                 // [6][4096]
    __half* Bs = smg + 6 * 4096;      // [6][4096]

    const int tid = threadIdx.x;
    const int nb = blockIdx.x, mb = blockIdx.y;
    const int KB = K >> 5;
    const int NP = KB >> 1;
    const int KB16 = K >> 4;
    const int NB = N >> 7;
    const int lane = tid & 31, warp = tid >> 5;
    const int wmBase = (warp >> 2) * 4;
    const int wnBase = (warp & 3) * 4;
    const int g = lane >> 2, t4 = lane & 3;

    const __half* aBase = At + (size_t)mb * KB16 * 2048;
    const __half* bBase = Bt + (size_t)nb * 2048;

    float acc[16][4];
#pragma unroll
    for (int i = 0; i < 16; i++)
#pragma unroll
        for (int j = 0; j < 4; j++) acc[i][j] = 0.f;

    auto issue = [&](int kb) {
        const int s = kb % 6;
        const __half* ab  = aBase + (size_t)kb * 4096;
        const __half* bb0 = bBase + (size_t)(kb * 2) * NB * 2048;
        const __half* bb1 = bBase + (size_t)(kb * 2 + 1) * NB * 2048;
        cp16(&As[s * 4096 + tid * 8],        ab + tid * 8);
        cp16(&As[s * 4096 + 2048 + tid * 8], ab + 2048 + tid * 8);
        cp16(&Bs[s * 4096 + tid * 8],        bb0 + tid * 8);
        cp16(&Bs[s * 4096 + 2048 + tid * 8], bb1 + tid * 8);
        asm volatile("cp.async.commit_group;" ::: "memory");
    };
    auto compute = [&](int kb) {
        const int s = kb % 6;
#pragma unroll
        for (int kk = 0; kk < 2; kk++) {
            uint32_t a[4][4], b[4][2];
#pragma unroll
            for (int mi = 0; mi < 4; mi++) {
                const uint4 fa = *reinterpret_cast<const uint4*>(
                    &As[s * 4096 + kk * 2048 + ((wmBase + mi) * 32 + lane) * 8]);
                a[mi][0] = fa.x; a[mi][1] = fa.y; a[mi][2] = fa.z; a[mi][3] = fa.w;
            }
#pragma unroll
            for (int ni = 0; ni < 4; ni++) {
                const uint2 fb = *reinterpret_cast<const uint2*>(
                    &Bs[s * 4096 + kk * 2048 + ((wnBase + ni) * 32 + lane) * 4]);
                b[ni][0] = fb.x; b[ni][1] = fb.y;
            }
#pragma unroll
            for (int mi = 0; mi < 4; mi++)
#pragma unroll
                for (int ni = 0; ni < 4; ni++)
                    MMA_H(acc[mi * 4 + ni], a[mi][0], a[mi][1], a[mi][2], a[mi][3],
                          b[ni][0], b[ni][1]);
        }
    };

    issue(0); issue(1); issue(2); issue(3);

    for (int p = 0; p < NP; p++) {
        const int kb = 2 * p;
        PIPE_WAIT_PAIR(p, NP);
        __syncthreads();
        if (kb + 4 < KB) issue(kb + 4);
        if (kb + 5 < KB) issue(kb + 5);
        compute(kb);
        compute(kb + 1);
    }

    const int rowBase = mb * 128;
    const int colBase = nb * 128;
    const int wm = (warp >> 2) * 64;
    const int wn = (warp & 3) * 32;
    const int KBo = N >> 4;
#pragma unroll
    for (int mi = 0; mi < 4; mi++) {
#pragma unroll
        for (int ni = 0; ni < 4; ni++) {
            float* c = acc[mi * 4 + ni];
            const int col = colBase + wn + ni * 8 + t4 * 2;
            const float2 bb = *reinterpret_cast<const float2*>(bias + col);
#pragma unroll
            for (int h = 0; h < 2; h++) {
                const int row = rowBase + wm + mi * 16 + g + h * 8;
                float o0 = c[h * 2 + 0] + bb.x;
                float o1 = c[h * 2 + 1] + bb.y;
                if (EPI == 0) {
                    __half* Ch = (__half*)Cv;
                    *reinterpret_cast<__half2*>(Ch + (size_t)row * N + col) =
                        __floats2half2_rn(o0, o1);
                } else {
                    __half* Ch = (__half*)Cv;
                    *reinterpret_cast<__half2*>(Ch + fmIdx(row, col, KBo)) =
                        __floats2half2_rn(gelu_exact(o0), gelu_exact(o1));
                }
            }
        }
    }
}

// ---------------- FP16 GEMM, 64x128 tile, SPLIT-K 2, raw fp32 partial out -----
// gridDim.z = 2 selects the K half. Partials written to part + z*NTOK*DMn.
#define GEMM64_SMEM (6 * 6144 * 2)
__global__ void __launch_bounds__(256, 3) gemm_h64sp(const __half* __restrict__ At,
                                                     const __half* __restrict__ Bt,
                                                     float* __restrict__ part,
                                                     int M, int N, int K)
{
    extern __shared__ __half smg[];
    __half* As = smg;                 // [6][2048]
    __half* Bs = smg + 6 * 2048;      // [6][4096]

    const int tid = threadIdx.x;
    const int nb = blockIdx.x, mb = blockIdx.y;
    const int kz = blockIdx.z;
    const int KBfull = K >> 5;
    const int KB = KBfull >> 1;       // half-K iterations (20 or 80 -> even)
    const int NP = KB >> 1;
    const int kbOff = kz * KB;
    const int KB16 = K >> 4;
    const int NB = N >> 7;
    const int lane = tid & 31, warp = tid >> 5;
    const int wmBase = (warp >> 2) * 2;
    const int wnBase = (warp & 3) * 4;
    const int g = lane >> 2, t4 = lane & 3;
    const int mhalf = mb & 1, mblk = mb >> 1;

    const __half* aBase = At + (size_t)mblk * KB16 * 2048 + mhalf * 1024;
    const __half* bBase = Bt + (size_t)nb * 2048;

    float acc[8][4];
#pragma unroll
    for (int i = 0; i < 8; i++)
#pragma unroll
        for (int j = 0; j < 4; j++) acc[i][j] = 0.f;

    auto issue = [&](int kb) {
        const int s = kb % 6;
        const int kbg = kbOff + kb;
        const __half* ab0 = aBase + (size_t)(kbg * 2) * 2048;
        const __half* ab1 = aBase + (size_t)(kbg * 2 + 1) * 2048;
        if (tid < 128) cp16(&As[s * 2048 + tid * 8], ab0 + tid * 8);
        else           cp16(&As[s * 2048 + 1024 + (tid - 128) * 8], ab1 + (tid - 128) * 8);
        const __half* bb0 = bBase + (size_t)(kbg * 2) * NB * 2048;
        const __half* bb1 = bBase + (size_t)(kbg * 2 + 1) * NB * 2048;
        cp16(&Bs[s * 4096 + tid * 8],        bb0 + tid * 8);
        cp16(&Bs[s * 4096 + 2048 + tid * 8], bb1 + tid * 8);
        asm volatile("cp.async.commit_group;" ::: "memory");
    };
    auto compute = [&](int kb) {
        const int s = kb % 6;
#pragma unroll
        for (int kk = 0; kk < 2; kk++) {
            uint32_t a[2][4], b[4][2];
#pragma unroll
            for (int mi = 0; mi < 2; mi++) {
                const uint4 fa = *reinterpret_cast<const uint4*>(
                    &As[s * 2048 + kk * 1024 + (wmBase + mi) * 256 + lane * 8]);
                a[mi][0] = fa.x; a[mi][1] = fa.y; a[mi][2] = fa.z; a[mi][3] = fa.w;
            }
#pragma unroll
            for (int ni = 0; ni < 4; ni++) {
                const uint2 fb = *reinterpret_cast<const uint2*>(
                    &Bs[s * 4096 + kk * 2048 + ((wnBase + ni) * 32 + lane) * 4]);
                b[ni][0] = fb.x; b[ni][1] = fb.y;
            }
#pragma unroll
            for (int mi = 0; mi < 2; mi++)
#pragma unroll
                for (int ni = 0; ni < 4; ni++)
                    MMA_H(acc[mi * 4 + ni], a[mi][0], a[mi][1], a[mi][2], a[mi][3],
                          b[ni][0], b[ni][1]);
        }
    };

    issue(0); issue(1); issue(2); issue(3);

    for (int p = 0; p < NP; p++) {
        const int kb = 2 * p;
        PIPE_WAIT_PAIR(p, NP);
        __syncthreads();
        if (kb + 4 < KB) issue(kb + 4);
        if (kb + 5 < KB) issue(kb + 5);
        compute(kb);
        compute(kb + 1);
    }

    float* C = part + (size_t)kz * NTOK * DMn;
    const int rowBase = mb * 64;
    const int colBase = nb * 128;
    const int wm = (warp >> 2) * 32;
    const int wn = (warp & 3) * 32;
#pragma unroll
    for (int mi = 0; mi < 2; mi++) {
#pragma unroll
        for (int ni = 0; ni < 4; ni++) {
            float* c = acc[mi * 4 + ni];
            const int col = colBase + wn + ni * 8 + t4 * 2;
#pragma unroll
            for (int h = 0; h < 2; h++) {
                const int row = rowBase + wm + mi * 16 + g + h * 8;
                *reinterpret_cast<float2*>(C + (size_t)row * N + col) =
                    make_float2(c[h * 2 + 0], c[h * 2 + 1]);
            }
        }
    }
}

// ---------------- flash attention: register softmax, PERSISTENT ---------------
#define KVST 72
#define FLASH_ITEMS ((Sn / 128) * NBH)       // 8 * 80 = 640
#define FLASH_SMEM (3 * 2 * 64 * KVST * 2)   // 3-stage K+V ring, fp16
__global__ void __launch_bounds__(256, 2) flash_reg(const __half* __restrict__ qkv,
                                                    __half* __restrict__ outT)
{
    extern __shared__ __half kvs[];
    __half* Ks = kvs;                       // [3][64*KVST]
    __half* Vs = kvs + 3 * 64 * KVST;       // [3][64*KVST]

    const int tid = threadIdx.x;
    const int lane = tid & 31, warp = tid >> 5;
    const int g = lane >> 2, t4 = lane & 3;
    const int lr = tid >> 2, lc = (tid & 3) * 16;
    const int KBo = DMn >> 4;

    for (int item = blockIdx.x; item < FLASH_ITEMS; item += gridDim.x) {
        const int bx = item & 7;
        const int bh = item >> 3;
        const int b = bh / Hn, h = bh % Hn;
        const int t0 = bx * 128;
        const int rw = t0 + warp * 16;

        __syncthreads();   // protect KV ring from previous item's readers

        uint32_t aq[4][4];
        {
            const __half* q0 = qkv + (size_t)(b * Sn + rw + g) * QKVLD + h * Dn + 2 * t4;
            const __half* q1 = q0 + (size_t)8 * QKVLD;
#pragma unroll
            for (int ks = 0; ks < 4; ks++) {
                const int k0 = ks * 16;
                aq[ks][0] = *reinterpret_cast<const uint32_t*>(q0 + k0);
                aq[ks][1] = *reinterpret_cast<const uint32_t*>(q1 + k0);
                aq[ks][2] = *reinterpret_cast<const uint32_t*>(q0 + k0 + 8);
                aq[ks][3] = *reinterpret_cast<const uint32_t*>(q1 + k0 + 8);
            }
        }

        float o[8][4];
#pragma unroll
        for (int ni = 0; ni < 8; ni++)
#pragma unroll
            for (int j = 0; j < 4; j++) o[ni][j] = 0.f;
        float m0 = -3e38f, m1 = -3e38f, l0 = 0.f, l1 = 0.f;

        auto loadKV = [&](int buf, int j0) {
            const __half* kr = qkv + (size_t)(b * Sn + j0 + lr) * QKVLD + DMn + h * Dn + lc;
            const __half* vr = kr + DMn;
            __half* kd = Ks + buf * (64 * KVST) + lr * KVST + lc;
            __half* vd = Vs + buf * (64 * KVST) + lr * KVST + lc;
            cp16(kd, kr); cp16(kd + 8, kr + 8);
            cp16(vd, vr); cp16(vd + 8, vr + 8);
            asm volatile("cp.async.commit_group;" ::: "memory");
        };

        loadKV(0, 0);
        loadKV(1, 64);

        for (int j = 0; j < 16; j++) {
            const int s = j % 3;
            PIPE_WAIT(j, 16);
            __syncthreads();
            if (j + 2 < 16) loadKV((j + 2) % 3, (j + 2) * 64);

            const __half* Kb = Ks + s * (64 * KVST);
            const __half* Vb = Vs + s * (64 * KVST);

            float sc[8][4];
#pragma unroll
            for (int ni = 0; ni < 8; ni++)
#pragma unroll
                for (int jj = 0; jj < 4; jj++) sc[ni][jj] = 0.f;
#pragma unroll
            for (int ks = 0; ks < 4; ks++) {
                const int k0 = ks * 16;
#pragma unroll
                for (int ni = 0; ni < 8; ni++) {
                    const __half* bp = Kb + (ni * 8 + g) * KVST + k0 + 2 * t4;
                    const uint32_t b0 = *reinterpret_cast<const uint32_t*>(bp);
                    const uint32_t b1 = *reinterpret_cast<const uint32_t*>(bp + 8);
                    MMA_H(sc[ni], aq[ks][0], aq[ks][1], aq[ks][2], aq[ks][3], b0, b1);
                }
            }

            float mx0 = -3e38f, mx1 = -3e38f;
#pragma unroll
            for (int ni = 0; ni < 8; ni++) {
#pragma unroll
                for (int jj = 0; jj < 4; jj++) sc[ni][jj] *= 0.125f;
                mx0 = fmaxf(mx0, fmaxf(sc[ni][0], sc[ni][1]));
                mx1 = fmaxf(mx1, fmaxf(sc[ni][2], sc[ni][3]));
            }
            mx0 = fmaxf(mx0, __shfl_xor_sync(0xffffffffu, mx0, 1));
            mx0 = fmaxf(mx0, __shfl_xor_sync(0xffffffffu, mx0, 2));
            mx1 = fmaxf(mx1, __shfl_xor_sync(0xffffffffu, mx1, 1));
            mx1 = fmaxf(mx1, __shfl_xor_sync(0xffffffffu, mx1, 2));

            const float mn0 = fmaxf(m0, mx0), mn1 = fmaxf(m1, mx1);
            const float al0 = __expf(m0 - mn0), al1 = __expf(m1 - mn1);
            m0 = mn0; m1 = mn1;

            uint32_t p[8][2];
            float sum0 = 0.f, sum1 = 0.f;
#pragma unroll
            for (int ni = 0; ni < 8; ni++) {
                const __half2 h20 = __floats2half2_rn(__expf(sc[ni][0] - m0),
                                                      __expf(sc[ni][1] - m0));
                const __half2 h21 = __floats2half2_rn(__expf(sc[ni][2] - m1),
                                                      __expf(sc[ni][3] - m1));
                p[ni][0] = *reinterpret_cast<const uint32_t*>(&h20);
                p[ni][1] = *reinterpret_cast<const uint32_t*>(&h21);
                sum0 += __low2float(h20) + __high2float(h20);
                sum1 += __low2float(h21) + __high2float(h21);
            }
            sum0 += __shfl_xor_sync(0xffffffffu, sum0, 1);
            sum0 += __shfl_xor_sync(0xffffffffu, sum0, 2);
            sum1 += __shfl_xor_sync(0xffffffffu, sum1, 1);
            sum1 += __shfl_xor_sync(0xffffffffu, sum1, 2);
            l0 = l0 * al0 + sum0;
            l1 = l1 * al1 + sum1;

#pragma unroll
            for (int ni = 0; ni < 8; ni++) {
                o[ni][0] *= al0; o[ni][1] *= al0;
                o[ni][2] *= al1; o[ni][3] *= al1;
            }

#pragma unroll
            for (int ks = 0; ks < 4; ks++) {
                const int k0 = ks * 16;
#pragma unroll
                for (int ni = 0; ni < 8; ni++) {
                    const __half* vp = Vb + (k0 + 2 * t4) * KVST + ni * 8 + g;
                    const uint32_t v00 = *reinterpret_cast<const uint16_t*>(vp);
                    const uint32_t v01 = *reinterpret_cast<const uint16_t*>(vp + KVST);
                    const uint32_t v10 = *reinterpret_cast<const uint16_t*>(vp + 8 * KVST);
                    const uint32_t v11 = *reinterpret_cast<const uint16_t*>(vp + 9 * KVST);
                    const uint32_t b0 = v00 | (v01 << 16);
                    const uint32_t b1 = v10 | (v11 << 16);
                    MMA_H(o[ni], p[2 * ks][0], p[2 * ks][1], p[2 * ks + 1][0], p[2 * ks + 1][1],
                          b0, b1);
                }
            }
        }

        const float il0 = 1.0f / l0, il1 = 1.0f / l1;
        const int mr0 = b * Sn + rw + g;
#pragma unroll
        for (int ni = 0; ni < 8; ni++) {
            const int k = h * Dn + ni * 8 + 2 * t4;
            *reinterpret_cast<__half2*>(outT + fmIdx(mr0, k, KBo)) =
                __floats2half2_rn(o[ni][0] * il0, o[ni][1] * il0);
            *reinterpret_cast<__half2*>(outT + fmIdx(mr0 + 8, k, KBo)) =
                __floats2half2_rn(o[ni][2] * il1, o[ni][3] * il1);
        }
    }
}

// ---------------- launch ------------------------------------------------------
extern "C" void kernel_launch(void* const* d_in, const int* in_sizes, int n_in,
                              void* d_out, int out_size)
{
    const float* x        = (const float*)d_in[0];
    const float* ln1_s    = (const float*)d_in[1];
    const float* ln1_o    = (const float*)d_in[2];
    const float* wq       = (const float*)d_in[3];
    const float* bq       = (const float*)d_in[4];
    const float* wk       = (const float*)d_in[5];
    const float* bk       = (const float*)d_in[6];
    const float* wv       = (const float*)d_in[7];
    const float* bv       = (const float*)d_in[8];
    const float* wo       = (const float*)d_in[9];
    const float* bo       = (const float*)d_in[10];
    const float* ln2_s    = (const float*)d_in[11];
    const float* ln2_o    = (const float*)d_in[12];
    const float* fc1_w    = (const float*)d_in[13];
    const float* fc1_b    = (const float*)d_in[14];
    const float* fc2_w    = (const float*)d_in[15];
    const float* fc2_b    = (const float*)d_in[16];
    float* out            = (float*)d_out;

    float *px1, *pbqkv, *ppart;
    __half *phT, *pqkv, *pf1T, *pwr;
    cudaGetSymbolAddress((void**)&phT,   g_hT);
    cudaGetSymbolAddress((void**)&pqkv,  g_qkv);
    cudaGetSymbolAddress((void**)&px1,   g_x1);
    cudaGetSymbolAddress((void**)&pf1T,  g_f1T);
    cudaGetSymbolAddress((void**)&pwr,   g_wr);
    cudaGetSymbolAddress((void**)&pbqkv, g_bqkv);
    cudaGetSymbolAddress((void**)&ppart, g_part);

    __half* rwqkv = pwr;                                     // fused, NBtot=30
    __half* rwo   = pwr + (size_t)3 * WSZ_DM;
    __half* rfc1  = pwr + (size_t)4 * WSZ_DM;
    __half* rfc2  = pwr + (size_t)4 * WSZ_DM + WSZ_FC;

    static int nsm = 0;
    if (!nsm) {
        cudaDeviceGetAttribute(&nsm, cudaDevAttrMultiProcessorCount, 0);
        cudaFuncSetAttribute(flash_reg, cudaFuncAttributeMaxDynamicSharedMemorySize, FLASH_SMEM);
        cudaFuncSetAttribute(gemm_h<0>, cudaFuncAttributeMaxDynamicSharedMemorySize, GEMM_SMEM);
        cudaFuncSetAttribute(gemm_h<2>, cudaFuncAttributeMaxDynamicSharedMemorySize, GEMM_SMEM);
        cudaFuncSetAttribute(gemm_h64sp, cudaFuncAttributeMaxDynamicSharedMemorySize, GEMM64_SMEM);
    }
    const int flashGrid = 2 * nsm;

    // 0) ALL weight transforms in one launch (9600 CTAs)
    {
        WtArgs wa;
        wa.src[0] = wq;   wa.dst[0] = rwqkv; wa.K[0] = DMn; wa.N[0] = DMn; wa.NBtot[0] = 30; wa.nbOff[0] = 0;
        wa.src[1] = wk;   wa.dst[1] = rwqkv; wa.K[1] = DMn; wa.N[1] = DMn; wa.NBtot[1] = 30; wa.nbOff[1] = 10;
        wa.src[2] = wv;   wa.dst[2] = rwqkv; wa.K[2] = DMn; wa.N[2] = DMn; wa.NBtot[2] = 30; wa.nbOff[2] = 20;
        wa.src[3] = wo;   wa.dst[3] = rwo;   wa.K[3] = DMn; wa.N[3] = DMn; wa.NBtot[3] = 10; wa.nbOff[3] = 0;
        wa.src[4] = fc1_w; wa.dst[4] = rfc1; wa.K[4] = DMn; wa.N[4] = DFn; wa.NBtot[4] = 40; wa.nbOff[4] = 0;
        wa.src[5] = fc2_w; wa.dst[5] = rfc2; wa.K[5] = DFn; wa.N[5] = DMn; wa.NBtot[5] = 10; wa.nbOff[5] = 0;
        wa.blockStart[0] = 0;
        wa.blockStart[1] = 800;
        wa.blockStart[2] = 1600;
        wa.blockStart[3] = 2400;
        wa.blockStart[4] = 3200;
        wa.blockStart[5] = 6400;
        wa.blockStart[6] = 9600;
        btrans_all<<<9600, 256>>>(wa);
        bias_concat<<<QKVLD / 256, 256>>>(bq, bk, bv, pbqkv);
    }

    // 1) LN1 -> fragment-major hT
    ln_ft<<<NTOK, 256>>>(x, ln1_s, ln1_o, phT);

    // 2) fused QKV projection -> qkv (plain fp16)
    {
        dim3 grid(QKVLD / 128, NTOK / 128);  // (30, 32)
        gemm_h<0><<<grid, 256, GEMM_SMEM>>>(phT, rwqkv, pbqkv, nullptr, pqkv, NTOK, QKVLD, DMn);
    }

    // 3) flash attention (persistent) -> fragment-major hT (reuse)
    flash_reg<<<flashGrid, 256, FLASH_SMEM>>>(pqkv, phT);

    // 4) O-proj split-K2 -> partials, combine(+bias+res x) -> x1
    {
        dim3 grid(DMn / 128, NTOK / 64, 2);  // (10, 64, 2)
        gemm_h64sp<<<grid, 256, GEMM64_SMEM>>>(phT, rwo, ppart, NTOK, DMn, DMn);
        combine_res<<<NTOK * DMn / 4 / 256, 256>>>(ppart, ppart + (size_t)NTOK * DMn,
                                                   bo, x, px1);
    }

    // 5) LN2 -> fragment-major hT (reuse)
    ln_ft<<<NTOK, 256>>>(px1, ln2_s, ln2_o, phT);

    // 6) FC1 + GELU -> fragment-major f1T
    {
        dim3 grid(DFn / 128, NTOK / 128);    // (40, 32)
        gemm_h<2><<<grid, 256, GEMM_SMEM>>>(phT, rfc1, fc1_b, nullptr, pf1T, NTOK, DFn, DMn);
    }

    // 7) FC2 split-K2 -> partials, combine(+bias+res x1) -> out
    {
        dim3 grid(DMn / 128, NTOK / 64, 2);  // (10, 64, 2)
        gemm_h64sp<<<grid, 256, GEMM64_SMEM>>>(pf1T, rfc2, ppart, NTOK, DMn, DFn);
        combine_res<<<NTOK * DMn / 4 / 256, 256>>>(ppart, ppart + (size_t)NTOK * DMn,
                                                   fc2_b, px1, out);
    }
}

// round 17
// speedup vs baseline: 1.0660x; 1.0060x over previous
#include <cuda_runtime.h>
#include <cuda_fp16.h>
#include <math.h>
#include <stdint.h>

// Problem constants
#define Bn   4
#define Sn   1024
#define Hn   20
#define Dn   64
#define DMn  1280
#define DFn  5120
#define NTOK 4096           // Bn*Sn
#define NBH  80             // Bn*Hn
#define EPSLN 1e-5f
#define QKVLD 3840          // row stride of fused qkv output

// ---------------- scratch (static device globals; no allocation) -------------
__device__ __half g_hT  [(size_t)NTOK * DMn];          // fragment-major A (reused 3x)
__device__ __half g_qkv [(size_t)NTOK * QKVLD];        // fused q|k|v (plain fp16)
__device__ float  g_x1  [(size_t)NTOK * DMn];          // residual 1
__device__ __half g_f1T [(size_t)NTOK * DFn];          // fragment-major FC1 out
__device__ __half g_wr  [19660800];                    // fragment-major weights (fp16)
__device__ float  g_bqkv[QKVLD];                       // concat bias
__device__ float  g_part[(size_t)2 * NTOK * DMn];      // split-K partials

#define WSZ_DM (DMn * DMn)          // 1,638,400
#define WSZ_FC (DMn * DFn)          // 6,553,600

// ---------------- PDL helpers ---------------------------------------------------
__device__ __forceinline__ void pdl_trigger() {
#if defined(__CUDA_ARCH__) && __CUDA_ARCH__ >= 900
    cudaTriggerProgrammaticLaunchCompletion();
#endif
}
__device__ __forceinline__ void pdl_wait() {
#if defined(__CUDA_ARCH__) && __CUDA_ARCH__ >= 900
    cudaGridDependencySynchronize();
#endif
}

// ---------------- fragment-major index helper ---------------------------------
__device__ __forceinline__ size_t fmIdx(int m, int k, int KB) {
    const int mb = m >> 7, mr = m & 127;
    const int kb = k >> 4, kr = k & 15;
    const int mt = mr >> 4, hh = (mr >> 3) & 1, gg = mr & 7;
    const int t4k = (kr >> 1) & 3, khi = kr >> 3, klo = kr & 1;
    return ((size_t)mb * KB + kb) * 2048 +
           (size_t)((mt * 32 + gg * 4 + t4k) * 8 + khi * 4 + hh * 2 + klo);
}

// ---------------- ALL weight transforms in ONE launch --------------------------
struct WtArgs {
    const float* src[6];
    __half*      dst[6];
    int K[6], N[6], NBtot[6], nbOff[6];
    int blockStart[7];
};

__global__ void __launch_bounds__(256) btrans_all(WtArgs wa)
{
    pdl_trigger();                      // inputs are pre-graph; no wait needed
    __shared__ __half s[2048];
    const int gb = blockIdx.x;
    int seg = 0;
#pragma unroll
    for (int i = 1; i < 6; i++) seg += (gb >= wa.blockStart[i]);
    const int lb = gb - wa.blockStart[seg];
    const int N = wa.N[seg];
    const int NBn = N >> 7;
    const int nb = lb % NBn, kb = lb / NBn;
    const int tid = threadIdx.x;
    const float* bb = wa.src[seg] + (size_t)(kb * 16) * N + nb * 128;

#pragma unroll
    for (int e4 = tid; e4 < 512; e4 += 256) {
        const int k = e4 >> 5, colq = (e4 & 31) * 4;
        const float4 f = *reinterpret_cast<const float4*>(bb + (size_t)k * N + colq);
        const int t4 = (k >> 1) & 3, khi = (k >> 3) & 1, klo = k & 1;
        const float vv[4] = {f.x, f.y, f.z, f.w};
#pragma unroll
        for (int j = 0; j < 4; j++) {
            const int col = colq + j;
            const int ni = col >> 3, gg = col & 7;
            s[(ni * 32 + gg * 4 + t4) * 4 + khi * 2 + klo] = __float2half_rn(vv[j]);
        }
    }
    __syncthreads();
    __half* ob = wa.dst[seg] + ((size_t)kb * wa.NBtot[seg] + wa.nbOff[seg] + nb) * 2048;
    *reinterpret_cast<uint4*>(ob + tid * 8) = *reinterpret_cast<const uint4*>(s + tid * 8);
}

// ---------------- bias concat for fused QKV (inputs only; overlaps btrans) -----
__global__ void __launch_bounds__(256) bias_concat(const float* __restrict__ bq,
                                                   const float* __restrict__ bk,
                                                   const float* __restrict__ bv,
                                                   float* __restrict__ o)
{
    pdl_trigger();                      // reads only harness inputs: no wait
    const int i = blockIdx.x * 256 + threadIdx.x;
    if (i < DMn) o[i] = bq[i];
    else if (i < 2 * DMn) o[i] = bk[i - DMn];
    else if (i < 3 * DMn) o[i] = bv[i - 2 * DMn];
}

// ---------------- split-K combine: out = p0 + p1 + bias + res ------------------
__global__ void __launch_bounds__(256) combine_res(const float* __restrict__ p0,
                                                   const float* __restrict__ p1,
                                                   const float* __restrict__ bias,
                                                   const float* __restrict__ res,
                                                   float* __restrict__ out)
{
    pdl_trigger();
    pdl_wait();
    const size_t i4 = (size_t)blockIdx.x * 256 + threadIdx.x;   // float4 index
    const size_t i = i4 * 4;
    const int col = (int)(i % DMn);
    const float4 a = *reinterpret_cast<const float4*>(p0 + i);
    const float4 b = *reinterpret_cast<const float4*>(p1 + i);
    const float4 r = *reinterpret_cast<const float4*>(res + i);
    const float4 bb = *reinterpret_cast<const float4*>(bias + col);
    float4 o;
    o.x = a.x + b.x + bb.x + r.x;
    o.y = a.y + b.y + bb.y + r.y;
    o.z = a.z + b.z + bb.z + r.z;
    o.w = a.w + b.w + bb.w + r.w;
    *reinterpret_cast<float4*>(out + i) = o;
}

// ---------------- LayerNorm (LN1) fused with fragment-major fp16 output --------
__global__ void __launch_bounds__(256) ln_ft(const float* __restrict__ x,
                                             const float* __restrict__ sc,
                                             const float* __restrict__ off,
                                             __half* __restrict__ yT)
{
    pdl_trigger();                      // LN1 reads only harness input x: no wait
    const int row = blockIdx.x;
    const float* xr = x + (size_t)row * DMn;
    const int t = threadIdx.x;
    const int lane = t & 31, wid = t >> 5;

    __shared__ float sh[32];
    __shared__ float s_mean, s_rstd;

    float2 p0 = *reinterpret_cast<const float2*>(xr + 2 * t);
    float2 p1 = *reinterpret_cast<const float2*>(xr + 512 + 2 * t);
    float2 p2 = make_float2(0.f, 0.f);
    if (t < 128) p2 = *reinterpret_cast<const float2*>(xr + 1024 + 2 * t);

    float s = p0.x + p0.y + p1.x + p1.y + p2.x + p2.y;
#pragma unroll
    for (int o = 16; o; o >>= 1) s += __shfl_xor_sync(0xffffffffu, s, o);
    if (lane == 0) sh[wid] = s;
    __syncthreads();
    if (wid == 0) {
        float v = (lane < 8) ? sh[lane] : 0.f;
#pragma unroll
        for (int o = 4; o; o >>= 1) v += __shfl_xor_sync(0xffffffffu, v, o);
        if (lane == 0) s_mean = v * (1.0f / DMn);
    }
    __syncthreads();
    const float mean = s_mean;
    __syncthreads();

    float vs = 0.f;
    {
        float d;
        d = p0.x - mean; vs += d * d;
        d = p0.y - mean; vs += d * d;
        d = p1.x - mean; vs += d * d;
        d = p1.y - mean; vs += d * d;
        if (t < 128) {
            d = p2.x - mean; vs += d * d;
            d = p2.y - mean; vs += d * d;
        }
    }
#pragma unroll
    for (int o = 16; o; o >>= 1) vs += __shfl_xor_sync(0xffffffffu, vs, o);
    if (lane == 0) sh[wid] = vs;
    __syncthreads();
    if (wid == 0) {
        float v = (lane < 8) ? sh[lane] : 0.f;
#pragma unroll
        for (int o = 4; o; o >>= 1) v += __shfl_xor_sync(0xffffffffu, v, o);
        if (lane == 0) s_rstd = rsqrtf(v * (1.0f / DMn) + EPSLN);
    }
    __syncthreads();
    const float rstd = s_rstd;

    const int KB = DMn >> 4;
    {
        const int c = 2 * t;
        const float2 g2 = *reinterpret_cast<const float2*>(sc + c);
        const float2 b2 = *reinterpret_cast<const float2*>(off + c);
        *reinterpret_cast<__half2*>(yT + fmIdx(row, c, KB)) =
            __floats2half2_rn((p0.x - mean) * rstd * g2.x + b2.x,
                              (p0.y - mean) * rstd * g2.y + b2.y);
    }
    {
        const int c = 512 + 2 * t;
        const float2 g2 = *reinterpret_cast<const float2*>(sc + c);
        const float2 b2 = *reinterpret_cast<const float2*>(off + c);
        *reinterpret_cast<__half2*>(yT + fmIdx(row, c, KB)) =
            __floats2half2_rn((p1.x - mean) * rstd * g2.x + b2.x,
                              (p1.y - mean) * rstd * g2.y + b2.y);
    }
    if (t < 128) {
        const int c = 1024 + 2 * t;
        const float2 g2 = *reinterpret_cast<const float2*>(sc + c);
        const float2 b2 = *reinterpret_cast<const float2*>(off + c);
        *reinterpret_cast<__half2*>(yT + fmIdx(row, c, KB)) =
            __floats2half2_rn((p2.x - mean) * rstd * g2.x + b2.x,
                              (p2.y - mean) * rstd * g2.y + b2.y);
    }
}

// ---------------- FUSED split-K combine + residual + LayerNorm -----------------
// x1 = p0 + p1 + bias + res  (written fp32, needed by FC2 residual)
// yT = LN(x1) in fragment-major fp16 (identical math to ln_ft)
__global__ void __launch_bounds__(256) combine_ln(const float* __restrict__ p0,
                                                  const float* __restrict__ p1,
                                                  const float* __restrict__ bias,
                                                  const float* __restrict__ res,
                                                  float* __restrict__ x1,
                                                  const float* __restrict__ sc,
                                                  const float* __restrict__ off,
                                                  __half* __restrict__ yT)
{
    pdl_trigger();
    pdl_wait();
    const int row = blockIdx.x;
    const size_t base = (size_t)row * DMn;
    const int t = threadIdx.x;
    const int lane = t & 31, wid = t >> 5;

    __shared__ float sh[32];
    __shared__ float s_mean, s_rstd;

    auto ld = [&](int c) -> float2 {
        const float2 a = *reinterpret_cast<const float2*>(p0 + base + c);
        const float2 b = *reinterpret_cast<const float2*>(p1 + base + c);
        const float2 r = *reinterpret_cast<const float2*>(res + base + c);
        const float2 bb = *reinterpret_cast<const float2*>(bias + c);
        return make_float2(a.x + b.x + bb.x + r.x, a.y + b.y + bb.y + r.y);
    };
    float2 v0 = ld(2 * t);
    float2 v1 = ld(512 + 2 * t);
    float2 v2 = make_float2(0.f, 0.f);
    if (t < 128) v2 = ld(1024 + 2 * t);

    *reinterpret_cast<float2*>(x1 + base + 2 * t) = v0;
    *reinterpret_cast<float2*>(x1 + base + 512 + 2 * t) = v1;
    if (t < 128) *reinterpret_cast<float2*>(x1 + base + 1024 + 2 * t) = v2;

    float s = v0.x + v0.y + v1.x + v1.y + v2.x + v2.y;
#pragma unroll
    for (int o = 16; o; o >>= 1) s += __shfl_xor_sync(0xffffffffu, s, o);
    if (lane == 0) sh[wid] = s;
    __syncthreads();
    if (wid == 0) {
        float v = (lane < 8) ? sh[lane] : 0.f;
#pragma unroll
        for (int o = 4; o; o >>= 1) v += __shfl_xor_sync(0xffffffffu, v, o);
        if (lane == 0) s_mean = v * (1.0f / DMn);
    }
    __syncthreads();
    const float mean = s_mean;
    __syncthreads();

    float vs = 0.f;
    {
        float d;
        d = v0.x - mean; vs += d * d;
        d = v0.y - mean; vs += d * d;
        d = v1.x - mean; vs += d * d;
        d = v1.y - mean; vs += d * d;
        if (t < 128) {
            d = v2.x - mean; vs += d * d;
            d = v2.y - mean; vs += d * d;
        }
    }
#pragma unroll
    for (int o = 16; o; o >>= 1) vs += __shfl_xor_sync(0xffffffffu, vs, o);
    if (lane == 0) sh[wid] = vs;
    __syncthreads();
    if (wid == 0) {
        float v = (lane < 8) ? sh[lane] : 0.f;
#pragma unroll
        for (int o = 4; o; o >>= 1) v += __shfl_xor_sync(0xffffffffu, v, o);
        if (lane == 0) s_rstd = rsqrtf(v * (1.0f / DMn) + EPSLN);
    }
    __syncthreads();
    const float rstd = s_rstd;

    const int KB = DMn >> 4;
    auto emit = [&](int c, float2 p) {
        const float2 g2 = *reinterpret_cast<const float2*>(sc + c);
        const float2 b2 = *reinterpret_cast<const float2*>(off + c);
        *reinterpret_cast<__half2*>(yT + fmIdx(row, c, KB)) =
            __floats2half2_rn((p.x - mean) * rstd * g2.x + b2.x,
                              (p.y - mean) * rstd * g2.y + b2.y);
    };
    emit(2 * t, v0);
    emit(512 + 2 * t, v1);
    if (t < 128) emit(1024 + 2 * t, v2);
}

// ---------------- GEMM helpers -------------------------------------------------
__device__ __forceinline__ float gelu_exact(float v) {
    return 0.5f * v * (1.0f + erff(v * 0.70710678118654752f));
}

__device__ __forceinline__ void cp16(void* smem_dst, const void* gsrc) {
    uint32_t s = (uint32_t)__cvta_generic_to_shared(smem_dst);
    asm volatile("cp.async.cg.shared.global [%0], [%1], 16;" :: "r"(s), "l"(gsrc));
}

// 3-stage drain (flash): wait_group 1 while another group is in flight, else 0.
#define PIPE_WAIT(kb, KB) \
    do { if ((kb) + 1 < (KB)) asm volatile("cp.async.wait_group 1;" ::: "memory"); \
         else                 asm volatile("cp.async.wait_group 0;" ::: "memory"); } while (0)

// Pair drain (6-stage GEMMs): wait_group 2 normally, 0 on the final pair.
#define PIPE_WAIT_PAIR(p, NP) \
    do { if ((p) + 1 < (NP)) asm volatile("cp.async.wait_group 2;" ::: "memory"); \
         else                asm volatile("cp.async.wait_group 0;" ::: "memory"); } while (0)

#define MMA_H(c, a0,a1,a2,a3, b0,b1) \
    asm volatile("mma.sync.aligned.m16n8k16.row.col.f32.f16.f16.f32 " \
                 "{%0,%1,%2,%3}, {%4,%5,%6,%7}, {%8,%9}, {%0,%1,%2,%3};" \
                 : "+f"((c)[0]), "+f"((c)[1]), "+f"((c)[2]), "+f"((c)[3]) \
                 : "r"(a0), "r"(a1), "r"(a2), "r"(a3), "r"(b0), "r"(b1))

// ---------------- FP16 GEMM, 128x128 tile, 6-stage pair-barrier ---------------
// EPI: 0 = bias -> plain fp16 ; 2 = bias+gelu -> fragment-major fp16.
#define GEMM_SMEM (6 * 8192 * 2)
template <int EPI>
__global__ void __launch_bounds__(256, 2) gemm_h(const __half* __restrict__ At,
                                                 const __half* __restrict__ Bt,
                                                 const float* __restrict__ bias,
                                                 const float* __restrict__ res,
                                                 void* __restrict__ Cv,
                                                 int M, int N, int K)
{
    extern __shared__ __half smg[];
    __half* As = smg;                 // [6][4096]
    __half* Bs = smg + 6 * 4096;      // [6][4096]

    pdl_trigger();

    const int tid = threadIdx.x;
    const int nb = blockIdx.x, mb = blockIdx.y;
    const int KB = K >> 5;
    const int NP = KB >> 1;
    const int KB16 = K >> 4;
    const int NB = N >> 7;
    const int lane = tid & 31, warp = tid >> 5;
    const int wmBase = (warp >> 2) * 4;
    const int wnBase = (warp & 3) * 4;
    const int g = lane >> 2, t4 = lane & 3;

    const __half* aBase = At + (size_t)mb * KB16 * 2048;
    const __half* bBase = Bt + (size_t)nb * 2048;

    float acc[16][4];
#pragma unroll
    for (int i = 0; i < 16; i++)
#pragma unroll
        for (int j = 0; j < 4; j++) acc[i][j] = 0.f;

    auto issue = [&](int kb) {
        const int s = kb % 6;
        const __half* ab  = aBase + (size_t)kb * 4096;
        const __half* bb0 = bBase + (size_t)(kb * 2) * NB * 2048;
        const __half* bb1 = bBase + (size_t)(kb * 2 + 1) * NB * 2048;
        cp16(&As[s * 4096 + tid * 8],        ab + tid * 8);
        cp16(&As[s * 4096 + 2048 + tid * 8], ab + 2048 + tid * 8);
        cp16(&Bs[s * 4096 + tid * 8],        bb0 + tid * 8);
        cp16(&Bs[s * 4096 + 2048 + tid * 8], bb1 + tid * 8);
        asm volatile("cp.async.commit_group;" ::: "memory");
    };
    auto compute = [&](int kb) {
        const int s = kb % 6;
#pragma unroll
        for (int kk = 0; kk < 2; kk++) {
            uint32_t a[4][4], b[4][2];
#pragma unroll
            for (int mi = 0; mi < 4; mi++) {
                const uint4 fa = *reinterpret_cast<const uint4*>(
                    &As[s * 4096 + kk * 2048 + ((wmBase + mi) * 32 + lane) * 8]);
                a[mi][0] = fa.x; a[mi][1] = fa.y; a[mi][2] = fa.z; a[mi][3] = fa.w;
            }
#pragma unroll
            for (int ni = 0; ni < 4; ni++) {
                const uint2 fb = *reinterpret_cast<const uint2*>(
                    &Bs[s * 4096 + kk * 2048 + ((wnBase + ni) * 32 + lane) * 4]);
                b[ni][0] = fb.x; b[ni][1] = fb.y;
            }
#pragma unroll
            for (int mi = 0; mi < 4; mi++)
#pragma unroll
                for (int ni = 0; ni < 4; ni++)
                    MMA_H(acc[mi * 4 + ni], a[mi][0], a[mi][1], a[mi][2], a[mi][3],
                          b[ni][0], b[ni][1]);
        }
    };

    pdl_wait();
    issue(0); issue(1); issue(2); issue(3);

    for (int p = 0; p < NP; p++) {
        const int kb = 2 * p;
        PIPE_WAIT_PAIR(p, NP);
        __syncthreads();
        if (kb + 4 < KB) issue(kb + 4);
        if (kb + 5 < KB) issue(kb + 5);
        compute(kb);
        compute(kb + 1);
    }

    const int rowBase = mb * 128;
    const int colBase = nb * 128;
    const int wm = (warp >> 2) * 64;
    const int wn = (warp & 3) * 32;
    const int KBo = N >> 4;
#pragma unroll
    for (int mi = 0; mi < 4; mi++) {
#pragma unroll
        for (int ni = 0; ni < 4; ni++) {
            float* c = acc[mi * 4 + ni];
            const int col = colBase + wn + ni * 8 + t4 * 2;
            const float2 bb = *reinterpret_cast<const float2*>(bias + col);
#pragma unroll
            for (int h = 0; h < 2; h++) {
                const int row = rowBase + wm + mi * 16 + g + h * 8;
                float o0 = c[h * 2 + 0] + bb.x;
                float o1 = c[h * 2 + 1] + bb.y;
                if (EPI == 0) {
                    __half* Ch = (__half*)Cv;
                    *reinterpret_cast<__half2*>(Ch + (size_t)row * N + col) =
                        __floats2half2_rn(o0, o1);
                } else {
                    __half* Ch = (__half*)Cv;
                    *reinterpret_cast<__half2*>(Ch + fmIdx(row, col, KBo)) =
                        __floats2half2_rn(gelu_exact(o0), gelu_exact(o1));
                }
            }
        }
    }
}

// ---------------- FP16 GEMM, 64x128 tile, SPLIT-K 2, raw fp32 partial out -----
#define GEMM64_SMEM (6 * 6144 * 2)
__global__ void __launch_bounds__(256, 3) gemm_h64sp(const __half* __restrict__ At,
                                                     const __half* __restrict__ Bt,
                                                     float* __restrict__ part,
                                                     int M, int N, int K)
{
    extern __shared__ __half smg[];
    __half* As = smg;                 // [6][2048]
    __half* Bs = smg + 6 * 2048;      // [6][4096]

    pdl_trigger();

    const int tid = threadIdx.x;
    const int nb = blockIdx.x, mb = blockIdx.y;
    const int kz = blockIdx.z;
    const int KBfull = K >> 5;
    const int KB = KBfull >> 1;       // half-K iterations (even)
    const int NP = KB >> 1;
    const int kbOff = kz * KB;
    const int KB16 = K >> 4;
    const int NB = N >> 7;
    const int lane = tid & 31, warp = tid >> 5;
    const int wmBase = (warp >> 2) * 2;
    const int wnBase = (warp & 3) * 4;
    const int g = lane >> 2, t4 = lane & 3;
    const int mhalf = mb & 1, mblk = mb >> 1;

    const __half* aBase = At + (size_t)mblk * KB16 * 2048 + mhalf * 1024;
    const __half* bBase = Bt + (size_t)nb * 2048;

    float acc[8][4];
#pragma unroll
    for (int i = 0; i < 8; i++)
#pragma unroll
        for (int j = 0; j < 4; j++) acc[i][j] = 0.f;

    auto issue = [&](int kb) {
        const int s = kb % 6;
        const int kbg = kbOff + kb;
        const __half* ab0 = aBase + (size_t)(kbg * 2) * 2048;
        const __half* ab1 = aBase + (size_t)(kbg * 2 + 1) * 2048;
        if (tid < 128) cp16(&As[s * 2048 + tid * 8], ab0 + tid * 8);
        else           cp16(&As[s * 2048 + 1024 + (tid - 128) * 8], ab1 + (tid - 128) * 8);
        const __half* bb0 = bBase + (size_t)(kbg * 2) * NB * 2048;
        const __half* bb1 = bBase + (size_t)(kbg * 2 + 1) * NB * 2048;
        cp16(&Bs[s * 4096 + tid * 8],        bb0 + tid * 8);
        cp16(&Bs[s * 4096 + 2048 + tid * 8], bb1 + tid * 8);
        asm volatile("cp.async.commit_group;" ::: "memory");
    };
    auto compute = [&](int kb) {
        const int s = kb % 6;
#pragma unroll
        for (int kk = 0; kk < 2; kk++) {
            uint32_t a[2][4], b[4][2];
#pragma unroll
            for (int mi = 0; mi < 2; mi++) {
                const uint4 fa = *reinterpret_cast<const uint4*>(
                    &As[s * 2048 + kk * 1024 + (wmBase + mi) * 256 + lane * 8]);
                a[mi][0] = fa.x; a[mi][1] = fa.y; a[mi][2] = fa.z; a[mi][3] = fa.w;
            }
#pragma unroll
            for (int ni = 0; ni < 4; ni++) {
                const uint2 fb = *reinterpret_cast<const uint2*>(
                    &Bs[s * 4096 + kk * 2048 + ((wnBase + ni) * 32 + lane) * 4]);
                b[ni][0] = fb.x; b[ni][1] = fb.y;
            }
#pragma unroll
            for (int mi = 0; mi < 2; mi++)
#pragma unroll
                for (int ni = 0; ni < 4; ni++)
                    MMA_H(acc[mi * 4 + ni], a[mi][0], a[mi][1], a[mi][2], a[mi][3],
                          b[ni][0], b[ni][1]);
        }
    };

    pdl_wait();
    issue(0); issue(1); issue(2); issue(3);

    for (int p = 0; p < NP; p++) {
        const int kb = 2 * p;
        PIPE_WAIT_PAIR(p, NP);
        __syncthreads();
        if (kb + 4 < KB) issue(kb + 4);
        if (kb + 5 < KB) issue(kb + 5);
        compute(kb);
        compute(kb + 1);
    }

    float* C = part + (size_t)kz * NTOK * DMn;
    const int rowBase = mb * 64;
    const int colBase = nb * 128;
    const int wm = (warp >> 2) * 32;
    const int wn = (warp & 3) * 32;
#pragma unroll
    for (int mi = 0; mi < 2; mi++) {
#pragma unroll
        for (int ni = 0; ni < 4; ni++) {
            float* c = acc[mi * 4 + ni];
            const int col = colBase + wn + ni * 8 + t4 * 2;
#pragma unroll
            for (int h = 0; h < 2; h++) {
                const int row = rowBase + wm + mi * 16 + g + h * 8;
                *reinterpret_cast<float2*>(C + (size_t)row * N + col) =
                    make_float2(c[h * 2 + 0], c[h * 2 + 1]);
            }
        }
    }
}

// ---------------- flash attention: register softmax, PERSISTENT ---------------
#define KVST 72
#define FLASH_ITEMS ((Sn / 128) * NBH)       // 8 * 80 = 640
#define FLASH_SMEM (3 * 2 * 64 * KVST * 2)   // 3-stage K+V ring, fp16
__global__ void __launch_bounds__(256, 2) flash_reg(const __half* __restrict__ qkv,
                                                    __half* __restrict__ outT)
{
    extern __shared__ __half kvs[];
    __half* Ks = kvs;                       // [3][64*KVST]
    __half* Vs = kvs + 3 * 64 * KVST;       // [3][64*KVST]

    pdl_trigger();
    pdl_wait();

    const int tid = threadIdx.x;
    const int lane = tid & 31, warp = tid >> 5;
    const int g = lane >> 2, t4 = lane & 3;
    const int lr = tid >> 2, lc = (tid & 3) * 16;
    const int KBo = DMn >> 4;

    for (int item = blockIdx.x; item < FLASH_ITEMS; item += gridDim.x) {
        const int bx = item & 7;
        const int bh = item >> 3;
        const int b = bh / Hn, h = bh % Hn;
        const int t0 = bx * 128;
        const int rw = t0 + warp * 16;

        __syncthreads();   // protect KV ring from previous item's readers

        uint32_t aq[4][4];
        {
            const __half* q0 = qkv + (size_t)(b * Sn + rw + g) * QKVLD + h * Dn + 2 * t4;
            const __half* q1 = q0 + (size_t)8 * QKVLD;
#pragma unroll
            for (int ks = 0; ks < 4; ks++) {
                const int k0 = ks * 16;
                aq[ks][0] = *reinterpret_cast<const uint32_t*>(q0 + k0);
                aq[ks][1] = *reinterpret_cast<const uint32_t*>(q1 + k0);
                aq[ks][2] = *reinterpret_cast<const uint32_t*>(q0 + k0 + 8);
                aq[ks][3] = *reinterpret_cast<const uint32_t*>(q1 + k0 + 8);
            }
        }

        float o[8][4];
#pragma unroll
        for (int ni = 0; ni < 8; ni++)
#pragma unroll
            for (int j = 0; j < 4; j++) o[ni][j] = 0.f;
        float m0 = -3e38f, m1 = -3e38f, l0 = 0.f, l1 = 0.f;

        auto loadKV = [&](int buf, int j0) {
            const __half* kr = qkv + (size_t)(b * Sn + j0 + lr) * QKVLD + DMn + h * Dn + lc;
            const __half* vr = kr + DMn;
            __half* kd = Ks + buf * (64 * KVST) + lr * KVST + lc;
            __half* vd = Vs + buf * (64 * KVST) + lr * KVST + lc;
            cp16(kd, kr); cp16(kd + 8, kr + 8);
            cp16(vd, vr); cp16(vd + 8, vr + 8);
            asm volatile("cp.async.commit_group;" ::: "memory");
        };

        loadKV(0, 0);
        loadKV(1, 64);

        for (int j = 0; j < 16; j++) {
            const int s = j % 3;
            PIPE_WAIT(j, 16);
            __syncthreads();
            if (j + 2 < 16) loadKV((j + 2) % 3, (j + 2) * 64);

            const __half* Kb = Ks + s * (64 * KVST);
            const __half* Vb = Vs + s * (64 * KVST);

            float sc[8][4];
#pragma unroll
            for (int ni = 0; ni < 8; ni++)
#pragma unroll
                for (int jj = 0; jj < 4; jj++) sc[ni][jj] = 0.f;
#pragma unroll
            for (int ks = 0; ks < 4; ks++) {
                const int k0 = ks * 16;
#pragma unroll
                for (int ni = 0; ni < 8; ni++) {
                    const __half* bp = Kb + (ni * 8 + g) * KVST + k0 + 2 * t4;
                    const uint32_t b0 = *reinterpret_cast<const uint32_t*>(bp);
                    const uint32_t b1 = *reinterpret_cast<const uint32_t*>(bp + 8);
                    MMA_H(sc[ni], aq[ks][0], aq[ks][1], aq[ks][2], aq[ks][3], b0, b1);
                }
            }

            float mx0 = -3e38f, mx1 = -3e38f;
#pragma unroll
            for (int ni = 0; ni < 8; ni++) {
#pragma unroll
                for (int jj = 0; jj < 4; jj++) sc[ni][jj] *= 0.125f;
                mx0 = fmaxf(mx0, fmaxf(sc[ni][0], sc[ni][1]));
                mx1 = fmaxf(mx1, fmaxf(sc[ni][2], sc[ni][3]));
            }
            mx0 = fmaxf(mx0, __shfl_xor_sync(0xffffffffu, mx0, 1));
            mx0 = fmaxf(mx0, __shfl_xor_sync(0xffffffffu, mx0, 2));
            mx1 = fmaxf(mx1, __shfl_xor_sync(0xffffffffu, mx1, 1));
            mx1 = fmaxf(mx1, __shfl_xor_sync(0xffffffffu, mx1, 2));

            const float mn0 = fmaxf(m0, mx0), mn1 = fmaxf(m1, mx1);
            const float al0 = __expf(m0 - mn0), al1 = __expf(m1 - mn1);
            m0 = mn0; m1 = mn1;

            uint32_t p[8][2];
            float sum0 = 0.f, sum1 = 0.f;
#pragma unroll
            for (int ni = 0; ni < 8; ni++) {
                const __half2 h20 = __floats2half2_rn(__expf(sc[ni][0] - m0),
                                                      __expf(sc[ni][1] - m0));
                const __half2 h21 = __floats2half2_rn(__expf(sc[ni][2] - m1),
                                                      __expf(sc[ni][3] - m1));
                p[ni][0] = *reinterpret_cast<const uint32_t*>(&h20);
                p[ni][1] = *reinterpret_cast<const uint32_t*>(&h21);
                sum0 += __low2float(h20) + __high2float(h20);
                sum1 += __low2float(h21) + __high2float(h21);
            }
            sum0 += __shfl_xor_sync(0xffffffffu, sum0, 1);
            sum0 += __shfl_xor_sync(0xffffffffu, sum0, 2);
            sum1 += __shfl_xor_sync(0xffffffffu, sum1, 1);
            sum1 += __shfl_xor_sync(0xffffffffu, sum1, 2);
            l0 = l0 * al0 + sum0;
            l1 = l1 * al1 + sum1;

#pragma unroll
            for (int ni = 0; ni < 8; ni++) {
                o[ni][0] *= al0; o[ni][1] *= al0;
                o[ni][2] *= al1; o[ni][3] *= al1;
            }

#pragma unroll
            for (int ks = 0; ks < 4; ks++) {
                const int k0 = ks * 16;
#pragma unroll
                for (int ni = 0; ni < 8; ni++) {
                    const __half* vp = Vb + (k0 + 2 * t4) * KVST + ni * 8 + g;
                    const uint32_t v00 = *reinterpret_cast<const uint16_t*>(vp);
                    const uint32_t v01 = *reinterpret_cast<const uint16_t*>(vp + KVST);
                    const uint32_t v10 = *reinterpret_cast<const uint16_t*>(vp + 8 * KVST);
                    const uint32_t v11 = *reinterpret_cast<const uint16_t*>(vp + 9 * KVST);
                    const uint32_t b0 = v00 | (v01 << 16);
                    const uint32_t b1 = v10 | (v11 << 16);
                    MMA_H(o[ni], p[2 * ks][0], p[2 * ks][1], p[2 * ks + 1][0], p[2 * ks + 1][1],
                          b0, b1);
                }
            }
        }

        const float il0 = 1.0f / l0, il1 = 1.0f / l1;
        const int mr0 = b * Sn + rw + g;
#pragma unroll
        for (int ni = 0; ni < 8; ni++) {
            const int k = h * Dn + ni * 8 + 2 * t4;
            *reinterpret_cast<__half2*>(outT + fmIdx(mr0, k, KBo)) =
                __floats2half2_rn(o[ni][0] * il0, o[ni][1] * il0);
            *reinterpret_cast<__half2*>(outT + fmIdx(mr0 + 8, k, KBo)) =
                __floats2half2_rn(o[ni][2] * il1, o[ni][3] * il1);
        }
    }
}

// ---------------- PDL launch helper --------------------------------------------
template <typename K, typename... Args>
static inline void launch_pdl(K kfn, dim3 g, dim3 b, size_t smem, Args... args)
{
    cudaLaunchConfig_t cfg = {};
    cfg.gridDim = g;
    cfg.blockDim = b;
    cfg.dynamicSmemBytes = smem;
    cfg.stream = 0;
    cudaLaunchAttribute at;
    at.id = cudaLaunchAttributeProgrammaticStreamSerialization;
    at.val.programmaticStreamSerializationAllowed = 1;
    cfg.attrs = &at;
    cfg.numAttrs = 1;
    cudaLaunchKernelEx(&cfg, kfn, args...);
}

// ---------------- launch ------------------------------------------------------
extern "C" void kernel_launch(void* const* d_in, const int* in_sizes, int n_in,
                              void* d_out, int out_size)
{
    const float* x        = (const float*)d_in[0];
    const float* ln1_s    = (const float*)d_in[1];
    const float* ln1_o    = (const float*)d_in[2];
    const float* wq       = (const float*)d_in[3];
    const float* bq       = (const float*)d_in[4];
    const float* wk       = (const float*)d_in[5];
    const float* bk       = (const float*)d_in[6];
    const float* wv       = (const float*)d_in[7];
    const float* bv       = (const float*)d_in[8];
    const float* wo       = (const float*)d_in[9];
    const float* bo       = (const float*)d_in[10];
    const float* ln2_s    = (const float*)d_in[11];
    const float* ln2_o    = (const float*)d_in[12];
    const float* fc1_w    = (const float*)d_in[13];
    const float* fc1_b    = (const float*)d_in[14];
    const float* fc2_w    = (const float*)d_in[15];
    const float* fc2_b    = (const float*)d_in[16];
    float* out            = (float*)d_out;

    float *px1, *pbqkv, *ppart;
    __half *phT, *pqkv, *pf1T, *pwr;
    cudaGetSymbolAddress((void**)&phT,   g_hT);
    cudaGetSymbolAddress((void**)&pqkv,  g_qkv);
    cudaGetSymbolAddress((void**)&px1,   g_x1);
    cudaGetSymbolAddress((void**)&pf1T,  g_f1T);
    cudaGetSymbolAddress((void**)&pwr,   g_wr);
    cudaGetSymbolAddress((void**)&pbqkv, g_bqkv);
    cudaGetSymbolAddress((void**)&ppart, g_part);

    __half* rwqkv = pwr;                                     // fused, NBtot=30
    __half* rwo   = pwr + (size_t)3 * WSZ_DM;
    __half* rfc1  = pwr + (size_t)4 * WSZ_DM;
    __half* rfc2  = pwr + (size_t)4 * WSZ_DM + WSZ_FC;

    static int nsm = 0;
    if (!nsm) {
        cudaDeviceGetAttribute(&nsm, cudaDevAttrMultiProcessorCount, 0);
        cudaFuncSetAttribute(flash_reg, cudaFuncAttributeMaxDynamicSharedMemorySize, FLASH_SMEM);
        cudaFuncSetAttribute(gemm_h<0>, cudaFuncAttributeMaxDynamicSharedMemorySize, GEMM_SMEM);
        cudaFuncSetAttribute(gemm_h<2>, cudaFuncAttributeMaxDynamicSharedMemorySize, GEMM_SMEM);
        cudaFuncSetAttribute(gemm_h64sp, cudaFuncAttributeMaxDynamicSharedMemorySize, GEMM64_SMEM);
    }
    const int flashGrid = 2 * nsm;

    // 0) ALL weight transforms in one launch (9600 CTAs); plain launch (first node)
    {
        WtArgs wa;
        wa.src[0] = wq;   wa.dst[0] = rwqkv; wa.K[0] = DMn; wa.N[0] = DMn; wa.NBtot[0] = 30; wa.nbOff[0] = 0;
        wa.src[1] = wk;   wa.dst[1] = rwqkv; wa.K[1] = DMn; wa.N[1] = DMn; wa.NBtot[1] = 30; wa.nbOff[1] = 10;
        wa.src[2] = wv;   wa.dst[2] = rwqkv; wa.K[2] = DMn; wa.N[2] = DMn; wa.NBtot[2] = 30; wa.nbOff[2] = 20;
        wa.src[3] = wo;   wa.dst[3] = rwo;   wa.K[3] = DMn; wa.N[3] = DMn; wa.NBtot[3] = 10; wa.nbOff[3] = 0;
        wa.src[4] = fc1_w; wa.dst[4] = rfc1; wa.K[4] = DMn; wa.N[4] = DFn; wa.NBtot[4] = 40; wa.nbOff[4] = 0;
        wa.src[5] = fc2_w; wa.dst[5] = rfc2; wa.K[5] = DFn; wa.N[5] = DMn; wa.NBtot[5] = 10; wa.nbOff[5] = 0;
        wa.blockStart[0] = 0;
        wa.blockStart[1] = 800;
        wa.blockStart[2] = 1600;
        wa.blockStart[3] = 2400;
        wa.blockStart[4] = 3200;
        wa.blockStart[5] = 6400;
        wa.blockStart[6] = 9600;
        btrans_all<<<9600, 256>>>(wa);
    }

    // bias_concat + LN1 read ONLY harness inputs (no pdl_wait inside) -> they
    // overlap btrans_all's long tail under PDL.
    launch_pdl(bias_concat, dim3(QKVLD / 256), dim3(256), 0, bq, bk, bv, pbqkv);
    launch_pdl(ln_ft, dim3(NTOK), dim3(256), 0, x, ln1_s, ln1_o, phT);

    // 2) fused QKV projection -> qkv (plain fp16)
    launch_pdl(gemm_h<0>, dim3(QKVLD / 128, NTOK / 128), dim3(256), (size_t)GEMM_SMEM,
               (const __half*)phT, (const __half*)rwqkv, (const float*)pbqkv,
               (const float*)nullptr, (void*)pqkv, NTOK, QKVLD, DMn);

    // 3) flash attention (persistent) -> fragment-major hT (reuse)
    launch_pdl(flash_reg, dim3(flashGrid), dim3(256), (size_t)FLASH_SMEM,
               (const __half*)pqkv, (__half*)phT);

    // 4) O-proj split-K2 -> partials; fused combine+LN2 -> x1 + phT
    launch_pdl(gemm_h64sp, dim3(DMn / 128, NTOK / 64, 2), dim3(256), (size_t)GEMM64_SMEM,
               (const __half*)phT, (const __half*)rwo, (float*)ppart, NTOK, DMn, DMn);
    launch_pdl(combine_ln, dim3(NTOK), dim3(256), 0,
               (const float*)ppart, (const float*)(ppart + (size_t)NTOK * DMn),
               bo, x, (float*)px1, ln2_s, ln2_o, (__half*)phT);

    // 6) FC1 + GELU -> fragment-major f1T
    launch_pdl(gemm_h<2>, dim3(DFn / 128, NTOK / 128), dim3(256), (size_t)GEMM_SMEM,
               (const __half*)phT, (const __half*)rfc1, fc1_b,
               (const float*)nullptr, (void*)pf1T, NTOK, DFn, DMn);

    // 7) FC2 split-K2 -> partials, combine(+bias+res x1) -> out
    launch_pdl(gemm_h64sp, dim3(DMn / 128, NTOK / 64, 2), dim3(256), (size_t)GEMM64_SMEM,
               (const __half*)pf1T, (const __half*)rfc2, (float*)ppart, NTOK, DMn, DFn);
    launch_pdl(combine_res, dim3(NTOK * DMn / 4 / 256), dim3(256), 0,
               (const float*)ppart, (const float*)(ppart + (size_t)NTOK * DMn),
               fc2_b, (const float*)px1, out);
}